// round 11
// baseline (speedup 1.0000x reference)
#include <cuda_runtime.h>
#include <cuda_bf16.h>
#include <math.h>
#include <stdint.h>

// Problem constants
#define BATCH 2
#define SEQ   4096
#define DIM   2048
#define HEADS 16
#define DHEAD 128
#define BLKSZ 32
#define SELK  16
#define HIDC  4096
#define WBLK  128
#define CM    129
#define ROWS  (BATCH*SEQ)
#define QKVN  (BATCH*HEADS*SEQ*DHEAD)
#define NEGV  (-1e30f)
#define EPSV  1.1920929e-7f
#define SCALEV 0.08838834764831845f

// ------------------------- scratch (device globals) -------------------------
__device__ __align__(256) float g_q [QKVN];
__device__ __align__(256) float g_qr[QKVN];
__device__ __align__(256) float g_kr[QKVN];
__device__ __align__(256) float g_v [QKVN];
__device__ __align__(256) float g_ckf[BATCH*HEADS*CM*DHEAD];
__device__ __align__(256) float g_cvf[BATCH*HEADS*CM*DHEAD];
__device__ __align__(256) float g_cout[QKVN];
__device__ __align__(256) float g_fout[QKVN];
__device__ __align__(256) float g_gates[ROWS*2*HEADS];
__device__ __align__(256) float g_imp_part[BATCH*HEADS*64*WBLK];
__device__ int g_idx[BATCH*HEADS*SELK];
__device__ int g_msk[BATCH*HEADS*SELK];

// bf16 hi/lo split operands
__device__ __align__(256) __nv_bfloat16 b_inp_h[ROWS*DIM],  b_inp_l[ROWS*DIM];
__device__ __align__(256) __nv_bfloat16 b_wq_h[DIM*DIM],    b_wq_l[DIM*DIM];
__device__ __align__(256) __nv_bfloat16 b_wk_h[DIM*DIM],    b_wk_l[DIM*DIM];
__device__ __align__(256) __nv_bfloat16 b_wv_h[DIM*DIM],    b_wv_l[DIM*DIM];
__device__ __align__(256) __nv_bfloat16 b_kw1_h[HIDC*HIDC], b_kw1_l[HIDC*HIDC];
__device__ __align__(256) __nv_bfloat16 b_vw1_h[HIDC*HIDC], b_vw1_l[HIDC*HIDC];
__device__ __align__(256) __nv_bfloat16 b_kw2_h[DHEAD*HIDC],b_kw2_l[DHEAD*HIDC];
__device__ __align__(256) __nv_bfloat16 b_vw2_h[DHEAD*HIDC],b_vw2_l[DHEAD*HIDC];
__device__ __align__(256) __nv_bfloat16 b_wo_h[DIM*DIM],    b_wo_l[DIM*DIM];
__device__ __align__(256) __nv_bfloat16 b_kc_h[QKVN],       b_kc_l[QKVN];
__device__ __align__(256) __nv_bfloat16 b_vc_h[QKVN],       b_vc_l[QKVN];
__device__ __align__(256) __nv_bfloat16 b_h1k_h[HIDC*HIDC], b_h1k_l[HIDC*HIDC];
__device__ __align__(256) __nv_bfloat16 b_h1v_h[HIDC*HIDC], b_h1v_l[HIDC*HIDC];
__device__ __align__(256) __nv_bfloat16 b_op_h[ROWS*DIM],   b_op_l[ROWS*DIM];

// ------------------------- helpers ------------------------------------------
__device__ __forceinline__ uint32_t smem_u32(const void* p){
    uint32_t a;
    asm("{ .reg .u64 t; cvta.to.shared.u64 t, %1; cvt.u32.u64 %0, t; }" : "=r"(a) : "l"(p));
    return a;
}
__device__ __forceinline__ void cp16(uint32_t saddr, const void* gaddr){
    asm volatile("cp.async.cg.shared.global [%0], [%1], 16;" :: "r"(saddr), "l"(gaddr));
}
__device__ __forceinline__ void mma16816(float* c, const uint32_t* a, const uint32_t* b){
    asm volatile("mma.sync.aligned.m16n8k16.row.col.f32.bf16.bf16.f32 "
        "{%0,%1,%2,%3}, {%4,%5,%6,%7}, {%8,%9}, {%0,%1,%2,%3};"
        : "+f"(c[0]), "+f"(c[1]), "+f"(c[2]), "+f"(c[3])
        : "r"(a[0]), "r"(a[1]), "r"(a[2]), "r"(a[3]), "r"(b[0]), "r"(b[1]));
}
__device__ __forceinline__ void ldsm4(uint32_t* r, uint32_t addr){
    asm volatile("ldmatrix.sync.aligned.m8n8.x4.shared.b16 {%0,%1,%2,%3}, [%4];"
        : "=r"(r[0]), "=r"(r[1]), "=r"(r[2]), "=r"(r[3]) : "r"(addr));
}
__device__ __forceinline__ void bsplit(float v, __nv_bfloat16& h, __nv_bfloat16& l){
    h = __float2bfloat16(v);
    l = __float2bfloat16(v - __bfloat162float(h));
}
#define DOT4(acc, a, b) \
    { acc += (a).x*(b).x; acc += (a).y*(b).y; acc += (a).z*(b).z; acc += (a).w*(b).w; }

// ------------------------- split-bf16 tensor-core GEMM ----------------------
// C[M,N] = A[M,K] @ B^T; 3-term: Ah*Bh + Ah*Bl + Al*Bh.
// EPI: 0 none, 1 +bias, 2 +bias+relu.
// PERM: 0 rowmajor (OUTB 0 fp32 / 1 bf16 split), 1 q+rope, 2 memshift,
//       3 k: rope->X1 +pos split->Ch/Cl, 4 v: raw->C +pos split->Ch/Cl.
// DUAL: 1 -> by>=gridDim.y/2 selects (A2,B2,bias2,C2,Ch2,Cl2).
#define KCH   64
#define ASTR  72
#define TELEM (128*ASTR)
#define STAGEE (4*TELEM)
#define GSMEM (2*STAGEE*2)             // 147456 bytes

template<int EPI, int PERM, int OUTB, int DUAL>
__global__ void __launch_bounds__(256, 1) tgemm_k(
    const __nv_bfloat16* __restrict__ Ah, const __nv_bfloat16* __restrict__ Al,
    const __nv_bfloat16* __restrict__ Bh, const __nv_bfloat16* __restrict__ Bl,
    const float* __restrict__ bias, float* __restrict__ C,
    __nv_bfloat16* __restrict__ Ch, __nv_bfloat16* __restrict__ Cl,
    float* __restrict__ X1, const float* __restrict__ pos,
    const __nv_bfloat16* __restrict__ A2h, const __nv_bfloat16* __restrict__ A2l,
    const __nv_bfloat16* __restrict__ B2h, const __nv_bfloat16* __restrict__ B2l,
    const float* __restrict__ bias2, float* __restrict__ C2,
    __nv_bfloat16* __restrict__ Ch2, __nv_bfloat16* __restrict__ Cl2,
    int M, int Nn, int K)
{
    extern __shared__ __nv_bfloat16 sm[];
    const uint32_t sb = smem_u32(sm);
    int tid = threadIdx.x;
    int warp = tid >> 5, lane = tid & 31;
    int wm = warp & 1, wn = warp >> 1;          // 2 x 4 warps, warp tile 64x32
    int grp = lane >> 2, tig = lane & 3;
    int bx = blockIdx.x, by = blockIdx.y;

    const __nv_bfloat16* Au = Ah; const __nv_bfloat16* Aul = Al;
    const __nv_bfloat16* Bu = Bh; const __nv_bfloat16* Bul = Bl;
    const float* bu = bias; float* Cu = C;
    __nv_bfloat16* Chu = Ch; __nv_bfloat16* Clu = Cl;
    if (DUAL) {
        int half = gridDim.y >> 1;
        if (by >= half) {
            Au = A2h; Aul = A2l; Bu = B2h; Bul = B2l;
            bu = bias2; Cu = C2; Chu = Ch2; Clu = Cl2;
            by -= half;
        }
    }

    const __nv_bfloat16* Agh = Au  + (size_t)by * 128 * K;
    const __nv_bfloat16* Agl = Aul + (size_t)by * 128 * K;
    const __nv_bfloat16* Bgh = Bu  + (size_t)bx * 128 * K;
    const __nv_bfloat16* Bgl = Bul + (size_t)bx * 128 * K;

    float acc[4][4][4];
#pragma unroll
    for (int i = 0; i < 4; i++)
#pragma unroll
        for (int j = 0; j < 4; j++)
#pragma unroll
            for (int r = 0; r < 4; r++) acc[i][j][r] = 0.f;

    int NC = K / KCH;

    auto load_stage = [&](int c, int s) {
        int k0 = c * KCH;
        uint32_t sbase = sb + s * STAGEE * 2;
#pragma unroll
        for (int i = 0; i < 4; i++) {
            int idx = tid + i * 256;
            int row = idx >> 3, kc = (idx & 7) * 8;
            uint32_t so = sbase + (uint32_t)(row * ASTR + kc) * 2;
            size_t go = (size_t)row * K + k0 + kc;
            cp16(so,                 Agh + go);
            cp16(so + TELEM * 2,     Agl + go);
            cp16(so + 2 * TELEM * 2, Bgh + go);
            cp16(so + 3 * TELEM * 2, Bgl + go);
        }
    };

    load_stage(0, 0);
    asm volatile("cp.async.commit_group;");

    int a_r  = lane & 15;
    int a_k8 = (lane >> 4) * 8;
    int b_l  = lane & 7;
    int b_seg = lane >> 3;
    int b_r  = (b_seg >= 2) ? b_l + 8 : b_l;
    int b_k8 = (b_seg & 1) * 8;

    for (int c = 0; c < NC; c++) {
        if (c + 1 < NC) {
            load_stage(c + 1, (c + 1) & 1);
            asm volatile("cp.async.commit_group;");
            asm volatile("cp.async.wait_group 1;");
        } else {
            asm volatile("cp.async.wait_group 0;");
        }
        __syncthreads();

        uint32_t sA  = sb + (c & 1) * STAGEE * 2;
        uint32_t sAl = sA + TELEM * 2;
        uint32_t sBh = sA + 2 * TELEM * 2;
        uint32_t sBl = sA + 3 * TELEM * 2;

#pragma unroll
        for (int ks = 0; ks < KCH / 16; ks++) {
            int kbase = ks * 16;
            uint32_t ah[4][4], al[4][4], bh[2][4], bl[2][4];
#pragma unroll
            for (int mt = 0; mt < 4; mt++) {
                uint32_t off = (uint32_t)((wm * 64 + mt * 16 + a_r) * ASTR + kbase + a_k8) * 2;
                ldsm4(ah[mt], sA  + off);
                ldsm4(al[mt], sAl + off);
            }
#pragma unroll
            for (int np = 0; np < 2; np++) {
                uint32_t off = (uint32_t)((wn * 32 + np * 16 + b_r) * ASTR + kbase + b_k8) * 2;
                ldsm4(bh[np], sBh + off);
                ldsm4(bl[np], sBl + off);
            }
#pragma unroll
            for (int mt = 0; mt < 4; mt++)
#pragma unroll
                for (int nt = 0; nt < 4; nt++) {
                    const uint32_t* bhp = &bh[nt >> 1][(nt & 1) * 2];
                    const uint32_t* blp = &bl[nt >> 1][(nt & 1) * 2];
                    mma16816(acc[mt][nt], ah[mt], bhp);
                    mma16816(acc[mt][nt], ah[mt], blp);
                    mma16816(acc[mt][nt], al[mt], bhp);
                }
        }
        __syncthreads();
    }

    // epilogue
#pragma unroll
    for (int mt = 0; mt < 4; mt++)
#pragma unroll
        for (int h8 = 0; h8 < 2; h8++) {
            int rowg = by * 128 + wm * 64 + mt * 16 + grp + h8 * 8;
#pragma unroll
            for (int nt = 0; nt < 4; nt++) {
                int colg = bx * 128 + wn * 32 + nt * 8 + tig * 2;
                float v0 = acc[mt][nt][h8 * 2 + 0];
                float v1 = acc[mt][nt][h8 * 2 + 1];
                if (EPI >= 1) { v0 += bu[colg]; v1 += bu[colg + 1]; }
                if (EPI == 2) { v0 = fmaxf(v0, 0.f); v1 = fmaxf(v1, 0.f); }
                if (PERM == 0) {
                    size_t rb = (size_t)rowg * Nn + colg;
                    if (OUTB) {
                        __nv_bfloat162 H, L;
                        bsplit(v0, H.x, L.x); bsplit(v1, H.y, L.y);
                        *(__nv_bfloat162*)(Chu + rb) = H;
                        *(__nv_bfloat162*)(Clu + rb) = L;
                    } else {
                        float2 p; p.x = v0; p.y = v1;
                        *(float2*)(Cu + rb) = p;
                    }
                } else if (PERM == 2) {
                    size_t rb = (size_t)(rowg + (rowg >> 7) + 1) * Nn + colg;
                    float2 p; p.x = v0; p.y = v1;
                    *(float2*)(Cu + rb) = p;
                } else {
                    int b = rowg >> 12, n = rowg & 4095;
                    int h = colg >> 7, d = colg & 127;
                    size_t dst = (((size_t)((b * HEADS + h) * SEQ + n)) << 7) + d;
                    if (PERM == 1 || PERM == 3) {
                        float inv = (float)exp(-(double)d * (9.210340371976184 / 128.0));
                        float t = (float)n * inv;
                        float s, cc; sincosf(t, &s, &cc);
                        float r0 = v0 * cc - v1 * s;
                        float r1 = v0 * s + v1 * cc;
                        float2 rp; rp.x = r0; rp.y = r1;
                        *(float2*)(X1 + dst) = rp;
                    }
                    if (PERM == 1 || PERM == 4) {
                        float2 p; p.x = v0; p.y = v1;
                        *(float2*)(Cu + dst) = p;
                    }
                    if (PERM == 3 || PERM == 4) {
                        const float* pp = pos + h * 4096 + (n & 31) * 128 + d;
                        __nv_bfloat162 H, L;
                        bsplit(v0 + pp[0], H.x, L.x);
                        bsplit(v1 + pp[1], H.y, L.y);
                        *(__nv_bfloat162*)(Chu + dst) = H;
                        *(__nv_bfloat162*)(Clu + dst) = L;
                    }
                }
            }
        }
}

// ------------------------- fp32 -> hi/lo bf16 convert ------------------------
__global__ void cvt_k(const float4* __restrict__ x, __nv_bfloat162* __restrict__ hi,
                      __nv_bfloat162* __restrict__ lo, int n4)
{
    int i = blockIdx.x * 256 + threadIdx.x;
    if (i >= n4) return;
    float4 v = x[i];
    __nv_bfloat162 H0, H1, L0, L1;
    bsplit(v.x, H0.x, L0.x); bsplit(v.y, H0.y, L0.y);
    bsplit(v.z, H1.x, L1.x); bsplit(v.w, H1.y, L1.y);
    hi[i * 2] = H0; hi[i * 2 + 1] = H1;
    lo[i * 2] = L0; lo[i * 2 + 1] = L1;
}

// transpose-convert: W[K,N] fp32 -> Wt hi/lo [N,K] bf16
__global__ void cvtT_k(const float* __restrict__ x, __nv_bfloat16* __restrict__ hi,
                       __nv_bfloat16* __restrict__ lo, int K, int N)
{
    __shared__ float t[32][33];
    int bx = blockIdx.x, by = blockIdx.y;
    int tx = threadIdx.x & 31, ty = threadIdx.x >> 5;
#pragma unroll
    for (int i = 0; i < 32; i += 8) {
        int kk = by * 32 + ty + i;
        t[ty + i][tx] = x[(size_t)kk * N + bx * 32 + tx];
    }
    __syncthreads();
#pragma unroll
    for (int i = 0; i < 32; i += 8) {
        int n = bx * 32 + ty + i;
        int kk = by * 32 + tx;
        float v = t[tx][ty + i];
        __nv_bfloat16 h, l; bsplit(v, h, l);
        hi[(size_t)n * K + kk] = h;
        lo[(size_t)n * K + kk] = l;
    }
}

// ------------------------- fused rmsnorm + gates ----------------------------
__global__ void gates_k(const float* __restrict__ inp, const float* __restrict__ g,
                        const float* __restrict__ Wg, const float* __restrict__ bg,
                        float* __restrict__ gates)
{
    __shared__ float xs[DIM];
    __shared__ float red[8];
    int row = blockIdx.x;
    int tid = threadIdx.x;
    const float* ip = inp + (size_t)row * DIM;
    float ss = 0.f;
    for (int k = tid; k < DIM; k += 256) { float v = ip[k]; xs[k] = v; ss += v * v; }
#pragma unroll
    for (int o = 16; o > 0; o >>= 1) ss += __shfl_xor_sync(~0u, ss, o);
    if ((tid & 31) == 0) red[tid >> 5] = ss;
    __syncthreads();
    float tot = red[0] + red[1] + red[2] + red[3] + red[4] + red[5] + red[6] + red[7];
    float rn = 1.0f / sqrtf(tot * (1.0f / DIM) + EPSV);
    int lane = tid & 31, warp = tid >> 5;
    for (int c = warp; c < 2 * HEADS; c += 8) {
        float acc = 0.f;
        for (int k = lane; k < DIM; k += 32) acc += xs[k] * g[k] * Wg[(size_t)k * (2 * HEADS) + c];
#pragma unroll
        for (int o = 16; o > 0; o >>= 1) acc += __shfl_xor_sync(~0u, acc, o);
        if (lane == 0) gates[(size_t)row * (2 * HEADS) + c] = 1.f / (1.f + expf(-(acc * rn + bg[c])));
    }
}

// ------------------------- mem slots into ckf/cvf ---------------------------
__global__ void fillmem_k(const float* __restrict__ memkv,
                          float* __restrict__ ckf, float* __restrict__ cvf)
{
    int idx = blockIdx.x * 256 + threadIdx.x;
    if (idx >= BATCH * HEADS * DHEAD) return;
    int d = idx & 127; int h = (idx >> 7) & 15; int b = idx >> 11;
    size_t dst = (((size_t)((b * HEADS + h) * CM)) << 7) + d;
    ckf[dst] = memkv[h * 128 + d];
    cvf[dst] = memkv[HEADS * 128 + h * 128 + d];
}

// ------------------------- compressed attention -----------------------------
__global__ void __launch_bounds__(256) attn_c_k(
    const float* __restrict__ q, const float* __restrict__ ckf,
    const float* __restrict__ cvf, float* __restrict__ cout,
    float* __restrict__ imp_part)
{
    extern __shared__ float smf[];
    float* qs   = smf;
    float* sims = smf + 64 * 128;
    float* cs   = sims + 64 * 132;
    int tid = threadIdx.x;
    int bh = blockIdx.y, n0 = blockIdx.x * 64;
    const float* qb = q + (((size_t)bh * SEQ + n0) << 7);
#pragma unroll
    for (int i = 0; i < 8; i++) {
        int vdx = tid + i * 256;
        int row = vdx >> 5, c4 = (vdx & 31) * 4;
        *(float4*)&qs[row * 128 + c4] = *(const float4*)(qb + row * 128 + c4);
    }
    int tx = tid & 15, ty = tid >> 4;

    for (int m0 = 0; m0 < CM; m0 += 32) {
        int mc = (CM - m0 < 32) ? (CM - m0) : 32;
        for (int vdx = tid; vdx < mc * 32; vdx += 256) {
            int rr = vdx >> 5, c4 = (vdx & 31) * 4;
            float4 t = *(const float4*)(ckf + (((size_t)bh * CM + m0 + rr) << 7) + c4);
            cs[rr * 132 + c4 + 0] = t.x; cs[rr * 132 + c4 + 1] = t.y;
            cs[rr * 132 + c4 + 2] = t.z; cs[rr * 132 + c4 + 3] = t.w;
        }
        __syncthreads();
        float a0[2] = {0, 0}, a1[2] = {0, 0}, a2[2] = {0, 0}, a3[2] = {0, 0};
#pragma unroll 8
        for (int k = 0; k < 128; k += 4) {
            float4 q0 = *(float4*)&qs[(ty * 4 + 0) * 128 + k];
            float4 q1 = *(float4*)&qs[(ty * 4 + 1) * 128 + k];
            float4 q2 = *(float4*)&qs[(ty * 4 + 2) * 128 + k];
            float4 q3 = *(float4*)&qs[(ty * 4 + 3) * 128 + k];
            float4 c0 = *(float4*)&cs[(tx * 2 + 0) * 132 + k];
            float4 c1 = *(float4*)&cs[(tx * 2 + 1) * 132 + k];
            DOT4(a0[0], q0, c0); DOT4(a0[1], q0, c1);
            DOT4(a1[0], q1, c0); DOT4(a1[1], q1, c1);
            DOT4(a2[0], q2, c0); DOT4(a2[1], q2, c1);
            DOT4(a3[0], q3, c0); DOT4(a3[1], q3, c1);
        }
#pragma unroll
        for (int mm = 0; mm < 2; mm++) {
            int m = tx * 2 + mm;
            if (m < mc) {
                sims[(ty * 4 + 0) * 132 + m0 + m] = a0[mm] * SCALEV;
                sims[(ty * 4 + 1) * 132 + m0 + m] = a1[mm] * SCALEV;
                sims[(ty * 4 + 2) * 132 + m0 + m] = a2[mm] * SCALEV;
                sims[(ty * 4 + 3) * 132 + m0 + m] = a3[mm] * SCALEV;
            }
        }
        __syncthreads();
    }

    {
        int lane = tid & 31, wrp = tid >> 5;
        for (int r = wrp; r < 64; r += 8) {
            float* srow = sims + r * 132;
            float mx = -1e38f;
            for (int m = lane; m < CM; m += 32) mx = fmaxf(mx, srow[m]);
#pragma unroll
            for (int o = 16; o > 0; o >>= 1) mx = fmaxf(mx, __shfl_xor_sync(~0u, mx, o));
            float sum = 0.f;
            for (int m = lane; m < CM; m += 32) { float e = expf(srow[m] - mx); srow[m] = e; sum += e; }
#pragma unroll
            for (int o = 16; o > 0; o >>= 1) sum += __shfl_xor_sync(~0u, sum, o);
            float inv = 1.f / sum;
            for (int m = lane; m < CM; m += 32) srow[m] *= inv;
        }
    }
    __syncthreads();
    if (tid < 128) {
        float s = 0.f;
        for (int r = 0; r < 64; r++) s += sims[r * 132 + 1 + tid];
        imp_part[(((size_t)bh * 64) + blockIdx.x) * 128 + tid] = s;
    }
    __syncthreads();

    float oacc[4][8];
#pragma unroll
    for (int i = 0; i < 4; i++)
#pragma unroll
        for (int j = 0; j < 8; j++) oacc[i][j] = 0.f;

    for (int m0 = 0; m0 < CM; m0 += 32) {
        int mc = (CM - m0 < 32) ? (CM - m0) : 32;
        for (int vdx = tid; vdx < mc * 32; vdx += 256) {
            int rr = vdx >> 5, c4 = (vdx & 31) * 4;
            float4 t = *(const float4*)(cvf + (((size_t)bh * CM + m0 + rr) << 7) + c4);
            cs[rr * 132 + c4 + 0] = t.x; cs[rr * 132 + c4 + 1] = t.y;
            cs[rr * 132 + c4 + 2] = t.z; cs[rr * 132 + c4 + 3] = t.w;
        }
        __syncthreads();
        for (int mm = 0; mm < mc; mm++) {
            float p0 = sims[(ty * 4 + 0) * 132 + m0 + mm];
            float p1 = sims[(ty * 4 + 1) * 132 + m0 + mm];
            float p2 = sims[(ty * 4 + 2) * 132 + m0 + mm];
            float p3 = sims[(ty * 4 + 3) * 132 + m0 + mm];
            float bv[8];
            *(float4*)&bv[0] = *(float4*)&cs[mm * 132 + tx * 8];
            *(float4*)&bv[4] = *(float4*)&cs[mm * 132 + tx * 8 + 4];
#pragma unroll
            for (int j = 0; j < 8; j++) {
                oacc[0][j] += p0 * bv[j];
                oacc[1][j] += p1 * bv[j];
                oacc[2][j] += p2 * bv[j];
                oacc[3][j] += p3 * bv[j];
            }
        }
        __syncthreads();
    }
#pragma unroll
    for (int rr = 0; rr < 4; rr++) {
        size_t dst = (((size_t)bh * SEQ) + n0 + ty * 4 + rr) * 128 + tx * 8;
        *(float4*)&cout[dst]     = *(float4*)&oacc[rr][0];
        *(float4*)&cout[dst + 4] = *(float4*)&oacc[rr][4];
    }
}

// ------------------------- importance reduce + top-k ------------------------
__global__ void topk_k(const float* __restrict__ imp_part,
                       int* __restrict__ idxout, int* __restrict__ maskout)
{
    __shared__ float vals[WBLK];
    int bh = blockIdx.x, tid = threadIdx.x;
    float s = 0.f;
    for (int t = 0; t < 64; t++) s += imp_part[(((size_t)bh * 64) + t) * 128 + tid];
    vals[tid] = s * (1.0f / SEQ);
    __syncthreads();
    if (tid == 0) {
        for (int sel = 0; sel < SELK; sel++) {
            float best = -1e38f; int bi = 0;
            for (int m = 0; m < WBLK; m++)
                if (vals[m] > best) { best = vals[m]; bi = m; }
            idxout[bh * SELK + sel] = bi;
            maskout[bh * SELK + sel] = (best > 1e-10f) ? 1 : 0;
            vals[bi] = -1e38f;
        }
    }
}

// ------------------------- selected (fine) attention, fused gather ----------
__global__ void __launch_bounds__(256) attn_f_k(
    const float* __restrict__ qr, const float* __restrict__ kr,
    const float* __restrict__ v, const int* __restrict__ idxs,
    const int* __restrict__ fmask, float* __restrict__ fout)
{
    extern __shared__ float smf[];
    float* qs   = smf;
    float* sims = smf + 4096;
    float* cs   = sims + 16512;
    __shared__ int maskS[SELK];
    __shared__ int blkS[SELK];
    int tid = threadIdx.x;
    int bh = blockIdx.y, n0 = blockIdx.x * 32;
    if (tid < SELK) {
        maskS[tid] = fmask[bh * SELK + tid];
        blkS[tid]  = idxs[bh * SELK + tid];
    }
    const float* qb = qr + (((size_t)bh * SEQ + n0) << 7);
#pragma unroll
    for (int i = 0; i < 4; i++) {
        int vdx = tid + i * 256;
        int row = vdx >> 5, c4 = (vdx & 31) * 4;
        *(float4*)&qs[row * 128 + c4] = *(const float4*)(qb + row * 128 + c4);
    }
    __syncthreads();
    int tx = tid & 15, ty = tid >> 4;

    for (int m0 = 0; m0 < 512; m0 += 32) {
        int blk = blkS[m0 >> 5];
        const float* kb = kr + (((size_t)bh * SEQ + blk * BLKSZ) << 7);
        for (int vdx = tid; vdx < 32 * 32; vdx += 256) {
            int rr = vdx >> 5, c4 = (vdx & 31) * 4;
            float4 t = *(const float4*)(kb + ((size_t)rr << 7) + c4);
            cs[rr * 132 + c4 + 0] = t.x; cs[rr * 132 + c4 + 1] = t.y;
            cs[rr * 132 + c4 + 2] = t.z; cs[rr * 132 + c4 + 3] = t.w;
        }
        __syncthreads();
        float a00 = 0, a01 = 0, a10 = 0, a11 = 0;
#pragma unroll 8
        for (int k = 0; k < 128; k += 4) {
            float4 q0 = *(float4*)&qs[(ty * 2 + 0) * 128 + k];
            float4 q1 = *(float4*)&qs[(ty * 2 + 1) * 128 + k];
            float4 c0 = *(float4*)&cs[(tx * 2 + 0) * 132 + k];
            float4 c1 = *(float4*)&cs[(tx * 2 + 1) * 132 + k];
            DOT4(a00, q0, c0); DOT4(a01, q0, c1);
            DOT4(a10, q1, c0); DOT4(a11, q1, c1);
        }
        sims[(ty * 2 + 0) * 516 + m0 + tx * 2 + 0] = a00 * SCALEV;
        sims[(ty * 2 + 0) * 516 + m0 + tx * 2 + 1] = a01 * SCALEV;
        sims[(ty * 2 + 1) * 516 + m0 + tx * 2 + 0] = a10 * SCALEV;
        sims[(ty * 2 + 1) * 516 + m0 + tx * 2 + 1] = a11 * SCALEV;
        __syncthreads();
    }

    {
        int lane = tid & 31, wrp = tid >> 5;
        for (int r = wrp; r < 32; r += 8) {
            float* srow = sims + r * 516;
            float mx = -1e38f;
            for (int m = lane; m < 512; m += 32) {
                float vv = srow[m];
                if (!maskS[m >> 5]) vv = NEGV;
                srow[m] = vv;
                mx = fmaxf(mx, vv);
            }
#pragma unroll
            for (int o = 16; o > 0; o >>= 1) mx = fmaxf(mx, __shfl_xor_sync(~0u, mx, o));
            float sum = 0.f;
            for (int m = lane; m < 512; m += 32) { float e = expf(srow[m] - mx); srow[m] = e; sum += e; }
#pragma unroll
            for (int o = 16; o > 0; o >>= 1) sum += __shfl_xor_sync(~0u, sum, o);
            float inv = 1.f / sum;
            for (int m = lane; m < 512; m += 32) srow[m] *= inv;
        }
    }
    __syncthreads();

    float o0[8], o1[8];
#pragma unroll
    for (int j = 0; j < 8; j++) { o0[j] = 0.f; o1[j] = 0.f; }
    for (int m0 = 0; m0 < 512; m0 += 32) {
        int blk = blkS[m0 >> 5];
        const float* vb = v + (((size_t)bh * SEQ + blk * BLKSZ) << 7);
        for (int vdx = tid; vdx < 32 * 32; vdx += 256) {
            int rr = vdx >> 5, c4 = (vdx & 31) * 4;
            float4 t = *(const float4*)(vb + ((size_t)rr << 7) + c4);
            cs[rr * 132 + c4 + 0] = t.x; cs[rr * 132 + c4 + 1] = t.y;
            cs[rr * 132 + c4 + 2] = t.z; cs[rr * 132 + c4 + 3] = t.w;
        }
        __syncthreads();
        for (int mm = 0; mm < 32; mm++) {
            float p0 = sims[(ty * 2 + 0) * 516 + m0 + mm];
            float p1 = sims[(ty * 2 + 1) * 516 + m0 + mm];
            float bv[8];
            *(float4*)&bv[0] = *(float4*)&cs[mm * 132 + tx * 8];
            *(float4*)&bv[4] = *(float4*)&cs[mm * 132 + tx * 8 + 4];
#pragma unroll
            for (int j = 0; j < 8; j++) { o0[j] += p0 * bv[j]; o1[j] += p1 * bv[j]; }
        }
        __syncthreads();
    }
    size_t dst0 = (((size_t)bh * SEQ) + n0 + ty * 2 + 0) * 128 + tx * 8;
    size_t dst1 = (((size_t)bh * SEQ) + n0 + ty * 2 + 1) * 128 + tx * 8;
    *(float4*)&fout[dst0] = *(float4*)&o0[0]; *(float4*)&fout[dst0 + 4] = *(float4*)&o0[4];
    *(float4*)&fout[dst1] = *(float4*)&o1[0]; *(float4*)&fout[dst1 + 4] = *(float4*)&o1[4];
}

// ------------------------- combine gates -> bf16 hi/lo ----------------------
__global__ void combine2_k(const float* __restrict__ cout, const float* __restrict__ fout,
                           const float* __restrict__ gates,
                           __nv_bfloat16* __restrict__ oh, __nv_bfloat16* __restrict__ ol)
{
    int idx = blockIdx.x * 256 + threadIdx.x;
    int d = idx & 127; int h = (idx >> 7) & 15; int nrow = idx >> 11;
    int b = nrow >> 12; int n = nrow & 4095;
    size_t src = (((size_t)(b * HEADS + h) * SEQ) + n) * 128 + d;
    float g0 = gates[(size_t)nrow * (2 * HEADS) + 2 * h];
    float g1 = gates[(size_t)nrow * (2 * HEADS) + 2 * h + 1];
    float v = g0 * cout[src] + g1 * fout[src];
    __nv_bfloat16 hh, ll; bsplit(v, hh, ll);
    oh[idx] = hh; ol[idx] = ll;
}

// ------------------------- launch ------------------------------------------
extern "C" void kernel_launch(void* const* d_in, const int* in_sizes, int n_in,
                              void* d_out, int out_size)
{
    const float* inp  = (const float*)d_in[0];
    const float* g    = (const float*)d_in[1];
    const float* Wq   = (const float*)d_in[2];
    const float* Wk   = (const float*)d_in[3];
    const float* Wv   = (const float*)d_in[4];
    const float* kpos = (const float*)d_in[5];
    const float* vpos = (const float*)d_in[6];
    const float* memkv= (const float*)d_in[7];
    const float* kW1  = (const float*)d_in[8];
    const float* kb1  = (const float*)d_in[9];
    const float* kW2  = (const float*)d_in[10];
    const float* kb2  = (const float*)d_in[11];
    const float* vW1  = (const float*)d_in[12];
    const float* vb1  = (const float*)d_in[13];
    const float* vW2  = (const float*)d_in[14];
    const float* vb2  = (const float*)d_in[15];
    const float* Wg   = (const float*)d_in[16];
    const float* bg   = (const float*)d_in[17];
    const float* Wo   = (const float*)d_in[18];
    float* out = (float*)d_out;

    float *q, *qr, *kr, *v, *ckf, *cvf, *cout, *fout, *gates, *imp;
    int *idxs, *msk;
    cudaGetSymbolAddress((void**)&q,    g_q);
    cudaGetSymbolAddress((void**)&qr,   g_qr);
    cudaGetSymbolAddress((void**)&kr,   g_kr);
    cudaGetSymbolAddress((void**)&v,    g_v);
    cudaGetSymbolAddress((void**)&ckf,  g_ckf);
    cudaGetSymbolAddress((void**)&cvf,  g_cvf);
    cudaGetSymbolAddress((void**)&cout, g_cout);
    cudaGetSymbolAddress((void**)&fout, g_fout);
    cudaGetSymbolAddress((void**)&gates,g_gates);
    cudaGetSymbolAddress((void**)&imp,  g_imp_part);
    cudaGetSymbolAddress((void**)&idxs, g_idx);
    cudaGetSymbolAddress((void**)&msk,  g_msk);

    __nv_bfloat16 *inph,*inpl,*wqh,*wql,*wkh,*wkl,*wvh,*wvl,*kw1h,*kw1l,*vw1h,*vw1l;
    __nv_bfloat16 *kw2h,*kw2l,*vw2h,*vw2l,*woh,*wol,*kch,*kcl,*vch,*vcl;
    __nv_bfloat16 *h1kh,*h1kl,*h1vh,*h1vl,*oph,*opl;
    cudaGetSymbolAddress((void**)&inph, b_inp_h); cudaGetSymbolAddress((void**)&inpl, b_inp_l);
    cudaGetSymbolAddress((void**)&wqh,  b_wq_h);  cudaGetSymbolAddress((void**)&wql,  b_wq_l);
    cudaGetSymbolAddress((void**)&wkh,  b_wk_h);  cudaGetSymbolAddress((void**)&wkl,  b_wk_l);
    cudaGetSymbolAddress((void**)&wvh,  b_wv_h);  cudaGetSymbolAddress((void**)&wvl,  b_wv_l);
    cudaGetSymbolAddress((void**)&kw1h, b_kw1_h); cudaGetSymbolAddress((void**)&kw1l, b_kw1_l);
    cudaGetSymbolAddress((void**)&vw1h, b_vw1_h); cudaGetSymbolAddress((void**)&vw1l, b_vw1_l);
    cudaGetSymbolAddress((void**)&kw2h, b_kw2_h); cudaGetSymbolAddress((void**)&kw2l, b_kw2_l);
    cudaGetSymbolAddress((void**)&vw2h, b_vw2_h); cudaGetSymbolAddress((void**)&vw2l, b_vw2_l);
    cudaGetSymbolAddress((void**)&woh,  b_wo_h);  cudaGetSymbolAddress((void**)&wol,  b_wo_l);
    cudaGetSymbolAddress((void**)&kch,  b_kc_h);  cudaGetSymbolAddress((void**)&kcl,  b_kc_l);
    cudaGetSymbolAddress((void**)&vch,  b_vc_h);  cudaGetSymbolAddress((void**)&vcl,  b_vc_l);
    cudaGetSymbolAddress((void**)&h1kh, b_h1k_h); cudaGetSymbolAddress((void**)&h1kl, b_h1k_l);
    cudaGetSymbolAddress((void**)&h1vh, b_h1v_h); cudaGetSymbolAddress((void**)&h1vl, b_h1v_l);
    cudaGetSymbolAddress((void**)&oph,  b_op_h);  cudaGetSymbolAddress((void**)&opl,  b_op_l);

    const int SMEM_C = (64 * 128 + 64 * 132 + 32 * 132) * 4;
    const int SMEM_F = (32 * 128 + 32 * 516 + 32 * 132) * 4;
    cudaFuncSetAttribute(attn_c_k, cudaFuncAttributeMaxDynamicSharedMemorySize, SMEM_C);
    cudaFuncSetAttribute(attn_f_k, cudaFuncAttributeMaxDynamicSharedMemorySize, SMEM_F);
    cudaFuncSetAttribute(tgemm_k<0,1,0,0>, cudaFuncAttributeMaxDynamicSharedMemorySize, GSMEM);
    cudaFuncSetAttribute(tgemm_k<0,3,0,0>, cudaFuncAttributeMaxDynamicSharedMemorySize, GSMEM);
    cudaFuncSetAttribute(tgemm_k<0,4,0,0>, cudaFuncAttributeMaxDynamicSharedMemorySize, GSMEM);
    cudaFuncSetAttribute(tgemm_k<2,0,1,1>, cudaFuncAttributeMaxDynamicSharedMemorySize, GSMEM);
    cudaFuncSetAttribute(tgemm_k<1,2,0,1>, cudaFuncAttributeMaxDynamicSharedMemorySize, GSMEM);
    cudaFuncSetAttribute(tgemm_k<0,0,0,0>, cudaFuncAttributeMaxDynamicSharedMemorySize, GSMEM);

    // 0) converts
    cvt_k<<<(ROWS*DIM/4 + 255)/256, 256>>>((const float4*)inp, (__nv_bfloat162*)inph, (__nv_bfloat162*)inpl, ROWS*DIM/4);
    cvtT_k<<<dim3(DIM/32, DIM/32), 256>>>(Wq, wqh, wql, DIM, DIM);
    cvtT_k<<<dim3(DIM/32, DIM/32), 256>>>(Wk, wkh, wkl, DIM, DIM);
    cvtT_k<<<dim3(DIM/32, DIM/32), 256>>>(Wv, wvh, wvl, DIM, DIM);
    cvtT_k<<<dim3(HIDC/32, HIDC/32), 256>>>(kW1, kw1h, kw1l, HIDC, HIDC);

    // 1) QKV projections with fused RoPE / pos-pack epilogues
    dim3 gq(DIM/128, ROWS/128);
    tgemm_k<0,1,0,0><<<gq, 256, GSMEM>>>(inph, inpl, wqh, wql, nullptr, q, nullptr, nullptr,
        qr, nullptr, nullptr, nullptr, nullptr, nullptr, nullptr, nullptr, nullptr, nullptr,
        ROWS, DIM, DIM);
    tgemm_k<0,3,0,0><<<gq, 256, GSMEM>>>(inph, inpl, wkh, wkl, nullptr, nullptr, kch, kcl,
        kr, kpos, nullptr, nullptr, nullptr, nullptr, nullptr, nullptr, nullptr, nullptr,
        ROWS, DIM, DIM);
    tgemm_k<0,4,0,0><<<gq, 256, GSMEM>>>(inph, inpl, wvh, wvl, nullptr, v, vch, vcl,
        nullptr, vpos, nullptr, nullptr, nullptr, nullptr, nullptr, nullptr, nullptr, nullptr,
        ROWS, DIM, DIM);

    // remaining converts + gates (overlap with GEMM tails)
    cvtT_k<<<dim3(HIDC/32, HIDC/32), 256>>>(vW1, vw1h, vw1l, HIDC, HIDC);
    cvtT_k<<<dim3(DHEAD/32, HIDC/32), 256>>>(kW2, kw2h, kw2l, HIDC, DHEAD);
    cvtT_k<<<dim3(DHEAD/32, HIDC/32), 256>>>(vW2, vw2h, vw2l, HIDC, DHEAD);
    cvtT_k<<<dim3(DIM/32, DIM/32), 256>>>(Wo, woh, wol, DIM, DIM);
    gates_k<<<ROWS, 256>>>(inp, g, Wg, bg, gates);

    // 3) compress MLP layer 1 — k and v merged into one dual launch
    tgemm_k<2,0,1,1><<<dim3(HIDC/128, 2*(HIDC/128)), 256, GSMEM>>>(
        kch, kcl, kw1h, kw1l, kb1, nullptr, h1kh, h1kl, nullptr, nullptr,
        vch, vcl, vw1h, vw1l, vb1, nullptr, h1vh, h1vl,
        BATCH*HEADS*WBLK, HIDC, HIDC);

    // 4) compress MLP layer 2 — k and v merged into one dual launch
    tgemm_k<1,2,0,1><<<dim3(1, 64), 256, GSMEM>>>(
        h1kh, h1kl, kw2h, kw2l, kb2, ckf, nullptr, nullptr, nullptr, nullptr,
        h1vh, h1vl, vw2h, vw2l, vb2, cvf, nullptr, nullptr,
        BATCH*HEADS*WBLK, DHEAD, HIDC);
    fillmem_k<<<16, 256>>>(memkv, ckf, cvf);

    // 5) compressed attention + importance partials
    attn_c_k<<<dim3(SEQ/64, BATCH*HEADS), 256, SMEM_C>>>(q, ckf, cvf, cout, imp);

    // 6) top-k
    topk_k<<<BATCH*HEADS, 128>>>(imp, idxs, msk);

    // 7) fine attention (gather fused via block indices)
    attn_f_k<<<dim3(SEQ/32, BATCH*HEADS), 256, SMEM_F>>>(qr, kr, v, idxs, msk, fout);

    // 8) gate-combine -> split bf16
    combine2_k<<<QKVN/256, 256>>>(cout, fout, gates, oph, opl);

    // 9) output projection (fp32 out)
    tgemm_k<0,0,0,0><<<dim3(DIM/128, ROWS/128), 256, GSMEM>>>(
        oph, opl, woh, wol, nullptr, out, nullptr, nullptr, nullptr, nullptr,
        nullptr, nullptr, nullptr, nullptr, nullptr, nullptr, nullptr, nullptr,
        ROWS, DIM, DIM);
}

// round 12
// speedup vs baseline: 1.0070x; 1.0070x over previous
#include <cuda_runtime.h>
#include <cuda_fp16.h>
#include <math.h>
#include <stdint.h>

// Problem constants
#define BATCH 2
#define SEQ   4096
#define DIM   2048
#define HEADS 16
#define DHEAD 128
#define BLKSZ 32
#define SELK  16
#define HIDC  4096
#define WBLK  128
#define CM    129
#define ROWS  (BATCH*SEQ)
#define QKVN  (BATCH*HEADS*SEQ*DHEAD)
#define NEGV  (-1e30f)
#define EPSV  1.1920929e-7f
#define SCALEV 0.08838834764831845f

// ------------------------- scratch (device globals) -------------------------
__device__ __align__(256) float g_q [QKVN];
__device__ __align__(256) float g_qr[QKVN];
__device__ __align__(256) float g_kr[QKVN];
__device__ __align__(256) float g_v [QKVN];
__device__ __align__(256) float g_ckf[BATCH*HEADS*CM*DHEAD];
__device__ __align__(256) float g_cvf[BATCH*HEADS*CM*DHEAD];
__device__ __align__(256) float g_cout[QKVN];
__device__ __align__(256) float g_fout[QKVN];
__device__ __align__(256) float g_gates[ROWS*2*HEADS];
__device__ __align__(256) float g_imp_part[BATCH*HEADS*64*WBLK];
__device__ int g_idx[BATCH*HEADS*SELK];
__device__ int g_msk[BATCH*HEADS*SELK];

// fp16 hi/lo split operands
__device__ __align__(256) __half b_inp_h[ROWS*DIM],  b_inp_l[ROWS*DIM];
__device__ __align__(256) __half b_wq_h[DIM*DIM],    b_wq_l[DIM*DIM];
__device__ __align__(256) __half b_wk_h[DIM*DIM],    b_wk_l[DIM*DIM];
__device__ __align__(256) __half b_wv_h[DIM*DIM],    b_wv_l[DIM*DIM];
__device__ __align__(256) __half b_kw1_h[HIDC*HIDC], b_kw1_l[HIDC*HIDC];
__device__ __align__(256) __half b_vw1_h[HIDC*HIDC], b_vw1_l[HIDC*HIDC];
__device__ __align__(256) __half b_kw2_h[DHEAD*HIDC],b_kw2_l[DHEAD*HIDC];
__device__ __align__(256) __half b_vw2_h[DHEAD*HIDC],b_vw2_l[DHEAD*HIDC];
__device__ __align__(256) __half b_wo_h[DIM*DIM],    b_wo_l[DIM*DIM];
__device__ __align__(256) __half b_kc_h[QKVN],       b_kc_l[QKVN];
__device__ __align__(256) __half b_vc_h[QKVN],       b_vc_l[QKVN];
__device__ __align__(256) __half b_h1k_h[HIDC*HIDC], b_h1k_l[HIDC*HIDC];
__device__ __align__(256) __half b_h1v_h[HIDC*HIDC], b_h1v_l[HIDC*HIDC];
__device__ __align__(256) __half b_op_h[ROWS*DIM],   b_op_l[ROWS*DIM];

// ------------------------- helpers ------------------------------------------
__device__ __forceinline__ uint32_t smem_u32(const void* p){
    uint32_t a;
    asm("{ .reg .u64 t; cvta.to.shared.u64 t, %1; cvt.u32.u64 %0, t; }" : "=r"(a) : "l"(p));
    return a;
}
__device__ __forceinline__ void cp16(uint32_t saddr, const void* gaddr){
    asm volatile("cp.async.cg.shared.global [%0], [%1], 16;" :: "r"(saddr), "l"(gaddr));
}
// fp16 inputs, fp32 accumulate (hi*hi term)
__device__ __forceinline__ void mma_f32(float* c, const uint32_t* a, const uint32_t* b){
    asm volatile("mma.sync.aligned.m16n8k16.row.col.f32.f16.f16.f32 "
        "{%0,%1,%2,%3}, {%4,%5,%6,%7}, {%8,%9}, {%0,%1,%2,%3};"
        : "+f"(c[0]), "+f"(c[1]), "+f"(c[2]), "+f"(c[3])
        : "r"(a[0]), "r"(a[1]), "r"(a[2]), "r"(a[3]), "r"(b[0]), "r"(b[1]));
}
// fp16 inputs, fp16 accumulate (cross terms; corrections ~2^-12 of output)
__device__ __forceinline__ void mma_f16(uint32_t* c, const uint32_t* a, const uint32_t* b){
    asm volatile("mma.sync.aligned.m16n8k16.row.col.f16.f16.f16.f16 "
        "{%0,%1}, {%2,%3,%4,%5}, {%6,%7}, {%0,%1};"
        : "+r"(c[0]), "+r"(c[1])
        : "r"(a[0]), "r"(a[1]), "r"(a[2]), "r"(a[3]), "r"(b[0]), "r"(b[1]));
}
__device__ __forceinline__ void ldsm4(uint32_t* r, uint32_t addr){
    asm volatile("ldmatrix.sync.aligned.m8n8.x4.shared.b16 {%0,%1,%2,%3}, [%4];"
        : "=r"(r[0]), "=r"(r[1]), "=r"(r[2]), "=r"(r[3]) : "r"(addr));
}
__device__ __forceinline__ void hsplit(float v, __half& h, __half& l){
    h = __float2half_rn(v);
    l = __float2half_rn(v - __half2float(h));
}

// ------------------------- split-fp16 tensor-core GEMM ----------------------
// C[M,N] = A[M,K] @ B^T; terms: Ah*Bh (f32 acc) + Ah*Bl + Al*Bh (f16 acc).
// EPI: 0 none, 1 +bias, 2 +bias+relu.
// PERM: 0 rowmajor (OUTB 0 fp32 / 1 fp16 split), 1 q+rope, 2 memshift,
//       3 k: rope->X1 +pos split->Ch/Cl, 4 v: raw->C +pos split->Ch/Cl.
// DUAL: 1 -> by>=gridDim.y/2 selects second operand set.
#define KCH   64
#define ASTR  72
#define TELEM (128*ASTR)
#define STAGEE (4*TELEM)
#define GSMEM (2*STAGEE*2)             // 147456 bytes

template<int EPI, int PERM, int OUTB, int DUAL>
__global__ void __launch_bounds__(256, 1) tgemm_k(
    const __half* __restrict__ Ah, const __half* __restrict__ Al,
    const __half* __restrict__ Bh, const __half* __restrict__ Bl,
    const float* __restrict__ bias, float* __restrict__ C,
    __half* __restrict__ Ch, __half* __restrict__ Cl,
    float* __restrict__ X1, const float* __restrict__ pos,
    const __half* __restrict__ A2h, const __half* __restrict__ A2l,
    const __half* __restrict__ B2h, const __half* __restrict__ B2l,
    const float* __restrict__ bias2, float* __restrict__ C2,
    __half* __restrict__ Ch2, __half* __restrict__ Cl2,
    int M, int Nn, int K)
{
    extern __shared__ __half sm[];
    const uint32_t sb = smem_u32(sm);
    int tid = threadIdx.x;
    int warp = tid >> 5, lane = tid & 31;
    int wm = warp & 1, wn = warp >> 1;          // 2 x 4 warps, warp tile 64x32
    int grp = lane >> 2, tig = lane & 3;
    int bx = blockIdx.x, by = blockIdx.y;

    const __half* Au = Ah; const __half* Aul = Al;
    const __half* Bu = Bh; const __half* Bul = Bl;
    const float* bu = bias; float* Cu = C;
    __half* Chu = Ch; __half* Clu = Cl;
    if (DUAL) {
        int half_ = gridDim.y >> 1;
        if (by >= half_) {
            Au = A2h; Aul = A2l; Bu = B2h; Bul = B2l;
            bu = bias2; Cu = C2; Chu = Ch2; Clu = Cl2;
            by -= half_;
        }
    }

    const __half* Agh = Au  + (size_t)by * 128 * K;
    const __half* Agl = Aul + (size_t)by * 128 * K;
    const __half* Bgh = Bu  + (size_t)bx * 128 * K;
    const __half* Bgl = Bul + (size_t)bx * 128 * K;

    float acc[4][4][4];
    uint32_t acc16[4][4][2];
#pragma unroll
    for (int i = 0; i < 4; i++)
#pragma unroll
        for (int j = 0; j < 4; j++) {
#pragma unroll
            for (int r = 0; r < 4; r++) acc[i][j][r] = 0.f;
            acc16[i][j][0] = 0u; acc16[i][j][1] = 0u;
        }

    int NC = K / KCH;

    auto load_stage = [&](int c, int s) {
        int k0 = c * KCH;
        uint32_t sbase = sb + s * STAGEE * 2;
#pragma unroll
        for (int i = 0; i < 4; i++) {
            int idx = tid + i * 256;
            int row = idx >> 3, kc = (idx & 7) * 8;
            uint32_t so = sbase + (uint32_t)(row * ASTR + kc) * 2;
            size_t go = (size_t)row * K + k0 + kc;
            cp16(so,                 Agh + go);
            cp16(so + TELEM * 2,     Agl + go);
            cp16(so + 2 * TELEM * 2, Bgh + go);
            cp16(so + 3 * TELEM * 2, Bgl + go);
        }
    };

    load_stage(0, 0);
    asm volatile("cp.async.commit_group;");

    int a_r  = lane & 15;
    int a_k8 = (lane >> 4) * 8;
    int b_l  = lane & 7;
    int b_seg = lane >> 3;
    int b_r  = (b_seg >= 2) ? b_l + 8 : b_l;
    int b_k8 = (b_seg & 1) * 8;

    for (int c = 0; c < NC; c++) {
        if (c + 1 < NC) {
            load_stage(c + 1, (c + 1) & 1);
            asm volatile("cp.async.commit_group;");
            asm volatile("cp.async.wait_group 1;");
        } else {
            asm volatile("cp.async.wait_group 0;");
        }
        __syncthreads();

        uint32_t sA  = sb + (c & 1) * STAGEE * 2;
        uint32_t sAl = sA + TELEM * 2;
        uint32_t sBh = sA + 2 * TELEM * 2;
        uint32_t sBl = sA + 3 * TELEM * 2;

#pragma unroll
        for (int ks = 0; ks < KCH / 16; ks++) {
            int kbase = ks * 16;
            uint32_t ah[4][4], al[4][4], bh[2][4], bl[2][4];
#pragma unroll
            for (int mt = 0; mt < 4; mt++) {
                uint32_t off = (uint32_t)((wm * 64 + mt * 16 + a_r) * ASTR + kbase + a_k8) * 2;
                ldsm4(ah[mt], sA  + off);
                ldsm4(al[mt], sAl + off);
            }
#pragma unroll
            for (int np = 0; np < 2; np++) {
                uint32_t off = (uint32_t)((wn * 32 + np * 16 + b_r) * ASTR + kbase + b_k8) * 2;
                ldsm4(bh[np], sBh + off);
                ldsm4(bl[np], sBl + off);
            }
#pragma unroll
            for (int mt = 0; mt < 4; mt++)
#pragma unroll
                for (int nt = 0; nt < 4; nt++) {
                    const uint32_t* bhp = &bh[nt >> 1][(nt & 1) * 2];
                    const uint32_t* blp = &bl[nt >> 1][(nt & 1) * 2];
                    mma_f32(acc[mt][nt], ah[mt], bhp);
                    mma_f16(acc16[mt][nt], ah[mt], blp);
                    mma_f16(acc16[mt][nt], al[mt], bhp);
                }
        }
        __syncthreads();
    }

    // epilogue (merge f16 correction accumulators)
#pragma unroll
    for (int mt = 0; mt < 4; mt++)
#pragma unroll
        for (int h8 = 0; h8 < 2; h8++) {
            int rowg = by * 128 + wm * 64 + mt * 16 + grp + h8 * 8;
#pragma unroll
            for (int nt = 0; nt < 4; nt++) {
                int colg = bx * 128 + wn * 32 + nt * 8 + tig * 2;
                __half2 hc = *(__half2*)&acc16[mt][nt][h8];
                float v0 = acc[mt][nt][h8 * 2 + 0] + __low2float(hc);
                float v1 = acc[mt][nt][h8 * 2 + 1] + __high2float(hc);
                if (EPI >= 1) { v0 += bu[colg]; v1 += bu[colg + 1]; }
                if (EPI == 2) { v0 = fmaxf(v0, 0.f); v1 = fmaxf(v1, 0.f); }
                if (PERM == 0) {
                    size_t rb = (size_t)rowg * Nn + colg;
                    if (OUTB) {
                        __half2 H, L;
                        hsplit(v0, H.x, L.x); hsplit(v1, H.y, L.y);
                        *(__half2*)(Chu + rb) = H;
                        *(__half2*)(Clu + rb) = L;
                    } else {
                        float2 p; p.x = v0; p.y = v1;
                        *(float2*)(Cu + rb) = p;
                    }
                } else if (PERM == 2) {
                    size_t rb = (size_t)(rowg + (rowg >> 7) + 1) * Nn + colg;
                    float2 p; p.x = v0; p.y = v1;
                    *(float2*)(Cu + rb) = p;
                } else {
                    int b = rowg >> 12, n = rowg & 4095;
                    int h = colg >> 7, d = colg & 127;
                    size_t dst = (((size_t)((b * HEADS + h) * SEQ + n)) << 7) + d;
                    if (PERM == 1 || PERM == 3) {
                        float inv = (float)exp(-(double)d * (9.210340371976184 / 128.0));
                        float t = (float)n * inv;
                        float s, cc; sincosf(t, &s, &cc);
                        float r0 = v0 * cc - v1 * s;
                        float r1 = v0 * s + v1 * cc;
                        float2 rp; rp.x = r0; rp.y = r1;
                        *(float2*)(X1 + dst) = rp;
                    }
                    if (PERM == 1 || PERM == 4) {
                        float2 p; p.x = v0; p.y = v1;
                        *(float2*)(Cu + dst) = p;
                    }
                    if (PERM == 3 || PERM == 4) {
                        const float* pp = pos + h * 4096 + (n & 31) * 128 + d;
                        __half2 H, L;
                        hsplit(v0 + pp[0], H.x, L.x);
                        hsplit(v1 + pp[1], H.y, L.y);
                        *(__half2*)(Chu + dst) = H;
                        *(__half2*)(Clu + dst) = L;
                    }
                }
            }
        }
}

// ------------------------- fp32 -> hi/lo fp16 convert ------------------------
__global__ void cvt_k(const float4* __restrict__ x, __half2* __restrict__ hi,
                      __half2* __restrict__ lo, int n4)
{
    int i = blockIdx.x * 256 + threadIdx.x;
    if (i >= n4) return;
    float4 v = x[i];
    __half2 H0, H1, L0, L1;
    hsplit(v.x, H0.x, L0.x); hsplit(v.y, H0.y, L0.y);
    hsplit(v.z, H1.x, L1.x); hsplit(v.w, H1.y, L1.y);
    hi[i * 2] = H0; hi[i * 2 + 1] = H1;
    lo[i * 2] = L0; lo[i * 2 + 1] = L1;
}

// transpose-convert: W[K,N] fp32 -> Wt hi/lo [N,K] fp16
__global__ void cvtT_k(const float* __restrict__ x, __half* __restrict__ hi,
                       __half* __restrict__ lo, int K, int N)
{
    __shared__ float t[32][33];
    int bx = blockIdx.x, by = blockIdx.y;
    int tx = threadIdx.x & 31, ty = threadIdx.x >> 5;
#pragma unroll
    for (int i = 0; i < 32; i += 8) {
        int kk = by * 32 + ty + i;
        t[ty + i][tx] = x[(size_t)kk * N + bx * 32 + tx];
    }
    __syncthreads();
#pragma unroll
    for (int i = 0; i < 32; i += 8) {
        int n = bx * 32 + ty + i;
        int kk = by * 32 + tx;
        float v = t[tx][ty + i];
        __half h, l; hsplit(v, h, l);
        hi[(size_t)n * K + kk] = h;
        lo[(size_t)n * K + kk] = l;
    }
}

// ------------------------- fused rmsnorm + gates ----------------------------
__global__ void gates_k(const float* __restrict__ inp, const float* __restrict__ g,
                        const float* __restrict__ Wg, const float* __restrict__ bg,
                        float* __restrict__ gates)
{
    __shared__ float xs[DIM];
    __shared__ float red[8];
    int row = blockIdx.x;
    int tid = threadIdx.x;
    const float* ip = inp + (size_t)row * DIM;
    float ss = 0.f;
    for (int k = tid; k < DIM; k += 256) { float v = ip[k]; xs[k] = v; ss += v * v; }
#pragma unroll
    for (int o = 16; o > 0; o >>= 1) ss += __shfl_xor_sync(~0u, ss, o);
    if ((tid & 31) == 0) red[tid >> 5] = ss;
    __syncthreads();
    float tot = red[0] + red[1] + red[2] + red[3] + red[4] + red[5] + red[6] + red[7];
    float rn = 1.0f / sqrtf(tot * (1.0f / DIM) + EPSV);
    int lane = tid & 31, warp = tid >> 5;
    for (int c = warp; c < 2 * HEADS; c += 8) {
        float acc = 0.f;
        for (int k = lane; k < DIM; k += 32) acc += xs[k] * g[k] * Wg[(size_t)k * (2 * HEADS) + c];
#pragma unroll
        for (int o = 16; o > 0; o >>= 1) acc += __shfl_xor_sync(~0u, acc, o);
        if (lane == 0) gates[(size_t)row * (2 * HEADS) + c] = 1.f / (1.f + expf(-(acc * rn + bg[c])));
    }
}

// ------------------------- mem slots into ckf/cvf ---------------------------
__global__ void fillmem_k(const float* __restrict__ memkv,
                          float* __restrict__ ckf, float* __restrict__ cvf)
{
    int idx = blockIdx.x * 256 + threadIdx.x;
    if (idx >= BATCH * HEADS * DHEAD) return;
    int d = idx & 127; int h = (idx >> 7) & 15; int b = idx >> 11;
    size_t dst = (((size_t)((b * HEADS + h) * CM)) << 7) + d;
    ckf[dst] = memkv[h * 128 + d];
    cvf[dst] = memkv[HEADS * 128 + h * 128 + d];
}

// ------------------------- compressed attention -----------------------------
__global__ void __launch_bounds__(256) attn_c_k(
    const float* __restrict__ q, const float* __restrict__ ckf,
    const float* __restrict__ cvf, float* __restrict__ cout,
    float* __restrict__ imp_part)
{
    extern __shared__ float smf[];
    float* qs   = smf;
    float* sims = smf + 64 * 128;
    float* cs   = sims + 64 * 132;
    int tid = threadIdx.x;
    int bh = blockIdx.y, n0 = blockIdx.x * 64;
    const float* qb = q + (((size_t)bh * SEQ + n0) << 7);
#pragma unroll
    for (int i = 0; i < 8; i++) {
        int vdx = tid + i * 256;
        int row = vdx >> 5, c4 = (vdx & 31) * 4;
        *(float4*)&qs[row * 128 + c4] = *(const float4*)(qb + row * 128 + c4);
    }
    int tx = tid & 15, ty = tid >> 4;

    for (int m0 = 0; m0 < CM; m0 += 32) {
        int mc = (CM - m0 < 32) ? (CM - m0) : 32;
        for (int vdx = tid; vdx < mc * 32; vdx += 256) {
            int rr = vdx >> 5, c4 = (vdx & 31) * 4;
            float4 t = *(const float4*)(ckf + (((size_t)bh * CM + m0 + rr) << 7) + c4);
            cs[rr * 132 + c4 + 0] = t.x; cs[rr * 132 + c4 + 1] = t.y;
            cs[rr * 132 + c4 + 2] = t.z; cs[rr * 132 + c4 + 3] = t.w;
        }
        __syncthreads();
        float a0[2] = {0, 0}, a1[2] = {0, 0}, a2[2] = {0, 0}, a3[2] = {0, 0};
#pragma unroll 4
        for (int k = 0; k < 128; k++) {
            float q0 = qs[(ty * 4 + 0) * 128 + k];
            float q1 = qs[(ty * 4 + 1) * 128 + k];
            float q2 = qs[(ty * 4 + 2) * 128 + k];
            float q3 = qs[(ty * 4 + 3) * 128 + k];
            float c0 = cs[(tx * 2 + 0) * 132 + k];
            float c1 = cs[(tx * 2 + 1) * 132 + k];
            a0[0] += q0 * c0; a0[1] += q0 * c1;
            a1[0] += q1 * c0; a1[1] += q1 * c1;
            a2[0] += q2 * c0; a2[1] += q2 * c1;
            a3[0] += q3 * c0; a3[1] += q3 * c1;
        }
#pragma unroll
        for (int mm = 0; mm < 2; mm++) {
            int m = tx * 2 + mm;
            if (m < mc) {
                sims[(ty * 4 + 0) * 132 + m0 + m] = a0[mm] * SCALEV;
                sims[(ty * 4 + 1) * 132 + m0 + m] = a1[mm] * SCALEV;
                sims[(ty * 4 + 2) * 132 + m0 + m] = a2[mm] * SCALEV;
                sims[(ty * 4 + 3) * 132 + m0 + m] = a3[mm] * SCALEV;
            }
        }
        __syncthreads();
    }

    {
        int lane = tid & 31, wrp = tid >> 5;
        for (int r = wrp; r < 64; r += 8) {
            float* srow = sims + r * 132;
            float mx = -1e38f;
            for (int m = lane; m < CM; m += 32) mx = fmaxf(mx, srow[m]);
#pragma unroll
            for (int o = 16; o > 0; o >>= 1) mx = fmaxf(mx, __shfl_xor_sync(~0u, mx, o));
            float sum = 0.f;
            for (int m = lane; m < CM; m += 32) { float e = expf(srow[m] - mx); srow[m] = e; sum += e; }
#pragma unroll
            for (int o = 16; o > 0; o >>= 1) sum += __shfl_xor_sync(~0u, sum, o);
            float inv = 1.f / sum;
            for (int m = lane; m < CM; m += 32) srow[m] *= inv;
        }
    }
    __syncthreads();
    if (tid < 128) {
        float s = 0.f;
        for (int r = 0; r < 64; r++) s += sims[r * 132 + 1 + tid];
        imp_part[(((size_t)bh * 64) + blockIdx.x) * 128 + tid] = s;
    }
    __syncthreads();

    float oacc[4][8];
#pragma unroll
    for (int i = 0; i < 4; i++)
#pragma unroll
        for (int j = 0; j < 8; j++) oacc[i][j] = 0.f;

    for (int m0 = 0; m0 < CM; m0 += 32) {
        int mc = (CM - m0 < 32) ? (CM - m0) : 32;
        for (int vdx = tid; vdx < mc * 32; vdx += 256) {
            int rr = vdx >> 5, c4 = (vdx & 31) * 4;
            float4 t = *(const float4*)(cvf + (((size_t)bh * CM + m0 + rr) << 7) + c4);
            cs[rr * 132 + c4 + 0] = t.x; cs[rr * 132 + c4 + 1] = t.y;
            cs[rr * 132 + c4 + 2] = t.z; cs[rr * 132 + c4 + 3] = t.w;
        }
        __syncthreads();
        for (int mm = 0; mm < mc; mm++) {
            float p0 = sims[(ty * 4 + 0) * 132 + m0 + mm];
            float p1 = sims[(ty * 4 + 1) * 132 + m0 + mm];
            float p2 = sims[(ty * 4 + 2) * 132 + m0 + mm];
            float p3 = sims[(ty * 4 + 3) * 132 + m0 + mm];
            float bv[8];
            *(float4*)&bv[0] = *(float4*)&cs[mm * 132 + tx * 8];
            *(float4*)&bv[4] = *(float4*)&cs[mm * 132 + tx * 8 + 4];
#pragma unroll
            for (int j = 0; j < 8; j++) {
                oacc[0][j] += p0 * bv[j];
                oacc[1][j] += p1 * bv[j];
                oacc[2][j] += p2 * bv[j];
                oacc[3][j] += p3 * bv[j];
            }
        }
        __syncthreads();
    }
#pragma unroll
    for (int rr = 0; rr < 4; rr++) {
        size_t dst = (((size_t)bh * SEQ) + n0 + ty * 4 + rr) * 128 + tx * 8;
        *(float4*)&cout[dst]     = *(float4*)&oacc[rr][0];
        *(float4*)&cout[dst + 4] = *(float4*)&oacc[rr][4];
    }
}

// ------------------------- importance reduce + top-k ------------------------
__global__ void topk_k(const float* __restrict__ imp_part,
                       int* __restrict__ idxout, int* __restrict__ maskout)
{
    __shared__ float vals[WBLK];
    int bh = blockIdx.x, tid = threadIdx.x;
    float s = 0.f;
    for (int t = 0; t < 64; t++) s += imp_part[(((size_t)bh * 64) + t) * 128 + tid];
    vals[tid] = s * (1.0f / SEQ);
    __syncthreads();
    if (tid == 0) {
        for (int sel = 0; sel < SELK; sel++) {
            float best = -1e38f; int bi = 0;
            for (int m = 0; m < WBLK; m++)
                if (vals[m] > best) { best = vals[m]; bi = m; }
            idxout[bh * SELK + sel] = bi;
            maskout[bh * SELK + sel] = (best > 1e-10f) ? 1 : 0;
            vals[bi] = -1e38f;
        }
    }
}

// ------------------------- selected (fine) attention, fused gather ----------
__global__ void __launch_bounds__(256) attn_f_k(
    const float* __restrict__ qr, const float* __restrict__ kr,
    const float* __restrict__ v, const int* __restrict__ idxs,
    const int* __restrict__ fmask, float* __restrict__ fout)
{
    extern __shared__ float smf[];
    float* qs   = smf;
    float* sims = smf + 4096;
    float* cs   = sims + 16512;
    __shared__ int maskS[SELK];
    __shared__ int blkS[SELK];
    int tid = threadIdx.x;
    int bh = blockIdx.y, n0 = blockIdx.x * 32;
    if (tid < SELK) {
        maskS[tid] = fmask[bh * SELK + tid];
        blkS[tid]  = idxs[bh * SELK + tid];
    }
    const float* qb = qr + (((size_t)bh * SEQ + n0) << 7);
#pragma unroll
    for (int i = 0; i < 4; i++) {
        int vdx = tid + i * 256;
        int row = vdx >> 5, c4 = (vdx & 31) * 4;
        *(float4*)&qs[row * 128 + c4] = *(const float4*)(qb + row * 128 + c4);
    }
    __syncthreads();
    int tx = tid & 15, ty = tid >> 4;

    for (int m0 = 0; m0 < 512; m0 += 32) {
        int blk = blkS[m0 >> 5];
        const float* kb = kr + (((size_t)bh * SEQ + blk * BLKSZ) << 7);
        for (int vdx = tid; vdx < 32 * 32; vdx += 256) {
            int rr = vdx >> 5, c4 = (vdx & 31) * 4;
            float4 t = *(const float4*)(kb + ((size_t)rr << 7) + c4);
            cs[rr * 132 + c4 + 0] = t.x; cs[rr * 132 + c4 + 1] = t.y;
            cs[rr * 132 + c4 + 2] = t.z; cs[rr * 132 + c4 + 3] = t.w;
        }
        __syncthreads();
        float a00 = 0, a01 = 0, a10 = 0, a11 = 0;
#pragma unroll 4
        for (int k = 0; k < 128; k++) {
            float q0 = qs[(ty * 2 + 0) * 128 + k], q1 = qs[(ty * 2 + 1) * 128 + k];
            float c0 = cs[(tx * 2 + 0) * 132 + k], c1 = cs[(tx * 2 + 1) * 132 + k];
            a00 += q0 * c0; a01 += q0 * c1; a10 += q1 * c0; a11 += q1 * c1;
        }
        sims[(ty * 2 + 0) * 516 + m0 + tx * 2 + 0] = a00 * SCALEV;
        sims[(ty * 2 + 0) * 516 + m0 + tx * 2 + 1] = a01 * SCALEV;
        sims[(ty * 2 + 1) * 516 + m0 + tx * 2 + 0] = a10 * SCALEV;
        sims[(ty * 2 + 1) * 516 + m0 + tx * 2 + 1] = a11 * SCALEV;
        __syncthreads();
    }

    {
        int lane = tid & 31, wrp = tid >> 5;
        for (int r = wrp; r < 32; r += 8) {
            float* srow = sims + r * 516;
            float mx = -1e38f;
            for (int m = lane; m < 512; m += 32) {
                float vv = srow[m];
                if (!maskS[m >> 5]) vv = NEGV;
                srow[m] = vv;
                mx = fmaxf(mx, vv);
            }
#pragma unroll
            for (int o = 16; o > 0; o >>= 1) mx = fmaxf(mx, __shfl_xor_sync(~0u, mx, o));
            float sum = 0.f;
            for (int m = lane; m < 512; m += 32) { float e = expf(srow[m] - mx); srow[m] = e; sum += e; }
#pragma unroll
            for (int o = 16; o > 0; o >>= 1) sum += __shfl_xor_sync(~0u, sum, o);
            float inv = 1.f / sum;
            for (int m = lane; m < 512; m += 32) srow[m] *= inv;
        }
    }
    __syncthreads();

    float o0[8], o1[8];
#pragma unroll
    for (int j = 0; j < 8; j++) { o0[j] = 0.f; o1[j] = 0.f; }
    for (int m0 = 0; m0 < 512; m0 += 32) {
        int blk = blkS[m0 >> 5];
        const float* vb = v + (((size_t)bh * SEQ + blk * BLKSZ) << 7);
        for (int vdx = tid; vdx < 32 * 32; vdx += 256) {
            int rr = vdx >> 5, c4 = (vdx & 31) * 4;
            float4 t = *(const float4*)(vb + ((size_t)rr << 7) + c4);
            cs[rr * 132 + c4 + 0] = t.x; cs[rr * 132 + c4 + 1] = t.y;
            cs[rr * 132 + c4 + 2] = t.z; cs[rr * 132 + c4 + 3] = t.w;
        }
        __syncthreads();
        for (int mm = 0; mm < 32; mm++) {
            float p0 = sims[(ty * 2 + 0) * 516 + m0 + mm];
            float p1 = sims[(ty * 2 + 1) * 516 + m0 + mm];
            float bv[8];
            *(float4*)&bv[0] = *(float4*)&cs[mm * 132 + tx * 8];
            *(float4*)&bv[4] = *(float4*)&cs[mm * 132 + tx * 8 + 4];
#pragma unroll
            for (int j = 0; j < 8; j++) { o0[j] += p0 * bv[j]; o1[j] += p1 * bv[j]; }
        }
        __syncthreads();
    }
    size_t dst0 = (((size_t)bh * SEQ) + n0 + ty * 2 + 0) * 128 + tx * 8;
    size_t dst1 = (((size_t)bh * SEQ) + n0 + ty * 2 + 1) * 128 + tx * 8;
    *(float4*)&fout[dst0] = *(float4*)&o0[0]; *(float4*)&fout[dst0 + 4] = *(float4*)&o0[4];
    *(float4*)&fout[dst1] = *(float4*)&o1[0]; *(float4*)&fout[dst1 + 4] = *(float4*)&o1[4];
}

// ------------------------- combine gates -> fp16 hi/lo ----------------------
__global__ void combine2_k(const float* __restrict__ cout, const float* __restrict__ fout,
                           const float* __restrict__ gates,
                           __half* __restrict__ oh, __half* __restrict__ ol)
{
    int idx = blockIdx.x * 256 + threadIdx.x;
    int d = idx & 127; int h = (idx >> 7) & 15; int nrow = idx >> 11;
    int b = nrow >> 12; int n = nrow & 4095;
    size_t src = (((size_t)(b * HEADS + h) * SEQ) + n) * 128 + d;
    float g0 = gates[(size_t)nrow * (2 * HEADS) + 2 * h];
    float g1 = gates[(size_t)nrow * (2 * HEADS) + 2 * h + 1];
    float v = g0 * cout[src] + g1 * fout[src];
    __half hh, ll; hsplit(v, hh, ll);
    oh[idx] = hh; ol[idx] = ll;
}

// ------------------------- launch ------------------------------------------
extern "C" void kernel_launch(void* const* d_in, const int* in_sizes, int n_in,
                              void* d_out, int out_size)
{
    const float* inp  = (const float*)d_in[0];
    const float* g    = (const float*)d_in[1];
    const float* Wq   = (const float*)d_in[2];
    const float* Wk   = (const float*)d_in[3];
    const float* Wv   = (const float*)d_in[4];
    const float* kpos = (const float*)d_in[5];
    const float* vpos = (const float*)d_in[6];
    const float* memkv= (const float*)d_in[7];
    const float* kW1  = (const float*)d_in[8];
    const float* kb1  = (const float*)d_in[9];
    const float* kW2  = (const float*)d_in[10];
    const float* kb2  = (const float*)d_in[11];
    const float* vW1  = (const float*)d_in[12];
    const float* vb1  = (const float*)d_in[13];
    const float* vW2  = (const float*)d_in[14];
    const float* vb2  = (const float*)d_in[15];
    const float* Wg   = (const float*)d_in[16];
    const float* bg   = (const float*)d_in[17];
    const float* Wo   = (const float*)d_in[18];
    float* out = (float*)d_out;

    float *q, *qr, *kr, *v, *ckf, *cvf, *cout, *fout, *gates, *imp;
    int *idxs, *msk;
    cudaGetSymbolAddress((void**)&q,    g_q);
    cudaGetSymbolAddress((void**)&qr,   g_qr);
    cudaGetSymbolAddress((void**)&kr,   g_kr);
    cudaGetSymbolAddress((void**)&v,    g_v);
    cudaGetSymbolAddress((void**)&ckf,  g_ckf);
    cudaGetSymbolAddress((void**)&cvf,  g_cvf);
    cudaGetSymbolAddress((void**)&cout, g_cout);
    cudaGetSymbolAddress((void**)&fout, g_fout);
    cudaGetSymbolAddress((void**)&gates,g_gates);
    cudaGetSymbolAddress((void**)&imp,  g_imp_part);
    cudaGetSymbolAddress((void**)&idxs, g_idx);
    cudaGetSymbolAddress((void**)&msk,  g_msk);

    __half *inph,*inpl,*wqh,*wql,*wkh,*wkl,*wvh,*wvl,*kw1h,*kw1l,*vw1h,*vw1l;
    __half *kw2h,*kw2l,*vw2h,*vw2l,*woh,*wol,*kch,*kcl,*vch,*vcl;
    __half *h1kh,*h1kl,*h1vh,*h1vl,*oph,*opl;
    cudaGetSymbolAddress((void**)&inph, b_inp_h); cudaGetSymbolAddress((void**)&inpl, b_inp_l);
    cudaGetSymbolAddress((void**)&wqh,  b_wq_h);  cudaGetSymbolAddress((void**)&wql,  b_wq_l);
    cudaGetSymbolAddress((void**)&wkh,  b_wk_h);  cudaGetSymbolAddress((void**)&wkl,  b_wk_l);
    cudaGetSymbolAddress((void**)&wvh,  b_wv_h);  cudaGetSymbolAddress((void**)&wvl,  b_wv_l);
    cudaGetSymbolAddress((void**)&kw1h, b_kw1_h); cudaGetSymbolAddress((void**)&kw1l, b_kw1_l);
    cudaGetSymbolAddress((void**)&vw1h, b_vw1_h); cudaGetSymbolAddress((void**)&vw1l, b_vw1_l);
    cudaGetSymbolAddress((void**)&kw2h, b_kw2_h); cudaGetSymbolAddress((void**)&kw2l, b_kw2_l);
    cudaGetSymbolAddress((void**)&vw2h, b_vw2_h); cudaGetSymbolAddress((void**)&vw2l, b_vw2_l);
    cudaGetSymbolAddress((void**)&woh,  b_wo_h);  cudaGetSymbolAddress((void**)&wol,  b_wo_l);
    cudaGetSymbolAddress((void**)&kch,  b_kc_h);  cudaGetSymbolAddress((void**)&kcl,  b_kc_l);
    cudaGetSymbolAddress((void**)&vch,  b_vc_h);  cudaGetSymbolAddress((void**)&vcl,  b_vc_l);
    cudaGetSymbolAddress((void**)&h1kh, b_h1k_h); cudaGetSymbolAddress((void**)&h1kl, b_h1k_l);
    cudaGetSymbolAddress((void**)&h1vh, b_h1v_h); cudaGetSymbolAddress((void**)&h1vl, b_h1v_l);
    cudaGetSymbolAddress((void**)&oph,  b_op_h);  cudaGetSymbolAddress((void**)&opl,  b_op_l);

    const int SMEM_C = (64 * 128 + 64 * 132 + 32 * 132) * 4;
    const int SMEM_F = (32 * 128 + 32 * 516 + 32 * 132) * 4;
    cudaFuncSetAttribute(attn_c_k, cudaFuncAttributeMaxDynamicSharedMemorySize, SMEM_C);
    cudaFuncSetAttribute(attn_f_k, cudaFuncAttributeMaxDynamicSharedMemorySize, SMEM_F);
    cudaFuncSetAttribute(tgemm_k<0,1,0,0>, cudaFuncAttributeMaxDynamicSharedMemorySize, GSMEM);
    cudaFuncSetAttribute(tgemm_k<0,3,0,0>, cudaFuncAttributeMaxDynamicSharedMemorySize, GSMEM);
    cudaFuncSetAttribute(tgemm_k<0,4,0,0>, cudaFuncAttributeMaxDynamicSharedMemorySize, GSMEM);
    cudaFuncSetAttribute(tgemm_k<2,0,1,1>, cudaFuncAttributeMaxDynamicSharedMemorySize, GSMEM);
    cudaFuncSetAttribute(tgemm_k<1,2,0,1>, cudaFuncAttributeMaxDynamicSharedMemorySize, GSMEM);
    cudaFuncSetAttribute(tgemm_k<0,0,0,0>, cudaFuncAttributeMaxDynamicSharedMemorySize, GSMEM);

    // 0) converts
    cvt_k<<<(ROWS*DIM/4 + 255)/256, 256>>>((const float4*)inp, (__half2*)inph, (__half2*)inpl, ROWS*DIM/4);
    cvtT_k<<<dim3(DIM/32, DIM/32), 256>>>(Wq, wqh, wql, DIM, DIM);
    cvtT_k<<<dim3(DIM/32, DIM/32), 256>>>(Wk, wkh, wkl, DIM, DIM);
    cvtT_k<<<dim3(DIM/32, DIM/32), 256>>>(Wv, wvh, wvl, DIM, DIM);
    cvtT_k<<<dim3(HIDC/32, HIDC/32), 256>>>(kW1, kw1h, kw1l, HIDC, HIDC);

    // 1) QKV projections with fused RoPE / pos-pack epilogues
    dim3 gq(DIM/128, ROWS/128);
    tgemm_k<0,1,0,0><<<gq, 256, GSMEM>>>(inph, inpl, wqh, wql, nullptr, q, nullptr, nullptr,
        qr, nullptr, nullptr, nullptr, nullptr, nullptr, nullptr, nullptr, nullptr, nullptr,
        ROWS, DIM, DIM);
    tgemm_k<0,3,0,0><<<gq, 256, GSMEM>>>(inph, inpl, wkh, wkl, nullptr, nullptr, kch, kcl,
        kr, kpos, nullptr, nullptr, nullptr, nullptr, nullptr, nullptr, nullptr, nullptr,
        ROWS, DIM, DIM);
    tgemm_k<0,4,0,0><<<gq, 256, GSMEM>>>(inph, inpl, wvh, wvl, nullptr, v, vch, vcl,
        nullptr, vpos, nullptr, nullptr, nullptr, nullptr, nullptr, nullptr, nullptr, nullptr,
        ROWS, DIM, DIM);

    // remaining converts + gates (overlap with GEMM tails)
    cvtT_k<<<dim3(HIDC/32, HIDC/32), 256>>>(vW1, vw1h, vw1l, HIDC, HIDC);
    cvtT_k<<<dim3(DHEAD/32, HIDC/32), 256>>>(kW2, kw2h, kw2l, HIDC, DHEAD);
    cvtT_k<<<dim3(DHEAD/32, HIDC/32), 256>>>(vW2, vw2h, vw2l, HIDC, DHEAD);
    cvtT_k<<<dim3(DIM/32, DIM/32), 256>>>(Wo, woh, wol, DIM, DIM);
    gates_k<<<ROWS, 256>>>(inp, g, Wg, bg, gates);

    // 3) compress MLP layer 1 — k and v merged into one dual launch
    tgemm_k<2,0,1,1><<<dim3(HIDC/128, 2*(HIDC/128)), 256, GSMEM>>>(
        kch, kcl, kw1h, kw1l, kb1, nullptr, h1kh, h1kl, nullptr, nullptr,
        vch, vcl, vw1h, vw1l, vb1, nullptr, h1vh, h1vl,
        BATCH*HEADS*WBLK, HIDC, HIDC);

    // 4) compress MLP layer 2 — k and v merged into one dual launch
    tgemm_k<1,2,0,1><<<dim3(1, 64), 256, GSMEM>>>(
        h1kh, h1kl, kw2h, kw2l, kb2, ckf, nullptr, nullptr, nullptr, nullptr,
        h1vh, h1vl, vw2h, vw2l, vb2, cvf, nullptr, nullptr,
        BATCH*HEADS*WBLK, DHEAD, HIDC);
    fillmem_k<<<16, 256>>>(memkv, ckf, cvf);

    // 5) compressed attention + importance partials
    attn_c_k<<<dim3(SEQ/64, BATCH*HEADS), 256, SMEM_C>>>(q, ckf, cvf, cout, imp);

    // 6) top-k
    topk_k<<<BATCH*HEADS, 128>>>(imp, idxs, msk);

    // 7) fine attention (gather fused via block indices)
    attn_f_k<<<dim3(SEQ/32, BATCH*HEADS), 256, SMEM_F>>>(qr, kr, v, idxs, msk, fout);

    // 8) gate-combine -> split fp16
    combine2_k<<<QKVN/256, 256>>>(cout, fout, gates, oph, opl);

    // 9) output projection (fp32 out)
    tgemm_k<0,0,0,0><<<dim3(DIM/128, ROWS/128), 256, GSMEM>>>(
        oph, opl, woh, wol, nullptr, out, nullptr, nullptr, nullptr, nullptr,
        nullptr, nullptr, nullptr, nullptr, nullptr, nullptr, nullptr, nullptr,
        ROWS, DIM, DIM);
}

// round 13
// speedup vs baseline: 1.0428x; 1.0356x over previous
#include <cuda_runtime.h>
#include <cuda_fp16.h>
#include <math.h>
#include <stdint.h>

// Problem constants
#define BATCH 2
#define SEQ   4096
#define DIM   2048
#define HEADS 16
#define DHEAD 128
#define BLKSZ 32
#define SELK  16
#define HIDC  4096
#define WBLK  128
#define CM    129
#define ROWS  (BATCH*SEQ)
#define QKVN  (BATCH*HEADS*SEQ*DHEAD)
#define NEGV  (-1e30f)
#define EPSV  1.1920929e-7f
#define SCALEV 0.08838834764831845f

// ------------------------- scratch (device globals) -------------------------
__device__ __align__(256) float g_q [QKVN];
__device__ __align__(256) float g_qr[QKVN];
__device__ __align__(256) float g_kr[QKVN];
__device__ __align__(256) float g_v [QKVN];
__device__ __align__(256) float g_ckf[BATCH*HEADS*CM*DHEAD];
__device__ __align__(256) float g_cvf[BATCH*HEADS*CM*DHEAD];
__device__ __align__(256) float g_cout[QKVN];
__device__ __align__(256) float g_fout[QKVN];
__device__ __align__(256) float g_gates[ROWS*2*HEADS];
__device__ __align__(256) float g_imp_part[BATCH*HEADS*64*WBLK];
__device__ int g_idx[BATCH*HEADS*SELK];
__device__ int g_msk[BATCH*HEADS*SELK];

// fp16 hi/lo split operands
__device__ __align__(256) __half b_inp_h[ROWS*DIM],  b_inp_l[ROWS*DIM];
__device__ __align__(256) __half b_wq_h[DIM*DIM],    b_wq_l[DIM*DIM];
__device__ __align__(256) __half b_wk_h[DIM*DIM],    b_wk_l[DIM*DIM];
__device__ __align__(256) __half b_wv_h[DIM*DIM],    b_wv_l[DIM*DIM];
__device__ __align__(256) __half b_kw1_h[HIDC*HIDC], b_kw1_l[HIDC*HIDC];
__device__ __align__(256) __half b_vw1_h[HIDC*HIDC], b_vw1_l[HIDC*HIDC];
__device__ __align__(256) __half b_kw2_h[DHEAD*HIDC],b_kw2_l[DHEAD*HIDC];
__device__ __align__(256) __half b_vw2_h[DHEAD*HIDC],b_vw2_l[DHEAD*HIDC];
__device__ __align__(256) __half b_wo_h[DIM*DIM],    b_wo_l[DIM*DIM];
__device__ __align__(256) __half b_kc_h[QKVN],       b_kc_l[QKVN];
__device__ __align__(256) __half b_vc_h[QKVN],       b_vc_l[QKVN];
__device__ __align__(256) __half b_h1k_h[HIDC*HIDC], b_h1k_l[HIDC*HIDC];
__device__ __align__(256) __half b_h1v_h[HIDC*HIDC], b_h1v_l[HIDC*HIDC];
__device__ __align__(256) __half b_op_h[ROWS*DIM],   b_op_l[ROWS*DIM];

// ------------------------- helpers ------------------------------------------
__device__ __forceinline__ uint32_t smem_u32(const void* p){
    uint32_t a;
    asm("{ .reg .u64 t; cvta.to.shared.u64 t, %1; cvt.u32.u64 %0, t; }" : "=r"(a) : "l"(p));
    return a;
}
__device__ __forceinline__ void cp16(uint32_t saddr, const void* gaddr){
    asm volatile("cp.async.cg.shared.global [%0], [%1], 16;" :: "r"(saddr), "l"(gaddr));
}
__device__ __forceinline__ void mma_f32(float* c, const uint32_t* a, const uint32_t* b){
    asm volatile("mma.sync.aligned.m16n8k16.row.col.f32.f16.f16.f32 "
        "{%0,%1,%2,%3}, {%4,%5,%6,%7}, {%8,%9}, {%0,%1,%2,%3};"
        : "+f"(c[0]), "+f"(c[1]), "+f"(c[2]), "+f"(c[3])
        : "r"(a[0]), "r"(a[1]), "r"(a[2]), "r"(a[3]), "r"(b[0]), "r"(b[1]));
}
__device__ __forceinline__ void mma_f16(uint32_t* c, const uint32_t* a, const uint32_t* b){
    asm volatile("mma.sync.aligned.m16n8k16.row.col.f16.f16.f16.f16 "
        "{%0,%1}, {%2,%3,%4,%5}, {%6,%7}, {%0,%1};"
        : "+r"(c[0]), "+r"(c[1])
        : "r"(a[0]), "r"(a[1]), "r"(a[2]), "r"(a[3]), "r"(b[0]), "r"(b[1]));
}
__device__ __forceinline__ void ldsm4(uint32_t* r, uint32_t addr){
    asm volatile("ldmatrix.sync.aligned.m8n8.x4.shared.b16 {%0,%1,%2,%3}, [%4];"
        : "=r"(r[0]), "=r"(r[1]), "=r"(r[2]), "=r"(r[3]) : "r"(addr));
}
__device__ __forceinline__ void hsplit(float v, __half& h, __half& l){
    h = __float2half_rn(v);
    l = __float2half_rn(v - __half2float(h));
}

// ------------------------- split-fp16 tensor-core GEMM ----------------------
// Terms (TRM=3): Ah*Bh(f32) + Ah*Bl(f16) + Al*Bh(f16).
// Terms (TRM=2): Ah*Bh(f32) + Ah*Bl(f16)   [= Ah * B_exact; A-side fp16]
// For DUAL=1: first half (k-chain) always 3-term; second half uses TRM.
// EPI: 0 none, 1 +bias, 2 +bias+relu.
// PERM: 0 rowmajor (OUTB 0 fp32 / 1 fp16 split), 1 q+rope, 2 memshift,
//       3 k: rope->X1 +pos split->Ch/Cl, 4 v: raw->C +pos split->Ch/Cl.
#define KCH   64
#define ASTR  72
#define TELEM (128*ASTR)
#define STAGEE (4*TELEM)
#define GSMEM (2*STAGEE*2)             // 147456 bytes

template<int EPI, int PERM, int OUTB, int DUAL, int TRM>
__global__ void __launch_bounds__(256, 1) tgemm_k(
    const __half* __restrict__ Ah, const __half* __restrict__ Al,
    const __half* __restrict__ Bh, const __half* __restrict__ Bl,
    const float* __restrict__ bias, float* __restrict__ C,
    __half* __restrict__ Ch, __half* __restrict__ Cl,
    float* __restrict__ X1, const float* __restrict__ pos,
    const __half* __restrict__ A2h, const __half* __restrict__ A2l,
    const __half* __restrict__ B2h, const __half* __restrict__ B2l,
    const float* __restrict__ bias2, float* __restrict__ C2,
    __half* __restrict__ Ch2, __half* __restrict__ Cl2,
    int M, int Nn, int K)
{
    extern __shared__ __half sm[];
    const uint32_t sb = smem_u32(sm);
    int tid = threadIdx.x;
    int warp = tid >> 5, lane = tid & 31;
    int wm = warp & 1, wn = warp >> 1;          // 2 x 4 warps, warp tile 64x32
    int grp = lane >> 2, tig = lane & 3;
    int bx = blockIdx.x, by = blockIdx.y;

    const __half* Au = Ah; const __half* Aul = Al;
    const __half* Bu = Bh; const __half* Bul = Bl;
    const float* bu = bias; float* Cu = C;
    __half* Chu = Ch; __half* Clu = Cl;
    bool second = false;
    if (DUAL) {
        int half_ = gridDim.y >> 1;
        if (by >= half_) {
            Au = A2h; Aul = A2l; Bu = B2h; Bul = B2l;
            bu = bias2; Cu = C2; Chu = Ch2; Clu = Cl2;
            by -= half_;
            second = true;
        }
    }
    const int terms = (DUAL && !second) ? 3 : TRM;

    const __half* Agh = Au  + (size_t)by * 128 * K;
    const __half* Agl = Aul + (size_t)by * 128 * K;
    const __half* Bgh = Bu  + (size_t)bx * 128 * K;
    const __half* Bgl = Bul + (size_t)bx * 128 * K;

    float acc[4][4][4];
    uint32_t acc16[4][4][2];
#pragma unroll
    for (int i = 0; i < 4; i++)
#pragma unroll
        for (int j = 0; j < 4; j++) {
#pragma unroll
            for (int r = 0; r < 4; r++) acc[i][j][r] = 0.f;
            acc16[i][j][0] = 0u; acc16[i][j][1] = 0u;
        }

    int NC = K / KCH;

    auto load_stage = [&](int c, int s) {
        int k0 = c * KCH;
        uint32_t sbase = sb + s * STAGEE * 2;
#pragma unroll
        for (int i = 0; i < 4; i++) {
            int idx = tid + i * 256;
            int row = idx >> 3, kc = (idx & 7) * 8;
            uint32_t so = sbase + (uint32_t)(row * ASTR + kc) * 2;
            size_t go = (size_t)row * K + k0 + kc;
            cp16(so,                 Agh + go);
            if (terms == 3) cp16(so + TELEM * 2, Agl + go);
            cp16(so + 2 * TELEM * 2, Bgh + go);
            cp16(so + 3 * TELEM * 2, Bgl + go);
        }
    };

    load_stage(0, 0);
    asm volatile("cp.async.commit_group;");

    int a_r  = lane & 15;
    int a_k8 = (lane >> 4) * 8;
    int b_l  = lane & 7;
    int b_seg = lane >> 3;
    int b_r  = (b_seg >= 2) ? b_l + 8 : b_l;
    int b_k8 = (b_seg & 1) * 8;

    for (int c = 0; c < NC; c++) {
        if (c + 1 < NC) {
            load_stage(c + 1, (c + 1) & 1);
            asm volatile("cp.async.commit_group;");
            asm volatile("cp.async.wait_group 1;");
        } else {
            asm volatile("cp.async.wait_group 0;");
        }
        __syncthreads();

        uint32_t sA  = sb + (c & 1) * STAGEE * 2;
        uint32_t sAl = sA + TELEM * 2;
        uint32_t sBh = sA + 2 * TELEM * 2;
        uint32_t sBl = sA + 3 * TELEM * 2;

#pragma unroll
        for (int ks = 0; ks < KCH / 16; ks++) {
            int kbase = ks * 16;
            uint32_t ah[4][4], al[4][4], bh[2][4], bl[2][4];
#pragma unroll
            for (int mt = 0; mt < 4; mt++) {
                uint32_t off = (uint32_t)((wm * 64 + mt * 16 + a_r) * ASTR + kbase + a_k8) * 2;
                ldsm4(ah[mt], sA  + off);
                if (terms == 3) ldsm4(al[mt], sAl + off);
            }
#pragma unroll
            for (int np = 0; np < 2; np++) {
                uint32_t off = (uint32_t)((wn * 32 + np * 16 + b_r) * ASTR + kbase + b_k8) * 2;
                ldsm4(bh[np], sBh + off);
                ldsm4(bl[np], sBl + off);
            }
#pragma unroll
            for (int mt = 0; mt < 4; mt++)
#pragma unroll
                for (int nt = 0; nt < 4; nt++) {
                    const uint32_t* bhp = &bh[nt >> 1][(nt & 1) * 2];
                    const uint32_t* blp = &bl[nt >> 1][(nt & 1) * 2];
                    mma_f32(acc[mt][nt], ah[mt], bhp);
                    mma_f16(acc16[mt][nt], ah[mt], blp);
                    if (terms == 3) mma_f16(acc16[mt][nt], al[mt], bhp);
                }
        }
        __syncthreads();
    }

    // epilogue (merge f16 correction accumulators)
#pragma unroll
    for (int mt = 0; mt < 4; mt++)
#pragma unroll
        for (int h8 = 0; h8 < 2; h8++) {
            int rowg = by * 128 + wm * 64 + mt * 16 + grp + h8 * 8;
#pragma unroll
            for (int nt = 0; nt < 4; nt++) {
                int colg = bx * 128 + wn * 32 + nt * 8 + tig * 2;
                __half2 hc = *(__half2*)&acc16[mt][nt][h8];
                float v0 = acc[mt][nt][h8 * 2 + 0] + __low2float(hc);
                float v1 = acc[mt][nt][h8 * 2 + 1] + __high2float(hc);
                if (EPI >= 1) { v0 += bu[colg]; v1 += bu[colg + 1]; }
                if (EPI == 2) { v0 = fmaxf(v0, 0.f); v1 = fmaxf(v1, 0.f); }
                if (PERM == 0) {
                    size_t rb = (size_t)rowg * Nn + colg;
                    if (OUTB) {
                        __half2 H, L;
                        hsplit(v0, H.x, L.x); hsplit(v1, H.y, L.y);
                        *(__half2*)(Chu + rb) = H;
                        *(__half2*)(Clu + rb) = L;
                    } else {
                        float2 p; p.x = v0; p.y = v1;
                        *(float2*)(Cu + rb) = p;
                    }
                } else if (PERM == 2) {
                    size_t rb = (size_t)(rowg + (rowg >> 7) + 1) * Nn + colg;
                    float2 p; p.x = v0; p.y = v1;
                    *(float2*)(Cu + rb) = p;
                } else {
                    int b = rowg >> 12, n = rowg & 4095;
                    int h = colg >> 7, d = colg & 127;
                    size_t dst = (((size_t)((b * HEADS + h) * SEQ + n)) << 7) + d;
                    if (PERM == 1 || PERM == 3) {
                        float inv = (float)exp(-(double)d * (9.210340371976184 / 128.0));
                        float t = (float)n * inv;
                        float s, cc; sincosf(t, &s, &cc);
                        float r0 = v0 * cc - v1 * s;
                        float r1 = v0 * s + v1 * cc;
                        float2 rp; rp.x = r0; rp.y = r1;
                        *(float2*)(X1 + dst) = rp;
                    }
                    if (PERM == 1 || PERM == 4) {
                        float2 p; p.x = v0; p.y = v1;
                        *(float2*)(Cu + dst) = p;
                    }
                    if (PERM == 3 || PERM == 4) {
                        const float* pp = pos + h * 4096 + (n & 31) * 128 + d;
                        __half2 H, L;
                        hsplit(v0 + pp[0], H.x, L.x);
                        hsplit(v1 + pp[1], H.y, L.y);
                        *(__half2*)(Chu + dst) = H;
                        *(__half2*)(Clu + dst) = L;
                    }
                }
            }
        }
}

// ------------------------- fp32 -> hi/lo fp16 convert ------------------------
__global__ void cvt_k(const float4* __restrict__ x, __half2* __restrict__ hi,
                      __half2* __restrict__ lo, int n4)
{
    int i = blockIdx.x * 256 + threadIdx.x;
    if (i >= n4) return;
    float4 v = x[i];
    __half2 H0, H1, L0, L1;
    hsplit(v.x, H0.x, L0.x); hsplit(v.y, H0.y, L0.y);
    hsplit(v.z, H1.x, L1.x); hsplit(v.w, H1.y, L1.y);
    hi[i * 2] = H0; hi[i * 2 + 1] = H1;
    lo[i * 2] = L0; lo[i * 2 + 1] = L1;
}

// transpose-convert: W[K,N] fp32 -> Wt hi/lo [N,K] fp16
__global__ void cvtT_k(const float* __restrict__ x, __half* __restrict__ hi,
                       __half* __restrict__ lo, int K, int N)
{
    __shared__ float t[32][33];
    int bx = blockIdx.x, by = blockIdx.y;
    int tx = threadIdx.x & 31, ty = threadIdx.x >> 5;
#pragma unroll
    for (int i = 0; i < 32; i += 8) {
        int kk = by * 32 + ty + i;
        t[ty + i][tx] = x[(size_t)kk * N + bx * 32 + tx];
    }
    __syncthreads();
#pragma unroll
    for (int i = 0; i < 32; i += 8) {
        int n = bx * 32 + ty + i;
        int kk = by * 32 + tx;
        float v = t[tx][ty + i];
        __half h, l; hsplit(v, h, l);
        hi[(size_t)n * K + kk] = h;
        lo[(size_t)n * K + kk] = l;
    }
}

// ------------------------- fused rmsnorm + gates ----------------------------
__global__ void gates_k(const float* __restrict__ inp, const float* __restrict__ g,
                        const float* __restrict__ Wg, const float* __restrict__ bg,
                        float* __restrict__ gates)
{
    __shared__ float xs[DIM];
    __shared__ float red[8];
    int row = blockIdx.x;
    int tid = threadIdx.x;
    const float* ip = inp + (size_t)row * DIM;
    float ss = 0.f;
    for (int k = tid; k < DIM; k += 256) { float v = ip[k]; xs[k] = v; ss += v * v; }
#pragma unroll
    for (int o = 16; o > 0; o >>= 1) ss += __shfl_xor_sync(~0u, ss, o);
    if ((tid & 31) == 0) red[tid >> 5] = ss;
    __syncthreads();
    float tot = red[0] + red[1] + red[2] + red[3] + red[4] + red[5] + red[6] + red[7];
    float rn = 1.0f / sqrtf(tot * (1.0f / DIM) + EPSV);
    int lane = tid & 31, warp = tid >> 5;
    for (int c = warp; c < 2 * HEADS; c += 8) {
        float acc = 0.f;
        for (int k = lane; k < DIM; k += 32) acc += xs[k] * g[k] * Wg[(size_t)k * (2 * HEADS) + c];
#pragma unroll
        for (int o = 16; o > 0; o >>= 1) acc += __shfl_xor_sync(~0u, acc, o);
        if (lane == 0) gates[(size_t)row * (2 * HEADS) + c] = 1.f / (1.f + expf(-(acc * rn + bg[c])));
    }
}

// ------------------------- mem slots into ckf/cvf ---------------------------
__global__ void fillmem_k(const float* __restrict__ memkv,
                          float* __restrict__ ckf, float* __restrict__ cvf)
{
    int idx = blockIdx.x * 256 + threadIdx.x;
    if (idx >= BATCH * HEADS * DHEAD) return;
    int d = idx & 127; int h = (idx >> 7) & 15; int b = idx >> 11;
    size_t dst = (((size_t)((b * HEADS + h) * CM)) << 7) + d;
    ckf[dst] = memkv[h * 128 + d];
    cvf[dst] = memkv[HEADS * 128 + h * 128 + d];
}

// ------------------------- compressed attention -----------------------------
__global__ void __launch_bounds__(256) attn_c_k(
    const float* __restrict__ q, const float* __restrict__ ckf,
    const float* __restrict__ cvf, float* __restrict__ cout,
    float* __restrict__ imp_part)
{
    extern __shared__ float smf[];
    float* qs   = smf;
    float* sims = smf + 64 * 128;
    float* cs   = sims + 64 * 132;
    int tid = threadIdx.x;
    int bh = blockIdx.y, n0 = blockIdx.x * 64;
    const float* qb = q + (((size_t)bh * SEQ + n0) << 7);
#pragma unroll
    for (int i = 0; i < 8; i++) {
        int vdx = tid + i * 256;
        int row = vdx >> 5, c4 = (vdx & 31) * 4;
        *(float4*)&qs[row * 128 + c4] = *(const float4*)(qb + row * 128 + c4);
    }
    int tx = tid & 15, ty = tid >> 4;

    for (int m0 = 0; m0 < CM; m0 += 32) {
        int mc = (CM - m0 < 32) ? (CM - m0) : 32;
        for (int vdx = tid; vdx < mc * 32; vdx += 256) {
            int rr = vdx >> 5, c4 = (vdx & 31) * 4;
            float4 t = *(const float4*)(ckf + (((size_t)bh * CM + m0 + rr) << 7) + c4);
            cs[rr * 132 + c4 + 0] = t.x; cs[rr * 132 + c4 + 1] = t.y;
            cs[rr * 132 + c4 + 2] = t.z; cs[rr * 132 + c4 + 3] = t.w;
        }
        __syncthreads();
        float a0[2] = {0, 0}, a1[2] = {0, 0}, a2[2] = {0, 0}, a3[2] = {0, 0};
#pragma unroll 4
        for (int k = 0; k < 128; k++) {
            float q0 = qs[(ty * 4 + 0) * 128 + k];
            float q1 = qs[(ty * 4 + 1) * 128 + k];
            float q2 = qs[(ty * 4 + 2) * 128 + k];
            float q3 = qs[(ty * 4 + 3) * 128 + k];
            float c0 = cs[(tx * 2 + 0) * 132 + k];
            float c1 = cs[(tx * 2 + 1) * 132 + k];
            a0[0] += q0 * c0; a0[1] += q0 * c1;
            a1[0] += q1 * c0; a1[1] += q1 * c1;
            a2[0] += q2 * c0; a2[1] += q2 * c1;
            a3[0] += q3 * c0; a3[1] += q3 * c1;
        }
#pragma unroll
        for (int mm = 0; mm < 2; mm++) {
            int m = tx * 2 + mm;
            if (m < mc) {
                sims[(ty * 4 + 0) * 132 + m0 + m] = a0[mm] * SCALEV;
                sims[(ty * 4 + 1) * 132 + m0 + m] = a1[mm] * SCALEV;
                sims[(ty * 4 + 2) * 132 + m0 + m] = a2[mm] * SCALEV;
                sims[(ty * 4 + 3) * 132 + m0 + m] = a3[mm] * SCALEV;
            }
        }
        __syncthreads();
    }

    {
        int lane = tid & 31, wrp = tid >> 5;
        for (int r = wrp; r < 64; r += 8) {
            float* srow = sims + r * 132;
            float mx = -1e38f;
            for (int m = lane; m < CM; m += 32) mx = fmaxf(mx, srow[m]);
#pragma unroll
            for (int o = 16; o > 0; o >>= 1) mx = fmaxf(mx, __shfl_xor_sync(~0u, mx, o));
            float sum = 0.f;
            for (int m = lane; m < CM; m += 32) { float e = expf(srow[m] - mx); srow[m] = e; sum += e; }
#pragma unroll
            for (int o = 16; o > 0; o >>= 1) sum += __shfl_xor_sync(~0u, sum, o);
            float inv = 1.f / sum;
            for (int m = lane; m < CM; m += 32) srow[m] *= inv;
        }
    }
    __syncthreads();
    if (tid < 128) {
        float s = 0.f;
        for (int r = 0; r < 64; r++) s += sims[r * 132 + 1 + tid];
        imp_part[(((size_t)bh * 64) + blockIdx.x) * 128 + tid] = s;
    }
    __syncthreads();

    float oacc[4][8];
#pragma unroll
    for (int i = 0; i < 4; i++)
#pragma unroll
        for (int j = 0; j < 8; j++) oacc[i][j] = 0.f;

    for (int m0 = 0; m0 < CM; m0 += 32) {
        int mc = (CM - m0 < 32) ? (CM - m0) : 32;
        for (int vdx = tid; vdx < mc * 32; vdx += 256) {
            int rr = vdx >> 5, c4 = (vdx & 31) * 4;
            float4 t = *(const float4*)(cvf + (((size_t)bh * CM + m0 + rr) << 7) + c4);
            cs[rr * 132 + c4 + 0] = t.x; cs[rr * 132 + c4 + 1] = t.y;
            cs[rr * 132 + c4 + 2] = t.z; cs[rr * 132 + c4 + 3] = t.w;
        }
        __syncthreads();
        for (int mm = 0; mm < mc; mm++) {
            float p0 = sims[(ty * 4 + 0) * 132 + m0 + mm];
            float p1 = sims[(ty * 4 + 1) * 132 + m0 + mm];
            float p2 = sims[(ty * 4 + 2) * 132 + m0 + mm];
            float p3 = sims[(ty * 4 + 3) * 132 + m0 + mm];
            float bv[8];
            *(float4*)&bv[0] = *(float4*)&cs[mm * 132 + tx * 8];
            *(float4*)&bv[4] = *(float4*)&cs[mm * 132 + tx * 8 + 4];
#pragma unroll
            for (int j = 0; j < 8; j++) {
                oacc[0][j] += p0 * bv[j];
                oacc[1][j] += p1 * bv[j];
                oacc[2][j] += p2 * bv[j];
                oacc[3][j] += p3 * bv[j];
            }
        }
        __syncthreads();
    }
#pragma unroll
    for (int rr = 0; rr < 4; rr++) {
        size_t dst = (((size_t)bh * SEQ) + n0 + ty * 4 + rr) * 128 + tx * 8;
        *(float4*)&cout[dst]     = *(float4*)&oacc[rr][0];
        *(float4*)&cout[dst + 4] = *(float4*)&oacc[rr][4];
    }
}

// ------------------------- importance reduce + top-k ------------------------
__global__ void topk_k(const float* __restrict__ imp_part,
                       int* __restrict__ idxout, int* __restrict__ maskout)
{
    __shared__ float vals[WBLK];
    int bh = blockIdx.x, tid = threadIdx.x;
    float s = 0.f;
    for (int t = 0; t < 64; t++) s += imp_part[(((size_t)bh * 64) + t) * 128 + tid];
    vals[tid] = s * (1.0f / SEQ);
    __syncthreads();
    if (tid == 0) {
        for (int sel = 0; sel < SELK; sel++) {
            float best = -1e38f; int bi = 0;
            for (int m = 0; m < WBLK; m++)
                if (vals[m] > best) { best = vals[m]; bi = m; }
            idxout[bh * SELK + sel] = bi;
            maskout[bh * SELK + sel] = (best > 1e-10f) ? 1 : 0;
            vals[bi] = -1e38f;
        }
    }
}

// ------------------------- selected (fine) attention, fused gather ----------
__global__ void __launch_bounds__(256) attn_f_k(
    const float* __restrict__ qr, const float* __restrict__ kr,
    const float* __restrict__ v, const int* __restrict__ idxs,
    const int* __restrict__ fmask, float* __restrict__ fout)
{
    extern __shared__ float smf[];
    float* qs   = smf;
    float* sims = smf + 4096;
    float* cs   = sims + 16512;
    __shared__ int maskS[SELK];
    __shared__ int blkS[SELK];
    int tid = threadIdx.x;
    int bh = blockIdx.y, n0 = blockIdx.x * 32;
    if (tid < SELK) {
        maskS[tid] = fmask[bh * SELK + tid];
        blkS[tid]  = idxs[bh * SELK + tid];
    }
    const float* qb = qr + (((size_t)bh * SEQ + n0) << 7);
#pragma unroll
    for (int i = 0; i < 4; i++) {
        int vdx = tid + i * 256;
        int row = vdx >> 5, c4 = (vdx & 31) * 4;
        *(float4*)&qs[row * 128 + c4] = *(const float4*)(qb + row * 128 + c4);
    }
    __syncthreads();
    int tx = tid & 15, ty = tid >> 4;

    for (int m0 = 0; m0 < 512; m0 += 32) {
        int blk = blkS[m0 >> 5];
        const float* kb = kr + (((size_t)bh * SEQ + blk * BLKSZ) << 7);
        for (int vdx = tid; vdx < 32 * 32; vdx += 256) {
            int rr = vdx >> 5, c4 = (vdx & 31) * 4;
            float4 t = *(const float4*)(kb + ((size_t)rr << 7) + c4);
            cs[rr * 132 + c4 + 0] = t.x; cs[rr * 132 + c4 + 1] = t.y;
            cs[rr * 132 + c4 + 2] = t.z; cs[rr * 132 + c4 + 3] = t.w;
        }
        __syncthreads();
        float a00 = 0, a01 = 0, a10 = 0, a11 = 0;
#pragma unroll 4
        for (int k = 0; k < 128; k++) {
            float q0 = qs[(ty * 2 + 0) * 128 + k], q1 = qs[(ty * 2 + 1) * 128 + k];
            float c0 = cs[(tx * 2 + 0) * 132 + k], c1 = cs[(tx * 2 + 1) * 132 + k];
            a00 += q0 * c0; a01 += q0 * c1; a10 += q1 * c0; a11 += q1 * c1;
        }
        sims[(ty * 2 + 0) * 516 + m0 + tx * 2 + 0] = a00 * SCALEV;
        sims[(ty * 2 + 0) * 516 + m0 + tx * 2 + 1] = a01 * SCALEV;
        sims[(ty * 2 + 1) * 516 + m0 + tx * 2 + 0] = a10 * SCALEV;
        sims[(ty * 2 + 1) * 516 + m0 + tx * 2 + 1] = a11 * SCALEV;
        __syncthreads();
    }

    {
        int lane = tid & 31, wrp = tid >> 5;
        for (int r = wrp; r < 32; r += 8) {
            float* srow = sims + r * 516;
            float mx = -1e38f;
            for (int m = lane; m < 512; m += 32) {
                float vv = srow[m];
                if (!maskS[m >> 5]) vv = NEGV;
                srow[m] = vv;
                mx = fmaxf(mx, vv);
            }
#pragma unroll
            for (int o = 16; o > 0; o >>= 1) mx = fmaxf(mx, __shfl_xor_sync(~0u, mx, o));
            float sum = 0.f;
            for (int m = lane; m < 512; m += 32) { float e = expf(srow[m] - mx); srow[m] = e; sum += e; }
#pragma unroll
            for (int o = 16; o > 0; o >>= 1) sum += __shfl_xor_sync(~0u, sum, o);
            float inv = 1.f / sum;
            for (int m = lane; m < 512; m += 32) srow[m] *= inv;
        }
    }
    __syncthreads();

    float o0[8], o1[8];
#pragma unroll
    for (int j = 0; j < 8; j++) { o0[j] = 0.f; o1[j] = 0.f; }
    for (int m0 = 0; m0 < 512; m0 += 32) {
        int blk = blkS[m0 >> 5];
        const float* vb = v + (((size_t)bh * SEQ + blk * BLKSZ) << 7);
        for (int vdx = tid; vdx < 32 * 32; vdx += 256) {
            int rr = vdx >> 5, c4 = (vdx & 31) * 4;
            float4 t = *(const float4*)(vb + ((size_t)rr << 7) + c4);
            cs[rr * 132 + c4 + 0] = t.x; cs[rr * 132 + c4 + 1] = t.y;
            cs[rr * 132 + c4 + 2] = t.z; cs[rr * 132 + c4 + 3] = t.w;
        }
        __syncthreads();
        for (int mm = 0; mm < 32; mm++) {
            float p0 = sims[(ty * 2 + 0) * 516 + m0 + mm];
            float p1 = sims[(ty * 2 + 1) * 516 + m0 + mm];
            float bv[8];
            *(float4*)&bv[0] = *(float4*)&cs[mm * 132 + tx * 8];
            *(float4*)&bv[4] = *(float4*)&cs[mm * 132 + tx * 8 + 4];
#pragma unroll
            for (int j = 0; j < 8; j++) { o0[j] += p0 * bv[j]; o1[j] += p1 * bv[j]; }
        }
        __syncthreads();
    }
    size_t dst0 = (((size_t)bh * SEQ) + n0 + ty * 2 + 0) * 128 + tx * 8;
    size_t dst1 = (((size_t)bh * SEQ) + n0 + ty * 2 + 1) * 128 + tx * 8;
    *(float4*)&fout[dst0] = *(float4*)&o0[0]; *(float4*)&fout[dst0 + 4] = *(float4*)&o0[4];
    *(float4*)&fout[dst1] = *(float4*)&o1[0]; *(float4*)&fout[dst1 + 4] = *(float4*)&o1[4];
}

// ------------------------- combine gates -> fp16 hi/lo ----------------------
__global__ void combine2_k(const float* __restrict__ cout, const float* __restrict__ fout,
                           const float* __restrict__ gates,
                           __half* __restrict__ oh, __half* __restrict__ ol)
{
    int idx = blockIdx.x * 256 + threadIdx.x;
    int d = idx & 127; int h = (idx >> 7) & 15; int nrow = idx >> 11;
    int b = nrow >> 12; int n = nrow & 4095;
    size_t src = (((size_t)(b * HEADS + h) * SEQ) + n) * 128 + d;
    float g0 = gates[(size_t)nrow * (2 * HEADS) + 2 * h];
    float g1 = gates[(size_t)nrow * (2 * HEADS) + 2 * h + 1];
    float v = g0 * cout[src] + g1 * fout[src];
    __half hh, ll; hsplit(v, hh, ll);
    oh[idx] = hh; ol[idx] = ll;
}

// ------------------------- launch ------------------------------------------
extern "C" void kernel_launch(void* const* d_in, const int* in_sizes, int n_in,
                              void* d_out, int out_size)
{
    const float* inp  = (const float*)d_in[0];
    const float* g    = (const float*)d_in[1];
    const float* Wq   = (const float*)d_in[2];
    const float* Wk   = (const float*)d_in[3];
    const float* Wv   = (const float*)d_in[4];
    const float* kpos = (const float*)d_in[5];
    const float* vpos = (const float*)d_in[6];
    const float* memkv= (const float*)d_in[7];
    const float* kW1  = (const float*)d_in[8];
    const float* kb1  = (const float*)d_in[9];
    const float* kW2  = (const float*)d_in[10];
    const float* kb2  = (const float*)d_in[11];
    const float* vW1  = (const float*)d_in[12];
    const float* vb1  = (const float*)d_in[13];
    const float* vW2  = (const float*)d_in[14];
    const float* vb2  = (const float*)d_in[15];
    const float* Wg   = (const float*)d_in[16];
    const float* bg   = (const float*)d_in[17];
    const float* Wo   = (const float*)d_in[18];
    float* out = (float*)d_out;

    float *q, *qr, *kr, *v, *ckf, *cvf, *cout, *fout, *gates, *imp;
    int *idxs, *msk;
    cudaGetSymbolAddress((void**)&q,    g_q);
    cudaGetSymbolAddress((void**)&qr,   g_qr);
    cudaGetSymbolAddress((void**)&kr,   g_kr);
    cudaGetSymbolAddress((void**)&v,    g_v);
    cudaGetSymbolAddress((void**)&ckf,  g_ckf);
    cudaGetSymbolAddress((void**)&cvf,  g_cvf);
    cudaGetSymbolAddress((void**)&cout, g_cout);
    cudaGetSymbolAddress((void**)&fout, g_fout);
    cudaGetSymbolAddress((void**)&gates,g_gates);
    cudaGetSymbolAddress((void**)&imp,  g_imp_part);
    cudaGetSymbolAddress((void**)&idxs, g_idx);
    cudaGetSymbolAddress((void**)&msk,  g_msk);

    __half *inph,*inpl,*wqh,*wql,*wkh,*wkl,*wvh,*wvl,*kw1h,*kw1l,*vw1h,*vw1l;
    __half *kw2h,*kw2l,*vw2h,*vw2l,*woh,*wol,*kch,*kcl,*vch,*vcl;
    __half *h1kh,*h1kl,*h1vh,*h1vl,*oph,*opl;
    cudaGetSymbolAddress((void**)&inph, b_inp_h); cudaGetSymbolAddress((void**)&inpl, b_inp_l);
    cudaGetSymbolAddress((void**)&wqh,  b_wq_h);  cudaGetSymbolAddress((void**)&wql,  b_wq_l);
    cudaGetSymbolAddress((void**)&wkh,  b_wk_h);  cudaGetSymbolAddress((void**)&wkl,  b_wk_l);
    cudaGetSymbolAddress((void**)&wvh,  b_wv_h);  cudaGetSymbolAddress((void**)&wvl,  b_wv_l);
    cudaGetSymbolAddress((void**)&kw1h, b_kw1_h); cudaGetSymbolAddress((void**)&kw1l, b_kw1_l);
    cudaGetSymbolAddress((void**)&vw1h, b_vw1_h); cudaGetSymbolAddress((void**)&vw1l, b_vw1_l);
    cudaGetSymbolAddress((void**)&kw2h, b_kw2_h); cudaGetSymbolAddress((void**)&kw2l, b_kw2_l);
    cudaGetSymbolAddress((void**)&vw2h, b_vw2_h); cudaGetSymbolAddress((void**)&vw2l, b_vw2_l);
    cudaGetSymbolAddress((void**)&woh,  b_wo_h);  cudaGetSymbolAddress((void**)&wol,  b_wo_l);
    cudaGetSymbolAddress((void**)&kch,  b_kc_h);  cudaGetSymbolAddress((void**)&kcl,  b_kc_l);
    cudaGetSymbolAddress((void**)&vch,  b_vc_h);  cudaGetSymbolAddress((void**)&vcl,  b_vc_l);
    cudaGetSymbolAddress((void**)&h1kh, b_h1k_h); cudaGetSymbolAddress((void**)&h1kl, b_h1k_l);
    cudaGetSymbolAddress((void**)&h1vh, b_h1v_h); cudaGetSymbolAddress((void**)&h1vl, b_h1v_l);
    cudaGetSymbolAddress((void**)&oph,  b_op_h);  cudaGetSymbolAddress((void**)&opl,  b_op_l);

    const int SMEM_C = (64 * 128 + 64 * 132 + 32 * 132) * 4;
    const int SMEM_F = (32 * 128 + 32 * 516 + 32 * 132) * 4;
    cudaFuncSetAttribute(attn_c_k, cudaFuncAttributeMaxDynamicSharedMemorySize, SMEM_C);
    cudaFuncSetAttribute(attn_f_k, cudaFuncAttributeMaxDynamicSharedMemorySize, SMEM_F);
    cudaFuncSetAttribute(tgemm_k<0,1,0,0,3>, cudaFuncAttributeMaxDynamicSharedMemorySize, GSMEM);
    cudaFuncSetAttribute(tgemm_k<0,3,0,0,3>, cudaFuncAttributeMaxDynamicSharedMemorySize, GSMEM);
    cudaFuncSetAttribute(tgemm_k<0,4,0,0,2>, cudaFuncAttributeMaxDynamicSharedMemorySize, GSMEM);
    cudaFuncSetAttribute(tgemm_k<2,0,1,1,2>, cudaFuncAttributeMaxDynamicSharedMemorySize, GSMEM);
    cudaFuncSetAttribute(tgemm_k<1,2,0,1,2>, cudaFuncAttributeMaxDynamicSharedMemorySize, GSMEM);
    cudaFuncSetAttribute(tgemm_k<0,0,0,0,2>, cudaFuncAttributeMaxDynamicSharedMemorySize, GSMEM);

    // 0) converts
    cvt_k<<<(ROWS*DIM/4 + 255)/256, 256>>>((const float4*)inp, (__half2*)inph, (__half2*)inpl, ROWS*DIM/4);
    cvtT_k<<<dim3(DIM/32, DIM/32), 256>>>(Wq, wqh, wql, DIM, DIM);
    cvtT_k<<<dim3(DIM/32, DIM/32), 256>>>(Wk, wkh, wkl, DIM, DIM);
    cvtT_k<<<dim3(DIM/32, DIM/32), 256>>>(Wv, wvh, wvl, DIM, DIM);
    cvtT_k<<<dim3(HIDC/32, HIDC/32), 256>>>(kW1, kw1h, kw1l, HIDC, HIDC);

    // 1) QKV projections with fused RoPE / pos-pack epilogues
    dim3 gq(DIM/128, ROWS/128);
    tgemm_k<0,1,0,0,3><<<gq, 256, GSMEM>>>(inph, inpl, wqh, wql, nullptr, q, nullptr, nullptr,
        qr, nullptr, nullptr, nullptr, nullptr, nullptr, nullptr, nullptr, nullptr, nullptr,
        ROWS, DIM, DIM);
    tgemm_k<0,3,0,0,3><<<gq, 256, GSMEM>>>(inph, inpl, wkh, wkl, nullptr, nullptr, kch, kcl,
        kr, kpos, nullptr, nullptr, nullptr, nullptr, nullptr, nullptr, nullptr, nullptr,
        ROWS, DIM, DIM);
    tgemm_k<0,4,0,0,2><<<gq, 256, GSMEM>>>(inph, inpl, wvh, wvl, nullptr, v, vch, vcl,
        nullptr, vpos, nullptr, nullptr, nullptr, nullptr, nullptr, nullptr, nullptr, nullptr,
        ROWS, DIM, DIM);

    // remaining converts + gates (overlap with GEMM tails)
    cvtT_k<<<dim3(HIDC/32, HIDC/32), 256>>>(vW1, vw1h, vw1l, HIDC, HIDC);
    cvtT_k<<<dim3(DHEAD/32, HIDC/32), 256>>>(kW2, kw2h, kw2l, HIDC, DHEAD);
    cvtT_k<<<dim3(DHEAD/32, HIDC/32), 256>>>(vW2, vw2h, vw2l, HIDC, DHEAD);
    cvtT_k<<<dim3(DIM/32, DIM/32), 256>>>(Wo, woh, wol, DIM, DIM);
    gates_k<<<ROWS, 256>>>(inp, g, Wg, bg, gates);

    // 3) compress MLP layer 1 — k (3-term) and v (2-term) dual launch
    tgemm_k<2,0,1,1,2><<<dim3(HIDC/128, 2*(HIDC/128)), 256, GSMEM>>>(
        kch, kcl, kw1h, kw1l, kb1, nullptr, h1kh, h1kl, nullptr, nullptr,
        vch, vcl, vw1h, vw1l, vb1, nullptr, h1vh, h1vl,
        BATCH*HEADS*WBLK, HIDC, HIDC);

    // 4) compress MLP layer 2 — k (3-term) and v (2-term) dual launch
    tgemm_k<1,2,0,1,2><<<dim3(1, 64), 256, GSMEM>>>(
        h1kh, h1kl, kw2h, kw2l, kb2, ckf, nullptr, nullptr, nullptr, nullptr,
        h1vh, h1vl, vw2h, vw2l, vb2, cvf, nullptr, nullptr,
        BATCH*HEADS*WBLK, DHEAD, HIDC);
    fillmem_k<<<16, 256>>>(memkv, ckf, cvf);

    // 5) compressed attention + importance partials
    attn_c_k<<<dim3(SEQ/64, BATCH*HEADS), 256, SMEM_C>>>(q, ckf, cvf, cout, imp);

    // 6) top-k
    topk_k<<<BATCH*HEADS, 128>>>(imp, idxs, msk);

    // 7) fine attention (gather fused via block indices)
    attn_f_k<<<dim3(SEQ/32, BATCH*HEADS), 256, SMEM_F>>>(qr, kr, v, idxs, msk, fout);

    // 8) gate-combine -> split fp16
    combine2_k<<<QKVN/256, 256>>>(cout, fout, gates, oph, opl);

    // 9) output projection (fp32 out, 2-term)
    tgemm_k<0,0,0,0,2><<<dim3(DIM/128, ROWS/128), 256, GSMEM>>>(
        oph, opl, woh, wol, nullptr, out, nullptr, nullptr, nullptr, nullptr,
        nullptr, nullptr, nullptr, nullptr, nullptr, nullptr, nullptr, nullptr,
        ROWS, DIM, DIM);
}

// round 14
// speedup vs baseline: 1.1549x; 1.1075x over previous
#include <cuda_runtime.h>
#include <cuda_fp16.h>
#include <math.h>
#include <stdint.h>

// Problem constants
#define BATCH 2
#define SEQ   4096
#define DIM   2048
#define HEADS 16
#define DHEAD 128
#define BLKSZ 32
#define SELK  16
#define HIDC  4096
#define WBLK  128
#define CM    129
#define ROWS  (BATCH*SEQ)
#define QKVN  (BATCH*HEADS*SEQ*DHEAD)
#define NEGV  (-1e30f)
#define EPSV  1.1920929e-7f
#define SCALEV 0.08838834764831845f

// ------------------------- scratch (device globals) -------------------------
__device__ __align__(256) float g_q [QKVN];
__device__ __align__(256) float g_qr[QKVN];
__device__ __align__(256) float g_kr[QKVN];
__device__ __align__(256) float g_v [QKVN];
__device__ __align__(256) float g_ckf[BATCH*HEADS*CM*DHEAD];
__device__ __align__(256) float g_cvf[BATCH*HEADS*CM*DHEAD];
__device__ __align__(256) float g_cout[QKVN];
__device__ __align__(256) float g_fout[QKVN];
__device__ __align__(256) float g_gates[ROWS*2*HEADS];
__device__ __align__(256) float g_imp_part[BATCH*HEADS*64*WBLK];
__device__ int g_idx[BATCH*HEADS*SELK];
__device__ int g_msk[BATCH*HEADS*SELK];

// fp16 hi/lo split operands
__device__ __align__(256) __half b_inp_h[ROWS*DIM],  b_inp_l[ROWS*DIM];
__device__ __align__(256) __half b_wq_h[DIM*DIM],    b_wq_l[DIM*DIM];
__device__ __align__(256) __half b_wk_h[DIM*DIM],    b_wk_l[DIM*DIM];
__device__ __align__(256) __half b_wv_h[DIM*DIM],    b_wv_l[DIM*DIM];
__device__ __align__(256) __half b_kw1_h[HIDC*HIDC], b_kw1_l[HIDC*HIDC];
__device__ __align__(256) __half b_vw1_h[HIDC*HIDC], b_vw1_l[HIDC*HIDC];
__device__ __align__(256) __half b_kw2_h[DHEAD*HIDC],b_kw2_l[DHEAD*HIDC];
__device__ __align__(256) __half b_vw2_h[DHEAD*HIDC],b_vw2_l[DHEAD*HIDC];
__device__ __align__(256) __half b_wo_h[DIM*DIM],    b_wo_l[DIM*DIM];
__device__ __align__(256) __half b_kc_h[QKVN],       b_kc_l[QKVN];
__device__ __align__(256) __half b_vc_h[QKVN],       b_vc_l[QKVN];
__device__ __align__(256) __half b_h1k_h[HIDC*HIDC], b_h1k_l[HIDC*HIDC];
__device__ __align__(256) __half b_h1v_h[HIDC*HIDC], b_h1v_l[HIDC*HIDC];
__device__ __align__(256) __half b_op_h[ROWS*DIM],   b_op_l[ROWS*DIM];

// ------------------------- helpers ------------------------------------------
__device__ __forceinline__ uint32_t smem_u32(const void* p){
    uint32_t a;
    asm("{ .reg .u64 t; cvta.to.shared.u64 t, %1; cvt.u32.u64 %0, t; }" : "=r"(a) : "l"(p));
    return a;
}
__device__ __forceinline__ void cp16(uint32_t saddr, const void* gaddr){
    asm volatile("cp.async.cg.shared.global [%0], [%1], 16;" :: "r"(saddr), "l"(gaddr));
}
__device__ __forceinline__ void mma_f32(float* c, const uint32_t* a, const uint32_t* b){
    asm volatile("mma.sync.aligned.m16n8k16.row.col.f32.f16.f16.f32 "
        "{%0,%1,%2,%3}, {%4,%5,%6,%7}, {%8,%9}, {%0,%1,%2,%3};"
        : "+f"(c[0]), "+f"(c[1]), "+f"(c[2]), "+f"(c[3])
        : "r"(a[0]), "r"(a[1]), "r"(a[2]), "r"(a[3]), "r"(b[0]), "r"(b[1]));
}
__device__ __forceinline__ void mma_f16(uint32_t* c, const uint32_t* a, const uint32_t* b){
    asm volatile("mma.sync.aligned.m16n8k16.row.col.f16.f16.f16.f16 "
        "{%0,%1}, {%2,%3,%4,%5}, {%6,%7}, {%0,%1};"
        : "+r"(c[0]), "+r"(c[1])
        : "r"(a[0]), "r"(a[1]), "r"(a[2]), "r"(a[3]), "r"(b[0]), "r"(b[1]));
}
__device__ __forceinline__ void ldsm4(uint32_t* r, uint32_t addr){
    asm volatile("ldmatrix.sync.aligned.m8n8.x4.shared.b16 {%0,%1,%2,%3}, [%4];"
        : "=r"(r[0]), "=r"(r[1]), "=r"(r[2]), "=r"(r[3]) : "r"(addr));
}
__device__ __forceinline__ void hsplit(float v, __half& h, __half& l){
    h = __float2half_rn(v);
    l = __float2half_rn(v - __half2float(h));
}

// ------------------------- split-fp16 tensor-core GEMM ----------------------
// Terms (TRM=2): Ah*Bh(f32) + Ah*Bl(f16)   [= Ah * B_exact; A-side fp16 hi]
// Terms (TRM=3): adds Al*Bh(f16).
// EPI: 0 none, 1 +bias, 2 +bias+relu.
// PERM: 0 rowmajor (OUTB 0 fp32 / 1 fp16 split), 1 q+rope, 2 memshift,
//       3 k: rope->X1 +pos split->Ch/Cl, 4 v: raw->C +pos split->Ch/Cl.
#define KCH   64
#define ASTR  72
#define TELEM (128*ASTR)
#define STAGEE (4*TELEM)
#define GSMEM (2*STAGEE*2)             // 147456 bytes

template<int EPI, int PERM, int OUTB, int DUAL, int TRM>
__global__ void __launch_bounds__(256, 1) tgemm_k(
    const __half* __restrict__ Ah, const __half* __restrict__ Al,
    const __half* __restrict__ Bh, const __half* __restrict__ Bl,
    const float* __restrict__ bias, float* __restrict__ C,
    __half* __restrict__ Ch, __half* __restrict__ Cl,
    float* __restrict__ X1, const float* __restrict__ pos,
    const __half* __restrict__ A2h, const __half* __restrict__ A2l,
    const __half* __restrict__ B2h, const __half* __restrict__ B2l,
    const float* __restrict__ bias2, float* __restrict__ C2,
    __half* __restrict__ Ch2, __half* __restrict__ Cl2,
    int M, int Nn, int K)
{
    extern __shared__ __half sm[];
    const uint32_t sb = smem_u32(sm);
    int tid = threadIdx.x;
    int warp = tid >> 5, lane = tid & 31;
    int wm = warp & 1, wn = warp >> 1;          // 2 x 4 warps, warp tile 64x32
    int grp = lane >> 2, tig = lane & 3;
    int bx = blockIdx.x, by = blockIdx.y;

    const __half* Au = Ah; const __half* Aul = Al;
    const __half* Bu = Bh; const __half* Bul = Bl;
    const float* bu = bias; float* Cu = C;
    __half* Chu = Ch; __half* Clu = Cl;
    if (DUAL) {
        int half_ = gridDim.y >> 1;
        if (by >= half_) {
            Au = A2h; Aul = A2l; Bu = B2h; Bul = B2l;
            bu = bias2; Cu = C2; Chu = Ch2; Clu = Cl2;
            by -= half_;
        }
    }
    const int terms = TRM;

    const __half* Agh = Au  + (size_t)by * 128 * K;
    const __half* Agl = Aul + (size_t)by * 128 * K;
    const __half* Bgh = Bu  + (size_t)bx * 128 * K;
    const __half* Bgl = Bul + (size_t)bx * 128 * K;

    float acc[4][4][4];
    uint32_t acc16[4][4][2];
#pragma unroll
    for (int i = 0; i < 4; i++)
#pragma unroll
        for (int j = 0; j < 4; j++) {
#pragma unroll
            for (int r = 0; r < 4; r++) acc[i][j][r] = 0.f;
            acc16[i][j][0] = 0u; acc16[i][j][1] = 0u;
        }

    int NC = K / KCH;

    auto load_stage = [&](int c, int s) {
        int k0 = c * KCH;
        uint32_t sbase = sb + s * STAGEE * 2;
#pragma unroll
        for (int i = 0; i < 4; i++) {
            int idx = tid + i * 256;
            int row = idx >> 3, kc = (idx & 7) * 8;
            uint32_t so = sbase + (uint32_t)(row * ASTR + kc) * 2;
            size_t go = (size_t)row * K + k0 + kc;
            cp16(so,                 Agh + go);
            if (terms == 3) cp16(so + TELEM * 2, Agl + go);
            cp16(so + 2 * TELEM * 2, Bgh + go);
            cp16(so + 3 * TELEM * 2, Bgl + go);
        }
    };

    load_stage(0, 0);
    asm volatile("cp.async.commit_group;");

    int a_r  = lane & 15;
    int a_k8 = (lane >> 4) * 8;
    int b_l  = lane & 7;
    int b_seg = lane >> 3;
    int b_r  = (b_seg >= 2) ? b_l + 8 : b_l;
    int b_k8 = (b_seg & 1) * 8;

    for (int c = 0; c < NC; c++) {
        if (c + 1 < NC) {
            load_stage(c + 1, (c + 1) & 1);
            asm volatile("cp.async.commit_group;");
            asm volatile("cp.async.wait_group 1;");
        } else {
            asm volatile("cp.async.wait_group 0;");
        }
        __syncthreads();

        uint32_t sA  = sb + (c & 1) * STAGEE * 2;
        uint32_t sAl = sA + TELEM * 2;
        uint32_t sBh = sA + 2 * TELEM * 2;
        uint32_t sBl = sA + 3 * TELEM * 2;

#pragma unroll
        for (int ks = 0; ks < KCH / 16; ks++) {
            int kbase = ks * 16;
            uint32_t ah[4][4], al[4][4], bh[2][4], bl[2][4];
#pragma unroll
            for (int mt = 0; mt < 4; mt++) {
                uint32_t off = (uint32_t)((wm * 64 + mt * 16 + a_r) * ASTR + kbase + a_k8) * 2;
                ldsm4(ah[mt], sA  + off);
                if (terms == 3) ldsm4(al[mt], sAl + off);
            }
#pragma unroll
            for (int np = 0; np < 2; np++) {
                uint32_t off = (uint32_t)((wn * 32 + np * 16 + b_r) * ASTR + kbase + b_k8) * 2;
                ldsm4(bh[np], sBh + off);
                ldsm4(bl[np], sBl + off);
            }
#pragma unroll
            for (int mt = 0; mt < 4; mt++)
#pragma unroll
                for (int nt = 0; nt < 4; nt++) {
                    const uint32_t* bhp = &bh[nt >> 1][(nt & 1) * 2];
                    const uint32_t* blp = &bl[nt >> 1][(nt & 1) * 2];
                    mma_f32(acc[mt][nt], ah[mt], bhp);
                    mma_f16(acc16[mt][nt], ah[mt], blp);
                    if (terms == 3) mma_f16(acc16[mt][nt], al[mt], bhp);
                }
        }
        __syncthreads();
    }

    // epilogue (merge f16 correction accumulators)
#pragma unroll
    for (int mt = 0; mt < 4; mt++)
#pragma unroll
        for (int h8 = 0; h8 < 2; h8++) {
            int rowg = by * 128 + wm * 64 + mt * 16 + grp + h8 * 8;
#pragma unroll
            for (int nt = 0; nt < 4; nt++) {
                int colg = bx * 128 + wn * 32 + nt * 8 + tig * 2;
                __half2 hc = *(__half2*)&acc16[mt][nt][h8];
                float v0 = acc[mt][nt][h8 * 2 + 0] + __low2float(hc);
                float v1 = acc[mt][nt][h8 * 2 + 1] + __high2float(hc);
                if (EPI >= 1) { v0 += bu[colg]; v1 += bu[colg + 1]; }
                if (EPI == 2) { v0 = fmaxf(v0, 0.f); v1 = fmaxf(v1, 0.f); }
                if (PERM == 0) {
                    size_t rb = (size_t)rowg * Nn + colg;
                    if (OUTB) {
                        __half2 H, L;
                        hsplit(v0, H.x, L.x); hsplit(v1, H.y, L.y);
                        *(__half2*)(Chu + rb) = H;
                        *(__half2*)(Clu + rb) = L;
                    } else {
                        float2 p; p.x = v0; p.y = v1;
                        *(float2*)(Cu + rb) = p;
                    }
                } else if (PERM == 2) {
                    size_t rb = (size_t)(rowg + (rowg >> 7) + 1) * Nn + colg;
                    float2 p; p.x = v0; p.y = v1;
                    *(float2*)(Cu + rb) = p;
                } else {
                    int b = rowg >> 12, n = rowg & 4095;
                    int h = colg >> 7, d = colg & 127;
                    size_t dst = (((size_t)((b * HEADS + h) * SEQ + n)) << 7) + d;
                    if (PERM == 1 || PERM == 3) {
                        float inv = (float)exp(-(double)d * (9.210340371976184 / 128.0));
                        float t = (float)n * inv;
                        float s, cc; sincosf(t, &s, &cc);
                        float r0 = v0 * cc - v1 * s;
                        float r1 = v0 * s + v1 * cc;
                        float2 rp; rp.x = r0; rp.y = r1;
                        *(float2*)(X1 + dst) = rp;
                    }
                    if (PERM == 1 || PERM == 4) {
                        float2 p; p.x = v0; p.y = v1;
                        *(float2*)(Cu + dst) = p;
                    }
                    if (PERM == 3 || PERM == 4) {
                        const float* pp = pos + h * 4096 + (n & 31) * 128 + d;
                        __half2 H, L;
                        hsplit(v0 + pp[0], H.x, L.x);
                        hsplit(v1 + pp[1], H.y, L.y);
                        *(__half2*)(Chu + dst) = H;
                        *(__half2*)(Clu + dst) = L;
                    }
                }
            }
        }
}

// ------------------------- fp32 -> hi/lo fp16 convert ------------------------
__global__ void cvt_k(const float4* __restrict__ x, __half2* __restrict__ hi,
                      __half2* __restrict__ lo, int n4)
{
    int i = blockIdx.x * 256 + threadIdx.x;
    if (i >= n4) return;
    float4 v = x[i];
    __half2 H0, H1, L0, L1;
    hsplit(v.x, H0.x, L0.x); hsplit(v.y, H0.y, L0.y);
    hsplit(v.z, H1.x, L1.x); hsplit(v.w, H1.y, L1.y);
    hi[i * 2] = H0; hi[i * 2 + 1] = H1;
    lo[i * 2] = L0; lo[i * 2 + 1] = L1;
}

// transpose-convert: W[K,N] fp32 -> Wt hi/lo [N,K] fp16
__global__ void cvtT_k(const float* __restrict__ x, __half* __restrict__ hi,
                       __half* __restrict__ lo, int K, int N)
{
    __shared__ float t[32][33];
    int bx = blockIdx.x, by = blockIdx.y;
    int tx = threadIdx.x & 31, ty = threadIdx.x >> 5;
#pragma unroll
    for (int i = 0; i < 32; i += 8) {
        int kk = by * 32 + ty + i;
        t[ty + i][tx] = x[(size_t)kk * N + bx * 32 + tx];
    }
    __syncthreads();
#pragma unroll
    for (int i = 0; i < 32; i += 8) {
        int n = bx * 32 + ty + i;
        int kk = by * 32 + tx;
        float v = t[tx][ty + i];
        __half h, l; hsplit(v, h, l);
        hi[(size_t)n * K + kk] = h;
        lo[(size_t)n * K + kk] = l;
    }
}

// ------------------------- fused rmsnorm + gates ----------------------------
__global__ void gates_k(const float* __restrict__ inp, const float* __restrict__ g,
                        const float* __restrict__ Wg, const float* __restrict__ bg,
                        float* __restrict__ gates)
{
    __shared__ float xs[DIM];
    __shared__ float red[8];
    int row = blockIdx.x;
    int tid = threadIdx.x;
    const float* ip = inp + (size_t)row * DIM;
    float ss = 0.f;
    for (int k = tid; k < DIM; k += 256) { float v = ip[k]; xs[k] = v; ss += v * v; }
#pragma unroll
    for (int o = 16; o > 0; o >>= 1) ss += __shfl_xor_sync(~0u, ss, o);
    if ((tid & 31) == 0) red[tid >> 5] = ss;
    __syncthreads();
    float tot = red[0] + red[1] + red[2] + red[3] + red[4] + red[5] + red[6] + red[7];
    float rn = 1.0f / sqrtf(tot * (1.0f / DIM) + EPSV);
    int lane = tid & 31, warp = tid >> 5;
    for (int c = warp; c < 2 * HEADS; c += 8) {
        float acc = 0.f;
        for (int k = lane; k < DIM; k += 32) acc += xs[k] * g[k] * Wg[(size_t)k * (2 * HEADS) + c];
#pragma unroll
        for (int o = 16; o > 0; o >>= 1) acc += __shfl_xor_sync(~0u, acc, o);
        if (lane == 0) gates[(size_t)row * (2 * HEADS) + c] = 1.f / (1.f + expf(-(acc * rn + bg[c])));
    }
}

// ------------------------- mem slots into ckf/cvf ---------------------------
__global__ void fillmem_k(const float* __restrict__ memkv,
                          float* __restrict__ ckf, float* __restrict__ cvf)
{
    int idx = blockIdx.x * 256 + threadIdx.x;
    if (idx >= BATCH * HEADS * DHEAD) return;
    int d = idx & 127; int h = (idx >> 7) & 15; int b = idx >> 11;
    size_t dst = (((size_t)((b * HEADS + h) * CM)) << 7) + d;
    ckf[dst] = memkv[h * 128 + d];
    cvf[dst] = memkv[HEADS * 128 + h * 128 + d];
}

// ------------------------- compressed attention -----------------------------
__global__ void __launch_bounds__(256) attn_c_k(
    const float* __restrict__ q, const float* __restrict__ ckf,
    const float* __restrict__ cvf, float* __restrict__ cout,
    float* __restrict__ imp_part)
{
    extern __shared__ float smf[];
    float* qs   = smf;
    float* sims = smf + 64 * 128;
    float* cs   = sims + 64 * 132;
    int tid = threadIdx.x;
    int bh = blockIdx.y, n0 = blockIdx.x * 64;
    const float* qb = q + (((size_t)bh * SEQ + n0) << 7);
#pragma unroll
    for (int i = 0; i < 8; i++) {
        int vdx = tid + i * 256;
        int row = vdx >> 5, c4 = (vdx & 31) * 4;
        *(float4*)&qs[row * 128 + c4] = *(const float4*)(qb + row * 128 + c4);
    }
    int tx = tid & 15, ty = tid >> 4;

    for (int m0 = 0; m0 < CM; m0 += 32) {
        int mc = (CM - m0 < 32) ? (CM - m0) : 32;
        for (int vdx = tid; vdx < mc * 32; vdx += 256) {
            int rr = vdx >> 5, c4 = (vdx & 31) * 4;
            float4 t = *(const float4*)(ckf + (((size_t)bh * CM + m0 + rr) << 7) + c4);
            cs[rr * 132 + c4 + 0] = t.x; cs[rr * 132 + c4 + 1] = t.y;
            cs[rr * 132 + c4 + 2] = t.z; cs[rr * 132 + c4 + 3] = t.w;
        }
        __syncthreads();
        float a0[2] = {0, 0}, a1[2] = {0, 0}, a2[2] = {0, 0}, a3[2] = {0, 0};
#pragma unroll 4
        for (int k = 0; k < 128; k++) {
            float q0 = qs[(ty * 4 + 0) * 128 + k];
            float q1 = qs[(ty * 4 + 1) * 128 + k];
            float q2 = qs[(ty * 4 + 2) * 128 + k];
            float q3 = qs[(ty * 4 + 3) * 128 + k];
            float c0 = cs[(tx * 2 + 0) * 132 + k];
            float c1 = cs[(tx * 2 + 1) * 132 + k];
            a0[0] += q0 * c0; a0[1] += q0 * c1;
            a1[0] += q1 * c0; a1[1] += q1 * c1;
            a2[0] += q2 * c0; a2[1] += q2 * c1;
            a3[0] += q3 * c0; a3[1] += q3 * c1;
        }
#pragma unroll
        for (int mm = 0; mm < 2; mm++) {
            int m = tx * 2 + mm;
            if (m < mc) {
                sims[(ty * 4 + 0) * 132 + m0 + m] = a0[mm] * SCALEV;
                sims[(ty * 4 + 1) * 132 + m0 + m] = a1[mm] * SCALEV;
                sims[(ty * 4 + 2) * 132 + m0 + m] = a2[mm] * SCALEV;
                sims[(ty * 4 + 3) * 132 + m0 + m] = a3[mm] * SCALEV;
            }
        }
        __syncthreads();
    }

    {
        int lane = tid & 31, wrp = tid >> 5;
        for (int r = wrp; r < 64; r += 8) {
            float* srow = sims + r * 132;
            float mx = -1e38f;
            for (int m = lane; m < CM; m += 32) mx = fmaxf(mx, srow[m]);
#pragma unroll
            for (int o = 16; o > 0; o >>= 1) mx = fmaxf(mx, __shfl_xor_sync(~0u, mx, o));
            float sum = 0.f;
            for (int m = lane; m < CM; m += 32) { float e = expf(srow[m] - mx); srow[m] = e; sum += e; }
#pragma unroll
            for (int o = 16; o > 0; o >>= 1) sum += __shfl_xor_sync(~0u, sum, o);
            float inv = 1.f / sum;
            for (int m = lane; m < CM; m += 32) srow[m] *= inv;
        }
    }
    __syncthreads();
    if (tid < 128) {
        float s = 0.f;
        for (int r = 0; r < 64; r++) s += sims[r * 132 + 1 + tid];
        imp_part[(((size_t)bh * 64) + blockIdx.x) * 128 + tid] = s;
    }
    __syncthreads();

    float oacc[4][8];
#pragma unroll
    for (int i = 0; i < 4; i++)
#pragma unroll
        for (int j = 0; j < 8; j++) oacc[i][j] = 0.f;

    for (int m0 = 0; m0 < CM; m0 += 32) {
        int mc = (CM - m0 < 32) ? (CM - m0) : 32;
        for (int vdx = tid; vdx < mc * 32; vdx += 256) {
            int rr = vdx >> 5, c4 = (vdx & 31) * 4;
            float4 t = *(const float4*)(cvf + (((size_t)bh * CM + m0 + rr) << 7) + c4);
            cs[rr * 132 + c4 + 0] = t.x; cs[rr * 132 + c4 + 1] = t.y;
            cs[rr * 132 + c4 + 2] = t.z; cs[rr * 132 + c4 + 3] = t.w;
        }
        __syncthreads();
        for (int mm = 0; mm < mc; mm++) {
            float p0 = sims[(ty * 4 + 0) * 132 + m0 + mm];
            float p1 = sims[(ty * 4 + 1) * 132 + m0 + mm];
            float p2 = sims[(ty * 4 + 2) * 132 + m0 + mm];
            float p3 = sims[(ty * 4 + 3) * 132 + m0 + mm];
            float bv[8];
            *(float4*)&bv[0] = *(float4*)&cs[mm * 132 + tx * 8];
            *(float4*)&bv[4] = *(float4*)&cs[mm * 132 + tx * 8 + 4];
#pragma unroll
            for (int j = 0; j < 8; j++) {
                oacc[0][j] += p0 * bv[j];
                oacc[1][j] += p1 * bv[j];
                oacc[2][j] += p2 * bv[j];
                oacc[3][j] += p3 * bv[j];
            }
        }
        __syncthreads();
    }
#pragma unroll
    for (int rr = 0; rr < 4; rr++) {
        size_t dst = (((size_t)bh * SEQ) + n0 + ty * 4 + rr) * 128 + tx * 8;
        *(float4*)&cout[dst]     = *(float4*)&oacc[rr][0];
        *(float4*)&cout[dst + 4] = *(float4*)&oacc[rr][4];
    }
}

// ------------------------- importance reduce + top-k ------------------------
__global__ void topk_k(const float* __restrict__ imp_part,
                       int* __restrict__ idxout, int* __restrict__ maskout)
{
    __shared__ float vals[WBLK];
    int bh = blockIdx.x, tid = threadIdx.x;
    float s = 0.f;
    for (int t = 0; t < 64; t++) s += imp_part[(((size_t)bh * 64) + t) * 128 + tid];
    vals[tid] = s * (1.0f / SEQ);
    __syncthreads();
    if (tid == 0) {
        for (int sel = 0; sel < SELK; sel++) {
            float best = -1e38f; int bi = 0;
            for (int m = 0; m < WBLK; m++)
                if (vals[m] > best) { best = vals[m]; bi = m; }
            idxout[bh * SELK + sel] = bi;
            maskout[bh * SELK + sel] = (best > 1e-10f) ? 1 : 0;
            vals[bi] = -1e38f;
        }
    }
}

// ------------------------- selected (fine) attention, fused gather ----------
__global__ void __launch_bounds__(256) attn_f_k(
    const float* __restrict__ qr, const float* __restrict__ kr,
    const float* __restrict__ v, const int* __restrict__ idxs,
    const int* __restrict__ fmask, float* __restrict__ fout)
{
    extern __shared__ float smf[];
    float* qs   = smf;
    float* sims = smf + 4096;
    float* cs   = sims + 16512;
    __shared__ int maskS[SELK];
    __shared__ int blkS[SELK];
    int tid = threadIdx.x;
    int bh = blockIdx.y, n0 = blockIdx.x * 32;
    if (tid < SELK) {
        maskS[tid] = fmask[bh * SELK + tid];
        blkS[tid]  = idxs[bh * SELK + tid];
    }
    const float* qb = qr + (((size_t)bh * SEQ + n0) << 7);
#pragma unroll
    for (int i = 0; i < 4; i++) {
        int vdx = tid + i * 256;
        int row = vdx >> 5, c4 = (vdx & 31) * 4;
        *(float4*)&qs[row * 128 + c4] = *(const float4*)(qb + row * 128 + c4);
    }
    __syncthreads();
    int tx = tid & 15, ty = tid >> 4;

    for (int m0 = 0; m0 < 512; m0 += 32) {
        int blk = blkS[m0 >> 5];
        const float* kb = kr + (((size_t)bh * SEQ + blk * BLKSZ) << 7);
        for (int vdx = tid; vdx < 32 * 32; vdx += 256) {
            int rr = vdx >> 5, c4 = (vdx & 31) * 4;
            float4 t = *(const float4*)(kb + ((size_t)rr << 7) + c4);
            cs[rr * 132 + c4 + 0] = t.x; cs[rr * 132 + c4 + 1] = t.y;
            cs[rr * 132 + c4 + 2] = t.z; cs[rr * 132 + c4 + 3] = t.w;
        }
        __syncthreads();
        float a00 = 0, a01 = 0, a10 = 0, a11 = 0;
#pragma unroll 4
        for (int k = 0; k < 128; k++) {
            float q0 = qs[(ty * 2 + 0) * 128 + k], q1 = qs[(ty * 2 + 1) * 128 + k];
            float c0 = cs[(tx * 2 + 0) * 132 + k], c1 = cs[(tx * 2 + 1) * 132 + k];
            a00 += q0 * c0; a01 += q0 * c1; a10 += q1 * c0; a11 += q1 * c1;
        }
        sims[(ty * 2 + 0) * 516 + m0 + tx * 2 + 0] = a00 * SCALEV;
        sims[(ty * 2 + 0) * 516 + m0 + tx * 2 + 1] = a01 * SCALEV;
        sims[(ty * 2 + 1) * 516 + m0 + tx * 2 + 0] = a10 * SCALEV;
        sims[(ty * 2 + 1) * 516 + m0 + tx * 2 + 1] = a11 * SCALEV;
        __syncthreads();
    }

    {
        int lane = tid & 31, wrp = tid >> 5;
        for (int r = wrp; r < 32; r += 8) {
            float* srow = sims + r * 516;
            float mx = -1e38f;
            for (int m = lane; m < 512; m += 32) {
                float vv = srow[m];
                if (!maskS[m >> 5]) vv = NEGV;
                srow[m] = vv;
                mx = fmaxf(mx, vv);
            }
#pragma unroll
            for (int o = 16; o > 0; o >>= 1) mx = fmaxf(mx, __shfl_xor_sync(~0u, mx, o));
            float sum = 0.f;
            for (int m = lane; m < 512; m += 32) { float e = expf(srow[m] - mx); srow[m] = e; sum += e; }
#pragma unroll
            for (int o = 16; o > 0; o >>= 1) sum += __shfl_xor_sync(~0u, sum, o);
            float inv = 1.f / sum;
            for (int m = lane; m < 512; m += 32) srow[m] *= inv;
        }
    }
    __syncthreads();

    float o0[8], o1[8];
#pragma unroll
    for (int j = 0; j < 8; j++) { o0[j] = 0.f; o1[j] = 0.f; }
    for (int m0 = 0; m0 < 512; m0 += 32) {
        int blk = blkS[m0 >> 5];
        const float* vb = v + (((size_t)bh * SEQ + blk * BLKSZ) << 7);
        for (int vdx = tid; vdx < 32 * 32; vdx += 256) {
            int rr = vdx >> 5, c4 = (vdx & 31) * 4;
            float4 t = *(const float4*)(vb + ((size_t)rr << 7) + c4);
            cs[rr * 132 + c4 + 0] = t.x; cs[rr * 132 + c4 + 1] = t.y;
            cs[rr * 132 + c4 + 2] = t.z; cs[rr * 132 + c4 + 3] = t.w;
        }
        __syncthreads();
        for (int mm = 0; mm < 32; mm++) {
            float p0 = sims[(ty * 2 + 0) * 516 + m0 + mm];
            float p1 = sims[(ty * 2 + 1) * 516 + m0 + mm];
            float bv[8];
            *(float4*)&bv[0] = *(float4*)&cs[mm * 132 + tx * 8];
            *(float4*)&bv[4] = *(float4*)&cs[mm * 132 + tx * 8 + 4];
#pragma unroll
            for (int j = 0; j < 8; j++) { o0[j] += p0 * bv[j]; o1[j] += p1 * bv[j]; }
        }
        __syncthreads();
    }
    size_t dst0 = (((size_t)bh * SEQ) + n0 + ty * 2 + 0) * 128 + tx * 8;
    size_t dst1 = (((size_t)bh * SEQ) + n0 + ty * 2 + 1) * 128 + tx * 8;
    *(float4*)&fout[dst0] = *(float4*)&o0[0]; *(float4*)&fout[dst0 + 4] = *(float4*)&o0[4];
    *(float4*)&fout[dst1] = *(float4*)&o1[0]; *(float4*)&fout[dst1 + 4] = *(float4*)&o1[4];
}

// ------------------------- combine gates -> fp16 hi/lo ----------------------
__global__ void combine2_k(const float* __restrict__ cout, const float* __restrict__ fout,
                           const float* __restrict__ gates,
                           __half* __restrict__ oh, __half* __restrict__ ol)
{
    int idx = blockIdx.x * 256 + threadIdx.x;
    int d = idx & 127; int h = (idx >> 7) & 15; int nrow = idx >> 11;
    int b = nrow >> 12; int n = nrow & 4095;
    size_t src = (((size_t)(b * HEADS + h) * SEQ) + n) * 128 + d;
    float g0 = gates[(size_t)nrow * (2 * HEADS) + 2 * h];
    float g1 = gates[(size_t)nrow * (2 * HEADS) + 2 * h + 1];
    float v = g0 * cout[src] + g1 * fout[src];
    __half hh, ll; hsplit(v, hh, ll);
    oh[idx] = hh; ol[idx] = ll;
}

// ------------------------- launch ------------------------------------------
extern "C" void kernel_launch(void* const* d_in, const int* in_sizes, int n_in,
                              void* d_out, int out_size)
{
    const float* inp  = (const float*)d_in[0];
    const float* g    = (const float*)d_in[1];
    const float* Wq   = (const float*)d_in[2];
    const float* Wk   = (const float*)d_in[3];
    const float* Wv   = (const float*)d_in[4];
    const float* kpos = (const float*)d_in[5];
    const float* vpos = (const float*)d_in[6];
    const float* memkv= (const float*)d_in[7];
    const float* kW1  = (const float*)d_in[8];
    const float* kb1  = (const float*)d_in[9];
    const float* kW2  = (const float*)d_in[10];
    const float* kb2  = (const float*)d_in[11];
    const float* vW1  = (const float*)d_in[12];
    const float* vb1  = (const float*)d_in[13];
    const float* vW2  = (const float*)d_in[14];
    const float* vb2  = (const float*)d_in[15];
    const float* Wg   = (const float*)d_in[16];
    const float* bg   = (const float*)d_in[17];
    const float* Wo   = (const float*)d_in[18];
    float* out = (float*)d_out;

    float *q, *qr, *kr, *v, *ckf, *cvf, *cout, *fout, *gates, *imp;
    int *idxs, *msk;
    cudaGetSymbolAddress((void**)&q,    g_q);
    cudaGetSymbolAddress((void**)&qr,   g_qr);
    cudaGetSymbolAddress((void**)&kr,   g_kr);
    cudaGetSymbolAddress((void**)&v,    g_v);
    cudaGetSymbolAddress((void**)&ckf,  g_ckf);
    cudaGetSymbolAddress((void**)&cvf,  g_cvf);
    cudaGetSymbolAddress((void**)&cout, g_cout);
    cudaGetSymbolAddress((void**)&fout, g_fout);
    cudaGetSymbolAddress((void**)&gates,g_gates);
    cudaGetSymbolAddress((void**)&imp,  g_imp_part);
    cudaGetSymbolAddress((void**)&idxs, g_idx);
    cudaGetSymbolAddress((void**)&msk,  g_msk);

    __half *inph,*inpl,*wqh,*wql,*wkh,*wkl,*wvh,*wvl,*kw1h,*kw1l,*vw1h,*vw1l;
    __half *kw2h,*kw2l,*vw2h,*vw2l,*woh,*wol,*kch,*kcl,*vch,*vcl;
    __half *h1kh,*h1kl,*h1vh,*h1vl,*oph,*opl;
    cudaGetSymbolAddress((void**)&inph, b_inp_h); cudaGetSymbolAddress((void**)&inpl, b_inp_l);
    cudaGetSymbolAddress((void**)&wqh,  b_wq_h);  cudaGetSymbolAddress((void**)&wql,  b_wq_l);
    cudaGetSymbolAddress((void**)&wkh,  b_wk_h);  cudaGetSymbolAddress((void**)&wkl,  b_wk_l);
    cudaGetSymbolAddress((void**)&wvh,  b_wv_h);  cudaGetSymbolAddress((void**)&wvl,  b_wv_l);
    cudaGetSymbolAddress((void**)&kw1h, b_kw1_h); cudaGetSymbolAddress((void**)&kw1l, b_kw1_l);
    cudaGetSymbolAddress((void**)&vw1h, b_vw1_h); cudaGetSymbolAddress((void**)&vw1l, b_vw1_l);
    cudaGetSymbolAddress((void**)&kw2h, b_kw2_h); cudaGetSymbolAddress((void**)&kw2l, b_kw2_l);
    cudaGetSymbolAddress((void**)&vw2h, b_vw2_h); cudaGetSymbolAddress((void**)&vw2l, b_vw2_l);
    cudaGetSymbolAddress((void**)&woh,  b_wo_h);  cudaGetSymbolAddress((void**)&wol,  b_wo_l);
    cudaGetSymbolAddress((void**)&kch,  b_kc_h);  cudaGetSymbolAddress((void**)&kcl,  b_kc_l);
    cudaGetSymbolAddress((void**)&vch,  b_vc_h);  cudaGetSymbolAddress((void**)&vcl,  b_vc_l);
    cudaGetSymbolAddress((void**)&h1kh, b_h1k_h); cudaGetSymbolAddress((void**)&h1kl, b_h1k_l);
    cudaGetSymbolAddress((void**)&h1vh, b_h1v_h); cudaGetSymbolAddress((void**)&h1vl, b_h1v_l);
    cudaGetSymbolAddress((void**)&oph,  b_op_h);  cudaGetSymbolAddress((void**)&opl,  b_op_l);

    const int SMEM_C = (64 * 128 + 64 * 132 + 32 * 132) * 4;
    const int SMEM_F = (32 * 128 + 32 * 516 + 32 * 132) * 4;
    cudaFuncSetAttribute(attn_c_k, cudaFuncAttributeMaxDynamicSharedMemorySize, SMEM_C);
    cudaFuncSetAttribute(attn_f_k, cudaFuncAttributeMaxDynamicSharedMemorySize, SMEM_F);
    cudaFuncSetAttribute(tgemm_k<0,1,0,0,2>, cudaFuncAttributeMaxDynamicSharedMemorySize, GSMEM);
    cudaFuncSetAttribute(tgemm_k<0,3,0,0,2>, cudaFuncAttributeMaxDynamicSharedMemorySize, GSMEM);
    cudaFuncSetAttribute(tgemm_k<0,4,0,0,2>, cudaFuncAttributeMaxDynamicSharedMemorySize, GSMEM);
    cudaFuncSetAttribute(tgemm_k<2,0,1,1,2>, cudaFuncAttributeMaxDynamicSharedMemorySize, GSMEM);
    cudaFuncSetAttribute(tgemm_k<1,2,0,1,2>, cudaFuncAttributeMaxDynamicSharedMemorySize, GSMEM);
    cudaFuncSetAttribute(tgemm_k<0,0,0,0,2>, cudaFuncAttributeMaxDynamicSharedMemorySize, GSMEM);

    // 0) converts
    cvt_k<<<(ROWS*DIM/4 + 255)/256, 256>>>((const float4*)inp, (__half2*)inph, (__half2*)inpl, ROWS*DIM/4);
    cvtT_k<<<dim3(DIM/32, DIM/32), 256>>>(Wq, wqh, wql, DIM, DIM);
    cvtT_k<<<dim3(DIM/32, DIM/32), 256>>>(Wk, wkh, wkl, DIM, DIM);
    cvtT_k<<<dim3(DIM/32, DIM/32), 256>>>(Wv, wvh, wvl, DIM, DIM);
    cvtT_k<<<dim3(HIDC/32, HIDC/32), 256>>>(kW1, kw1h, kw1l, HIDC, HIDC);

    // 1) QKV projections with fused RoPE / pos-pack epilogues
    dim3 gq(DIM/128, ROWS/128);
    tgemm_k<0,1,0,0,2><<<gq, 256, GSMEM>>>(inph, inpl, wqh, wql, nullptr, q, nullptr, nullptr,
        qr, nullptr, nullptr, nullptr, nullptr, nullptr, nullptr, nullptr, nullptr, nullptr,
        ROWS, DIM, DIM);
    tgemm_k<0,3,0,0,2><<<gq, 256, GSMEM>>>(inph, inpl, wkh, wkl, nullptr, nullptr, kch, kcl,
        kr, kpos, nullptr, nullptr, nullptr, nullptr, nullptr, nullptr, nullptr, nullptr,
        ROWS, DIM, DIM);
    tgemm_k<0,4,0,0,2><<<gq, 256, GSMEM>>>(inph, inpl, wvh, wvl, nullptr, v, vch, vcl,
        nullptr, vpos, nullptr, nullptr, nullptr, nullptr, nullptr, nullptr, nullptr, nullptr,
        ROWS, DIM, DIM);

    // remaining converts + gates (overlap with GEMM tails)
    cvtT_k<<<dim3(HIDC/32, HIDC/32), 256>>>(vW1, vw1h, vw1l, HIDC, HIDC);
    cvtT_k<<<dim3(DHEAD/32, HIDC/32), 256>>>(kW2, kw2h, kw2l, HIDC, DHEAD);
    cvtT_k<<<dim3(DHEAD/32, HIDC/32), 256>>>(vW2, vw2h, vw2l, HIDC, DHEAD);
    cvtT_k<<<dim3(DIM/32, DIM/32), 256>>>(Wo, woh, wol, DIM, DIM);
    gates_k<<<ROWS, 256>>>(inp, g, Wg, bg, gates);

    // 3) compress MLP layer 1 — k and v dual launch (both 2-term)
    tgemm_k<2,0,1,1,2><<<dim3(HIDC/128, 2*(HIDC/128)), 256, GSMEM>>>(
        kch, kcl, kw1h, kw1l, kb1, nullptr, h1kh, h1kl, nullptr, nullptr,
        vch, vcl, vw1h, vw1l, vb1, nullptr, h1vh, h1vl,
        BATCH*HEADS*WBLK, HIDC, HIDC);

    // 4) compress MLP layer 2 — k and v dual launch (both 2-term)
    tgemm_k<1,2,0,1,2><<<dim3(1, 64), 256, GSMEM>>>(
        h1kh, h1kl, kw2h, kw2l, kb2, ckf, nullptr, nullptr, nullptr, nullptr,
        h1vh, h1vl, vw2h, vw2l, vb2, cvf, nullptr, nullptr,
        BATCH*HEADS*WBLK, DHEAD, HIDC);
    fillmem_k<<<16, 256>>>(memkv, ckf, cvf);

    // 5) compressed attention + importance partials
    attn_c_k<<<dim3(SEQ/64, BATCH*HEADS), 256, SMEM_C>>>(q, ckf, cvf, cout, imp);

    // 6) top-k
    topk_k<<<BATCH*HEADS, 128>>>(imp, idxs, msk);

    // 7) fine attention (gather fused via block indices)
    attn_f_k<<<dim3(SEQ/32, BATCH*HEADS), 256, SMEM_F>>>(qr, kr, v, idxs, msk, fout);

    // 8) gate-combine -> split fp16
    combine2_k<<<QKVN/256, 256>>>(cout, fout, gates, oph, opl);

    // 9) output projection (fp32 out, 2-term)
    tgemm_k<0,0,0,0,2><<<dim3(DIM/128, ROWS/128), 256, GSMEM>>>(
        oph, opl, woh, wol, nullptr, out, nullptr, nullptr, nullptr, nullptr,
        nullptr, nullptr, nullptr, nullptr, nullptr, nullptr, nullptr, nullptr,
        ROWS, DIM, DIM);
}

// round 15
// speedup vs baseline: 1.2978x; 1.1237x over previous
#include <cuda_runtime.h>
#include <cuda_fp16.h>
#include <math.h>
#include <stdint.h>

// Problem constants
#define BATCH 2
#define SEQ   4096
#define DIM   2048
#define HEADS 16
#define DHEAD 128
#define BLKSZ 32
#define SELK  16
#define HIDC  4096
#define WBLK  128
#define CM    129
#define ROWS  (BATCH*SEQ)
#define QKVN  (BATCH*HEADS*SEQ*DHEAD)
#define NEGV  (-1e30f)
#define EPSV  1.1920929e-7f
#define SCALEV 0.08838834764831845f

// ------------------------- scratch (device globals) -------------------------
__device__ __align__(256) float g_q [QKVN];
__device__ __align__(256) float g_qr[QKVN];
__device__ __align__(256) float g_kr[QKVN];
__device__ __align__(256) float g_v [QKVN];
__device__ __align__(256) float g_ckf[BATCH*HEADS*CM*DHEAD];
__device__ __align__(256) float g_cvf[BATCH*HEADS*CM*DHEAD];
__device__ __align__(256) float g_cout[QKVN];
__device__ __align__(256) float g_fout[QKVN];
__device__ __align__(256) float g_gates[ROWS*2*HEADS];
__device__ __align__(256) float g_imp_part[BATCH*HEADS*64*WBLK];
__device__ int g_idx[BATCH*HEADS*SELK];
__device__ int g_msk[BATCH*HEADS*SELK];

// fp16 hi/lo split operands
__device__ __align__(256) __half b_inp_h[ROWS*DIM],  b_inp_l[ROWS*DIM];
__device__ __align__(256) __half b_wq_h[DIM*DIM],    b_wq_l[DIM*DIM];
__device__ __align__(256) __half b_wk_h[DIM*DIM],    b_wk_l[DIM*DIM];
__device__ __align__(256) __half b_wv_h[DIM*DIM],    b_wv_l[DIM*DIM];
__device__ __align__(256) __half b_kw1_h[HIDC*HIDC], b_kw1_l[HIDC*HIDC];
__device__ __align__(256) __half b_vw1_h[HIDC*HIDC], b_vw1_l[HIDC*HIDC];
__device__ __align__(256) __half b_kw2_h[DHEAD*HIDC],b_kw2_l[DHEAD*HIDC];
__device__ __align__(256) __half b_vw2_h[DHEAD*HIDC],b_vw2_l[DHEAD*HIDC];
__device__ __align__(256) __half b_wo_h[DIM*DIM],    b_wo_l[DIM*DIM];
__device__ __align__(256) __half b_kc_h[QKVN],       b_kc_l[QKVN];
__device__ __align__(256) __half b_vc_h[QKVN],       b_vc_l[QKVN];
__device__ __align__(256) __half b_h1k_h[HIDC*HIDC], b_h1k_l[HIDC*HIDC];
__device__ __align__(256) __half b_h1v_h[HIDC*HIDC], b_h1v_l[HIDC*HIDC];
__device__ __align__(256) __half b_op_h[ROWS*DIM],   b_op_l[ROWS*DIM];

// ------------------------- helpers ------------------------------------------
__device__ __forceinline__ uint32_t smem_u32(const void* p){
    uint32_t a;
    asm("{ .reg .u64 t; cvta.to.shared.u64 t, %1; cvt.u32.u64 %0, t; }" : "=r"(a) : "l"(p));
    return a;
}
__device__ __forceinline__ void cp16(uint32_t saddr, const void* gaddr){
    asm volatile("cp.async.cg.shared.global [%0], [%1], 16;" :: "r"(saddr), "l"(gaddr));
}
__device__ __forceinline__ void mma_f32(float* c, const uint32_t* a, const uint32_t* b){
    asm volatile("mma.sync.aligned.m16n8k16.row.col.f32.f16.f16.f32 "
        "{%0,%1,%2,%3}, {%4,%5,%6,%7}, {%8,%9}, {%0,%1,%2,%3};"
        : "+f"(c[0]), "+f"(c[1]), "+f"(c[2]), "+f"(c[3])
        : "r"(a[0]), "r"(a[1]), "r"(a[2]), "r"(a[3]), "r"(b[0]), "r"(b[1]));
}
__device__ __forceinline__ void mma_f16(uint32_t* c, const uint32_t* a, const uint32_t* b){
    asm volatile("mma.sync.aligned.m16n8k16.row.col.f16.f16.f16.f16 "
        "{%0,%1}, {%2,%3,%4,%5}, {%6,%7}, {%0,%1};"
        : "+r"(c[0]), "+r"(c[1])
        : "r"(a[0]), "r"(a[1]), "r"(a[2]), "r"(a[3]), "r"(b[0]), "r"(b[1]));
}
__device__ __forceinline__ void ldsm4(uint32_t* r, uint32_t addr){
    asm volatile("ldmatrix.sync.aligned.m8n8.x4.shared.b16 {%0,%1,%2,%3}, [%4];"
        : "=r"(r[0]), "=r"(r[1]), "=r"(r[2]), "=r"(r[3]) : "r"(addr));
}
__device__ __forceinline__ void ldsm4t(uint32_t* r, uint32_t addr){
    asm volatile("ldmatrix.sync.aligned.m8n8.x4.trans.shared.b16 {%0,%1,%2,%3}, [%4];"
        : "=r"(r[0]), "=r"(r[1]), "=r"(r[2]), "=r"(r[3]) : "r"(addr));
}
__device__ __forceinline__ void hsplit(float v, __half& h, __half& l){
    h = __float2half_rn(v);
    l = __float2half_rn(v - __half2float(h));
}

// ------------------------- split-fp16 tensor-core GEMM ----------------------
// Terms (TRM=2): Ah*Bh(f32) + Ah*Bl(f16)   [= Ah * B_exact; A-side fp16 hi]
// EPI: 0 none, 1 +bias, 2 +bias+relu.
// PERM: 0 rowmajor (OUTB 0 fp32 / 1 fp16 split), 1 q+rope, 2 memshift,
//       3 k: rope->X1 +pos split->Ch/Cl, 4 v: raw->C +pos split->Ch/Cl.
#define KCH   64
#define ASTR  72
#define TELEM (128*ASTR)
#define STAGEE (4*TELEM)
#define GSMEM (2*STAGEE*2)             // 147456 bytes

template<int EPI, int PERM, int OUTB, int DUAL, int TRM>
__global__ void __launch_bounds__(256, 1) tgemm_k(
    const __half* __restrict__ Ah, const __half* __restrict__ Al,
    const __half* __restrict__ Bh, const __half* __restrict__ Bl,
    const float* __restrict__ bias, float* __restrict__ C,
    __half* __restrict__ Ch, __half* __restrict__ Cl,
    float* __restrict__ X1, const float* __restrict__ pos,
    const __half* __restrict__ A2h, const __half* __restrict__ A2l,
    const __half* __restrict__ B2h, const __half* __restrict__ B2l,
    const float* __restrict__ bias2, float* __restrict__ C2,
    __half* __restrict__ Ch2, __half* __restrict__ Cl2,
    int M, int Nn, int K)
{
    extern __shared__ __half sm[];
    const uint32_t sb = smem_u32(sm);
    int tid = threadIdx.x;
    int warp = tid >> 5, lane = tid & 31;
    int wm = warp & 1, wn = warp >> 1;          // 2 x 4 warps, warp tile 64x32
    int grp = lane >> 2, tig = lane & 3;
    int bx = blockIdx.x, by = blockIdx.y;

    const __half* Au = Ah; const __half* Aul = Al;
    const __half* Bu = Bh; const __half* Bul = Bl;
    const float* bu = bias; float* Cu = C;
    __half* Chu = Ch; __half* Clu = Cl;
    if (DUAL) {
        int half_ = gridDim.y >> 1;
        if (by >= half_) {
            Au = A2h; Aul = A2l; Bu = B2h; Bul = B2l;
            bu = bias2; Cu = C2; Chu = Ch2; Clu = Cl2;
            by -= half_;
        }
    }
    const int terms = TRM;

    const __half* Agh = Au  + (size_t)by * 128 * K;
    const __half* Agl = Aul + (size_t)by * 128 * K;
    const __half* Bgh = Bu  + (size_t)bx * 128 * K;
    const __half* Bgl = Bul + (size_t)bx * 128 * K;

    float acc[4][4][4];
    uint32_t acc16[4][4][2];
#pragma unroll
    for (int i = 0; i < 4; i++)
#pragma unroll
        for (int j = 0; j < 4; j++) {
#pragma unroll
            for (int r = 0; r < 4; r++) acc[i][j][r] = 0.f;
            acc16[i][j][0] = 0u; acc16[i][j][1] = 0u;
        }

    int NC = K / KCH;

    auto load_stage = [&](int c, int s) {
        int k0 = c * KCH;
        uint32_t sbase = sb + s * STAGEE * 2;
#pragma unroll
        for (int i = 0; i < 4; i++) {
            int idx = tid + i * 256;
            int row = idx >> 3, kc = (idx & 7) * 8;
            uint32_t so = sbase + (uint32_t)(row * ASTR + kc) * 2;
            size_t go = (size_t)row * K + k0 + kc;
            cp16(so,                 Agh + go);
            if (terms == 3) cp16(so + TELEM * 2, Agl + go);
            cp16(so + 2 * TELEM * 2, Bgh + go);
            cp16(so + 3 * TELEM * 2, Bgl + go);
        }
    };

    load_stage(0, 0);
    asm volatile("cp.async.commit_group;");

    int a_r  = lane & 15;
    int a_k8 = (lane >> 4) * 8;
    int b_l  = lane & 7;
    int b_seg = lane >> 3;
    int b_r  = (b_seg >= 2) ? b_l + 8 : b_l;
    int b_k8 = (b_seg & 1) * 8;

    for (int c = 0; c < NC; c++) {
        if (c + 1 < NC) {
            load_stage(c + 1, (c + 1) & 1);
            asm volatile("cp.async.commit_group;");
            asm volatile("cp.async.wait_group 1;");
        } else {
            asm volatile("cp.async.wait_group 0;");
        }
        __syncthreads();

        uint32_t sA  = sb + (c & 1) * STAGEE * 2;
        uint32_t sAl = sA + TELEM * 2;
        uint32_t sBh = sA + 2 * TELEM * 2;
        uint32_t sBl = sA + 3 * TELEM * 2;

#pragma unroll
        for (int ks = 0; ks < KCH / 16; ks++) {
            int kbase = ks * 16;
            uint32_t ah[4][4], al[4][4], bh[2][4], bl[2][4];
#pragma unroll
            for (int mt = 0; mt < 4; mt++) {
                uint32_t off = (uint32_t)((wm * 64 + mt * 16 + a_r) * ASTR + kbase + a_k8) * 2;
                ldsm4(ah[mt], sA  + off);
                if (terms == 3) ldsm4(al[mt], sAl + off);
            }
#pragma unroll
            for (int np = 0; np < 2; np++) {
                uint32_t off = (uint32_t)((wn * 32 + np * 16 + b_r) * ASTR + kbase + b_k8) * 2;
                ldsm4(bh[np], sBh + off);
                ldsm4(bl[np], sBl + off);
            }
#pragma unroll
            for (int mt = 0; mt < 4; mt++)
#pragma unroll
                for (int nt = 0; nt < 4; nt++) {
                    const uint32_t* bhp = &bh[nt >> 1][(nt & 1) * 2];
                    const uint32_t* blp = &bl[nt >> 1][(nt & 1) * 2];
                    mma_f32(acc[mt][nt], ah[mt], bhp);
                    mma_f16(acc16[mt][nt], ah[mt], blp);
                    if (terms == 3) mma_f16(acc16[mt][nt], al[mt], bhp);
                }
        }
        __syncthreads();
    }

    // epilogue (merge f16 correction accumulators)
#pragma unroll
    for (int mt = 0; mt < 4; mt++)
#pragma unroll
        for (int h8 = 0; h8 < 2; h8++) {
            int rowg = by * 128 + wm * 64 + mt * 16 + grp + h8 * 8;
#pragma unroll
            for (int nt = 0; nt < 4; nt++) {
                int colg = bx * 128 + wn * 32 + nt * 8 + tig * 2;
                __half2 hc = *(__half2*)&acc16[mt][nt][h8];
                float v0 = acc[mt][nt][h8 * 2 + 0] + __low2float(hc);
                float v1 = acc[mt][nt][h8 * 2 + 1] + __high2float(hc);
                if (EPI >= 1) { v0 += bu[colg]; v1 += bu[colg + 1]; }
                if (EPI == 2) { v0 = fmaxf(v0, 0.f); v1 = fmaxf(v1, 0.f); }
                if (PERM == 0) {
                    size_t rb = (size_t)rowg * Nn + colg;
                    if (OUTB) {
                        __half2 H, L;
                        hsplit(v0, H.x, L.x); hsplit(v1, H.y, L.y);
                        *(__half2*)(Chu + rb) = H;
                        *(__half2*)(Clu + rb) = L;
                    } else {
                        float2 p; p.x = v0; p.y = v1;
                        *(float2*)(Cu + rb) = p;
                    }
                } else if (PERM == 2) {
                    size_t rb = (size_t)(rowg + (rowg >> 7) + 1) * Nn + colg;
                    float2 p; p.x = v0; p.y = v1;
                    *(float2*)(Cu + rb) = p;
                } else {
                    int b = rowg >> 12, n = rowg & 4095;
                    int h = colg >> 7, d = colg & 127;
                    size_t dst = (((size_t)((b * HEADS + h) * SEQ + n)) << 7) + d;
                    if (PERM == 1 || PERM == 3) {
                        float inv = (float)exp(-(double)d * (9.210340371976184 / 128.0));
                        float t = (float)n * inv;
                        float s, cc; sincosf(t, &s, &cc);
                        float r0 = v0 * cc - v1 * s;
                        float r1 = v0 * s + v1 * cc;
                        float2 rp; rp.x = r0; rp.y = r1;
                        *(float2*)(X1 + dst) = rp;
                    }
                    if (PERM == 1 || PERM == 4) {
                        float2 p; p.x = v0; p.y = v1;
                        *(float2*)(Cu + dst) = p;
                    }
                    if (PERM == 3 || PERM == 4) {
                        const float* pp = pos + h * 4096 + (n & 31) * 128 + d;
                        __half2 H, L;
                        hsplit(v0 + pp[0], H.x, L.x);
                        hsplit(v1 + pp[1], H.y, L.y);
                        *(__half2*)(Chu + dst) = H;
                        *(__half2*)(Clu + dst) = L;
                    }
                }
            }
        }
}

// ------------------------- fp32 -> hi/lo fp16 convert ------------------------
__global__ void cvt_k(const float4* __restrict__ x, __half2* __restrict__ hi,
                      __half2* __restrict__ lo, int n4)
{
    int i = blockIdx.x * 256 + threadIdx.x;
    if (i >= n4) return;
    float4 v = x[i];
    __half2 H0, H1, L0, L1;
    hsplit(v.x, H0.x, L0.x); hsplit(v.y, H0.y, L0.y);
    hsplit(v.z, H1.x, L1.x); hsplit(v.w, H1.y, L1.y);
    hi[i * 2] = H0; hi[i * 2 + 1] = H1;
    lo[i * 2] = L0; lo[i * 2 + 1] = L1;
}

// transpose-convert: W[K,N] fp32 -> Wt hi/lo [N,K] fp16
__global__ void cvtT_k(const float* __restrict__ x, __half* __restrict__ hi,
                       __half* __restrict__ lo, int K, int N)
{
    __shared__ float t[32][33];
    int bx = blockIdx.x, by = blockIdx.y;
    int tx = threadIdx.x & 31, ty = threadIdx.x >> 5;
#pragma unroll
    for (int i = 0; i < 32; i += 8) {
        int kk = by * 32 + ty + i;
        t[ty + i][tx] = x[(size_t)kk * N + bx * 32 + tx];
    }
    __syncthreads();
#pragma unroll
    for (int i = 0; i < 32; i += 8) {
        int n = bx * 32 + ty + i;
        int kk = by * 32 + tx;
        float v = t[tx][ty + i];
        __half h, l; hsplit(v, h, l);
        hi[(size_t)n * K + kk] = h;
        lo[(size_t)n * K + kk] = l;
    }
}

// ------------------------- fused rmsnorm + gates ----------------------------
__global__ void gates_k(const float* __restrict__ inp, const float* __restrict__ g,
                        const float* __restrict__ Wg, const float* __restrict__ bg,
                        float* __restrict__ gates)
{
    __shared__ float xs[DIM];
    __shared__ float red[8];
    int row = blockIdx.x;
    int tid = threadIdx.x;
    const float* ip = inp + (size_t)row * DIM;
    float ss = 0.f;
    for (int k = tid; k < DIM; k += 256) { float v = ip[k]; xs[k] = v; ss += v * v; }
#pragma unroll
    for (int o = 16; o > 0; o >>= 1) ss += __shfl_xor_sync(~0u, ss, o);
    if ((tid & 31) == 0) red[tid >> 5] = ss;
    __syncthreads();
    float tot = red[0] + red[1] + red[2] + red[3] + red[4] + red[5] + red[6] + red[7];
    float rn = 1.0f / sqrtf(tot * (1.0f / DIM) + EPSV);
    int lane = tid & 31, warp = tid >> 5;
    for (int c = warp; c < 2 * HEADS; c += 8) {
        float acc = 0.f;
        for (int k = lane; k < DIM; k += 32) acc += xs[k] * g[k] * Wg[(size_t)k * (2 * HEADS) + c];
#pragma unroll
        for (int o = 16; o > 0; o >>= 1) acc += __shfl_xor_sync(~0u, acc, o);
        if (lane == 0) gates[(size_t)row * (2 * HEADS) + c] = 1.f / (1.f + expf(-(acc * rn + bg[c])));
    }
}

// ------------------------- mem slots into ckf/cvf ---------------------------
__global__ void fillmem_k(const float* __restrict__ memkv,
                          float* __restrict__ ckf, float* __restrict__ cvf)
{
    int idx = blockIdx.x * 256 + threadIdx.x;
    if (idx >= BATCH * HEADS * DHEAD) return;
    int d = idx & 127; int h = (idx >> 7) & 15; int b = idx >> 11;
    size_t dst = (((size_t)((b * HEADS + h) * CM)) << 7) + d;
    ckf[dst] = memkv[h * 128 + d];
    cvf[dst] = memkv[HEADS * 128 + h * 128 + d];
}

// ------------------------- compressed attention -----------------------------
__global__ void __launch_bounds__(256) attn_c_k(
    const float* __restrict__ q, const float* __restrict__ ckf,
    const float* __restrict__ cvf, float* __restrict__ cout,
    float* __restrict__ imp_part)
{
    extern __shared__ float smf[];
    float* qs   = smf;
    float* sims = smf + 64 * 128;
    float* cs   = sims + 64 * 132;
    int tid = threadIdx.x;
    int bh = blockIdx.y, n0 = blockIdx.x * 64;
    const float* qb = q + (((size_t)bh * SEQ + n0) << 7);
#pragma unroll
    for (int i = 0; i < 8; i++) {
        int vdx = tid + i * 256;
        int row = vdx >> 5, c4 = (vdx & 31) * 4;
        *(float4*)&qs[row * 128 + c4] = *(const float4*)(qb + row * 128 + c4);
    }
    int tx = tid & 15, ty = tid >> 4;

    for (int m0 = 0; m0 < CM; m0 += 32) {
        int mc = (CM - m0 < 32) ? (CM - m0) : 32;
        for (int vdx = tid; vdx < mc * 32; vdx += 256) {
            int rr = vdx >> 5, c4 = (vdx & 31) * 4;
            float4 t = *(const float4*)(ckf + (((size_t)bh * CM + m0 + rr) << 7) + c4);
            cs[rr * 132 + c4 + 0] = t.x; cs[rr * 132 + c4 + 1] = t.y;
            cs[rr * 132 + c4 + 2] = t.z; cs[rr * 132 + c4 + 3] = t.w;
        }
        __syncthreads();
        float a0[2] = {0, 0}, a1[2] = {0, 0}, a2[2] = {0, 0}, a3[2] = {0, 0};
#pragma unroll 4
        for (int k = 0; k < 128; k++) {
            float q0 = qs[(ty * 4 + 0) * 128 + k];
            float q1 = qs[(ty * 4 + 1) * 128 + k];
            float q2 = qs[(ty * 4 + 2) * 128 + k];
            float q3 = qs[(ty * 4 + 3) * 128 + k];
            float c0 = cs[(tx * 2 + 0) * 132 + k];
            float c1 = cs[(tx * 2 + 1) * 132 + k];
            a0[0] += q0 * c0; a0[1] += q0 * c1;
            a1[0] += q1 * c0; a1[1] += q1 * c1;
            a2[0] += q2 * c0; a2[1] += q2 * c1;
            a3[0] += q3 * c0; a3[1] += q3 * c1;
        }
#pragma unroll
        for (int mm = 0; mm < 2; mm++) {
            int m = tx * 2 + mm;
            if (m < mc) {
                sims[(ty * 4 + 0) * 132 + m0 + m] = a0[mm] * SCALEV;
                sims[(ty * 4 + 1) * 132 + m0 + m] = a1[mm] * SCALEV;
                sims[(ty * 4 + 2) * 132 + m0 + m] = a2[mm] * SCALEV;
                sims[(ty * 4 + 3) * 132 + m0 + m] = a3[mm] * SCALEV;
            }
        }
        __syncthreads();
    }

    {
        int lane = tid & 31, wrp = tid >> 5;
        for (int r = wrp; r < 64; r += 8) {
            float* srow = sims + r * 132;
            float mx = -1e38f;
            for (int m = lane; m < CM; m += 32) mx = fmaxf(mx, srow[m]);
#pragma unroll
            for (int o = 16; o > 0; o >>= 1) mx = fmaxf(mx, __shfl_xor_sync(~0u, mx, o));
            float sum = 0.f;
            for (int m = lane; m < CM; m += 32) { float e = expf(srow[m] - mx); srow[m] = e; sum += e; }
#pragma unroll
            for (int o = 16; o > 0; o >>= 1) sum += __shfl_xor_sync(~0u, sum, o);
            float inv = 1.f / sum;
            for (int m = lane; m < CM; m += 32) srow[m] *= inv;
        }
    }
    __syncthreads();
    if (tid < 128) {
        float s = 0.f;
        for (int r = 0; r < 64; r++) s += sims[r * 132 + 1 + tid];
        imp_part[(((size_t)bh * 64) + blockIdx.x) * 128 + tid] = s;
    }
    __syncthreads();

    float oacc[4][8];
#pragma unroll
    for (int i = 0; i < 4; i++)
#pragma unroll
        for (int j = 0; j < 8; j++) oacc[i][j] = 0.f;

    for (int m0 = 0; m0 < CM; m0 += 32) {
        int mc = (CM - m0 < 32) ? (CM - m0) : 32;
        for (int vdx = tid; vdx < mc * 32; vdx += 256) {
            int rr = vdx >> 5, c4 = (vdx & 31) * 4;
            float4 t = *(const float4*)(cvf + (((size_t)bh * CM + m0 + rr) << 7) + c4);
            cs[rr * 132 + c4 + 0] = t.x; cs[rr * 132 + c4 + 1] = t.y;
            cs[rr * 132 + c4 + 2] = t.z; cs[rr * 132 + c4 + 3] = t.w;
        }
        __syncthreads();
        for (int mm = 0; mm < mc; mm++) {
            float p0 = sims[(ty * 4 + 0) * 132 + m0 + mm];
            float p1 = sims[(ty * 4 + 1) * 132 + m0 + mm];
            float p2 = sims[(ty * 4 + 2) * 132 + m0 + mm];
            float p3 = sims[(ty * 4 + 3) * 132 + m0 + mm];
            float bv[8];
            *(float4*)&bv[0] = *(float4*)&cs[mm * 132 + tx * 8];
            *(float4*)&bv[4] = *(float4*)&cs[mm * 132 + tx * 8 + 4];
#pragma unroll
            for (int j = 0; j < 8; j++) {
                oacc[0][j] += p0 * bv[j];
                oacc[1][j] += p1 * bv[j];
                oacc[2][j] += p2 * bv[j];
                oacc[3][j] += p3 * bv[j];
            }
        }
        __syncthreads();
    }
#pragma unroll
    for (int rr = 0; rr < 4; rr++) {
        size_t dst = (((size_t)bh * SEQ) + n0 + ty * 4 + rr) * 128 + tx * 8;
        *(float4*)&cout[dst]     = *(float4*)&oacc[rr][0];
        *(float4*)&cout[dst + 4] = *(float4*)&oacc[rr][4];
    }
}

// ------------------------- importance reduce + top-k ------------------------
__global__ void topk_k(const float* __restrict__ imp_part,
                       int* __restrict__ idxout, int* __restrict__ maskout)
{
    __shared__ float vals[WBLK];
    int bh = blockIdx.x, tid = threadIdx.x;
    float s = 0.f;
    for (int t = 0; t < 64; t++) s += imp_part[(((size_t)bh * 64) + t) * 128 + tid];
    vals[tid] = s * (1.0f / SEQ);
    __syncthreads();
    if (tid == 0) {
        for (int sel = 0; sel < SELK; sel++) {
            float best = -1e38f; int bi = 0;
            for (int m = 0; m < WBLK; m++)
                if (vals[m] > best) { best = vals[m]; bi = m; }
            idxout[bh * SELK + sel] = bi;
            maskout[bh * SELK + sel] = (best > 1e-10f) ? 1 : 0;
            vals[bi] = -1e38f;
        }
    }
}

// ------------- selected (fine) attention: HMMA + fused gather ---------------
// 256 thr, 8 warps; CTA = 32 q-rows. S via 2-term (qh+ql)*k_fp16; P*V fp16.
#define QSTR 136
#define PSTR 520
#define SMEM_F2 ((3*32*QSTR)*2 + 32*516*4 + 32*PSTR*2)

__global__ void __launch_bounds__(256) attn_f_k(
    const float* __restrict__ qr, const float* __restrict__ kr,
    const float* __restrict__ v, const int* __restrict__ idxs,
    const int* __restrict__ fmask, float* __restrict__ fout)
{
    extern __shared__ char smc[];
    __half* qh  = (__half*)smc;                       // 32 x QSTR
    __half* ql  = qh + 32 * QSTR;
    __half* kvh = ql + 32 * QSTR;
    float*  sims = (float*)(kvh + 32 * QSTR);         // 32 x 516
    __half* ph  = (__half*)(sims + 32 * 516);         // 32 x PSTR
    __shared__ int maskS[SELK];
    __shared__ int blkS[SELK];
    int tid = threadIdx.x, w = tid >> 5, lane = tid & 31;
    int grp = lane >> 2, tig = lane & 3;
    int bh = blockIdx.y, n0 = blockIdx.x * 32;
    if (tid < SELK) {
        maskS[tid] = fmask[bh * SELK + tid];
        blkS[tid]  = idxs[bh * SELK + tid];
    }
    // load q -> fp16 hi/lo
    const float* qb = qr + (((size_t)bh * SEQ + n0) << 7);
    for (int i = tid; i < 32 * 32; i += 256) {
        int r = i >> 5, c4 = (i & 31) * 4;
        float4 t = *(const float4*)(qb + r * 128 + c4);
        __half2 H0, H1, L0, L1;
        hsplit(t.x, H0.x, L0.x); hsplit(t.y, H0.y, L0.y);
        hsplit(t.z, H1.x, L1.x); hsplit(t.w, H1.y, L1.y);
        *(__half2*)&qh[r * QSTR + c4]     = H0;
        *(__half2*)&qh[r * QSTR + c4 + 2] = H1;
        *(__half2*)&ql[r * QSTR + c4]     = L0;
        *(__half2*)&ql[r * QSTR + c4 + 2] = L1;
    }
    __syncthreads();

    uint32_t sqh = smem_u32(qh), sql = smem_u32(ql), skv = smem_u32(kvh), sph = smem_u32(ph);
    int mt = w & 1;                      // S/O row half
    int nt = w >> 1;                     // S: key n-tile (0-3)
    int a_r = lane & 15, a_k8 = (lane >> 4) * 8;
    // b addr (phase1): 8 key rows of this warp's n-tile, 4 k-offsets
    int b_key = nt * 8 + (lane & 7);
    int b_k8  = (lane >> 3) * 8;         // 0,8,16,24

    // ---- phase 1: S = q . k^T per selected block ----
    for (int b = 0; b < SELK; b++) {
        int blk = blkS[b];
        const float* kb = kr + (((size_t)bh * SEQ + blk * BLKSZ) << 7);
        for (int i = tid; i < 32 * 32; i += 256) {
            int r = i >> 5, c4 = (i & 31) * 4;
            float4 t = *(const float4*)(kb + r * 128 + c4);
            *(__half2*)&kvh[r * QSTR + c4]     = __floats2half2_rn(t.x, t.y);
            *(__half2*)&kvh[r * QSTR + c4 + 2] = __floats2half2_rn(t.z, t.w);
        }
        __syncthreads();
        float c[4] = {0.f, 0.f, 0.f, 0.f};
#pragma unroll
        for (int ks2 = 0; ks2 < 4; ks2++) {
            uint32_t bf[4];
            ldsm4(bf, skv + (uint32_t)(b_key * QSTR + ks2 * 32 + b_k8) * 2);
#pragma unroll
            for (int sub = 0; sub < 2; sub++) {
                int kb16 = ks2 * 32 + sub * 16;
                uint32_t ah[4], al[4];
                uint32_t aoff = (uint32_t)((mt * 16 + a_r) * QSTR + kb16 + a_k8) * 2;
                ldsm4(ah, sqh + aoff);
                ldsm4(al, sql + aoff);
                mma_f32(c, ah, &bf[sub * 2]);
                mma_f32(c, al, &bf[sub * 2]);
            }
        }
        int srow0 = mt * 16 + grp;
        int scol  = b * 32 + nt * 8 + tig * 2;
        sims[srow0 * 516 + scol]       = c[0] * SCALEV;
        sims[srow0 * 516 + scol + 1]   = c[1] * SCALEV;
        sims[(srow0 + 8) * 516 + scol]     = c[2] * SCALEV;
        sims[(srow0 + 8) * 516 + scol + 1] = c[3] * SCALEV;
        __syncthreads();
    }

    // ---- phase 2: softmax (fp32) + write P as fp16 ----
    {
        int wrp = w;
        for (int r = wrp; r < 32; r += 8) {
            float* srow = sims + r * 516;
            __half* prow = ph + r * PSTR;
            float mx = -1e38f;
            for (int m = lane; m < 512; m += 32) {
                float vv = srow[m];
                if (!maskS[m >> 5]) vv = NEGV;
                srow[m] = vv;
                mx = fmaxf(mx, vv);
            }
#pragma unroll
            for (int o = 16; o > 0; o >>= 1) mx = fmaxf(mx, __shfl_xor_sync(~0u, mx, o));
            float sum = 0.f;
            for (int m = lane; m < 512; m += 32) { float e = expf(srow[m] - mx); srow[m] = e; sum += e; }
#pragma unroll
            for (int o = 16; o > 0; o >>= 1) sum += __shfl_xor_sync(~0u, sum, o);
            float inv = 1.f / sum;
            for (int m = lane; m < 512; m += 32) prow[m] = __float2half_rn(srow[m] * inv);
        }
    }
    __syncthreads();

    // ---- phase 3: O = P . V ----
    int dg = w >> 1;                     // d-group 0-3 (32 dims each)
    // b addr (phase3, trans): key rows, d cols
    int t_key = (lane & 7) + ((lane >> 3) & 1) * 8;   // 0..15 pattern
    int t_d8  = (lane >> 4) * 8;
    float oacc[4][4];
#pragma unroll
    for (int i = 0; i < 4; i++)
#pragma unroll
        for (int j = 0; j < 4; j++) oacc[i][j] = 0.f;

    for (int b = 0; b < SELK; b++) {
        int blk = blkS[b];
        const float* vb = v + (((size_t)bh * SEQ + blk * BLKSZ) << 7);
        for (int i = tid; i < 32 * 32; i += 256) {
            int r = i >> 5, c4 = (i & 31) * 4;
            float4 t = *(const float4*)(vb + r * 128 + c4);
            *(__half2*)&kvh[r * QSTR + c4]     = __floats2half2_rn(t.x, t.y);
            *(__half2*)&kvh[r * QSTR + c4 + 2] = __floats2half2_rn(t.z, t.w);
        }
        __syncthreads();
#pragma unroll
        for (int s = 0; s < 2; s++) {    // 2 ksteps of 16 keys
            uint32_t af[4];
            ldsm4(af, sph + (uint32_t)((mt * 16 + a_r) * PSTR + b * 32 + s * 16 + a_k8) * 2);
#pragma unroll
            for (int p = 0; p < 2; p++) {  // 2 d-pairs (16 dims each)
                uint32_t bf[4];
                uint32_t boff = (uint32_t)((s * 16 + t_key) * QSTR + dg * 32 + p * 16 + t_d8) * 2;
                ldsm4t(bf, skv + boff);
                mma_f32(oacc[p * 2 + 0], af, &bf[0]);
                mma_f32(oacc[p * 2 + 1], af, &bf[2]);
            }
        }
        __syncthreads();
    }

    // write O
#pragma unroll
    for (int p = 0; p < 2; p++)
#pragma unroll
        for (int t = 0; t < 2; t++) {
            float* c = oacc[p * 2 + t];
            int d0 = dg * 32 + p * 16 + t * 8 + tig * 2;
            size_t r0 = (((size_t)bh * SEQ) + n0 + mt * 16 + grp) * 128 + d0;
            size_t r1 = r0 + 8 * 128;
            float2 v0; v0.x = c[0]; v0.y = c[1];
            float2 v1; v1.x = c[2]; v1.y = c[3];
            *(float2*)(fout + r0) = v0;
            *(float2*)(fout + r1) = v1;
        }
}

// ------------------------- combine gates -> fp16 hi/lo ----------------------
__global__ void combine2_k(const float* __restrict__ cout, const float* __restrict__ fout,
                           const float* __restrict__ gates,
                           __half* __restrict__ oh, __half* __restrict__ ol)
{
    int idx = blockIdx.x * 256 + threadIdx.x;
    int d = idx & 127; int h = (idx >> 7) & 15; int nrow = idx >> 11;
    int b = nrow >> 12; int n = nrow & 4095;
    size_t src = (((size_t)(b * HEADS + h) * SEQ) + n) * 128 + d;
    float g0 = gates[(size_t)nrow * (2 * HEADS) + 2 * h];
    float g1 = gates[(size_t)nrow * (2 * HEADS) + 2 * h + 1];
    float v = g0 * cout[src] + g1 * fout[src];
    __half hh, ll; hsplit(v, hh, ll);
    oh[idx] = hh; ol[idx] = ll;
}

// ------------------------- launch ------------------------------------------
extern "C" void kernel_launch(void* const* d_in, const int* in_sizes, int n_in,
                              void* d_out, int out_size)
{
    const float* inp  = (const float*)d_in[0];
    const float* g    = (const float*)d_in[1];
    const float* Wq   = (const float*)d_in[2];
    const float* Wk   = (const float*)d_in[3];
    const float* Wv   = (const float*)d_in[4];
    const float* kpos = (const float*)d_in[5];
    const float* vpos = (const float*)d_in[6];
    const float* memkv= (const float*)d_in[7];
    const float* kW1  = (const float*)d_in[8];
    const float* kb1  = (const float*)d_in[9];
    const float* kW2  = (const float*)d_in[10];
    const float* kb2  = (const float*)d_in[11];
    const float* vW1  = (const float*)d_in[12];
    const float* vb1  = (const float*)d_in[13];
    const float* vW2  = (const float*)d_in[14];
    const float* vb2  = (const float*)d_in[15];
    const float* Wg   = (const float*)d_in[16];
    const float* bg   = (const float*)d_in[17];
    const float* Wo   = (const float*)d_in[18];
    float* out = (float*)d_out;

    float *q, *qr, *kr, *v, *ckf, *cvf, *cout, *fout, *gates, *imp;
    int *idxs, *msk;
    cudaGetSymbolAddress((void**)&q,    g_q);
    cudaGetSymbolAddress((void**)&qr,   g_qr);
    cudaGetSymbolAddress((void**)&kr,   g_kr);
    cudaGetSymbolAddress((void**)&v,    g_v);
    cudaGetSymbolAddress((void**)&ckf,  g_ckf);
    cudaGetSymbolAddress((void**)&cvf,  g_cvf);
    cudaGetSymbolAddress((void**)&cout, g_cout);
    cudaGetSymbolAddress((void**)&fout, g_fout);
    cudaGetSymbolAddress((void**)&gates,g_gates);
    cudaGetSymbolAddress((void**)&imp,  g_imp_part);
    cudaGetSymbolAddress((void**)&idxs, g_idx);
    cudaGetSymbolAddress((void**)&msk,  g_msk);

    __half *inph,*inpl,*wqh,*wql,*wkh,*wkl,*wvh,*wvl,*kw1h,*kw1l,*vw1h,*vw1l;
    __half *kw2h,*kw2l,*vw2h,*vw2l,*woh,*wol,*kch,*kcl,*vch,*vcl;
    __half *h1kh,*h1kl,*h1vh,*h1vl,*oph,*opl;
    cudaGetSymbolAddress((void**)&inph, b_inp_h); cudaGetSymbolAddress((void**)&inpl, b_inp_l);
    cudaGetSymbolAddress((void**)&wqh,  b_wq_h);  cudaGetSymbolAddress((void**)&wql,  b_wq_l);
    cudaGetSymbolAddress((void**)&wkh,  b_wk_h);  cudaGetSymbolAddress((void**)&wkl,  b_wk_l);
    cudaGetSymbolAddress((void**)&wvh,  b_wv_h);  cudaGetSymbolAddress((void**)&wvl,  b_wv_l);
    cudaGetSymbolAddress((void**)&kw1h, b_kw1_h); cudaGetSymbolAddress((void**)&kw1l, b_kw1_l);
    cudaGetSymbolAddress((void**)&vw1h, b_vw1_h); cudaGetSymbolAddress((void**)&vw1l, b_vw1_l);
    cudaGetSymbolAddress((void**)&kw2h, b_kw2_h); cudaGetSymbolAddress((void**)&kw2l, b_kw2_l);
    cudaGetSymbolAddress((void**)&vw2h, b_vw2_h); cudaGetSymbolAddress((void**)&vw2l, b_vw2_l);
    cudaGetSymbolAddress((void**)&woh,  b_wo_h);  cudaGetSymbolAddress((void**)&wol,  b_wo_l);
    cudaGetSymbolAddress((void**)&kch,  b_kc_h);  cudaGetSymbolAddress((void**)&kcl,  b_kc_l);
    cudaGetSymbolAddress((void**)&vch,  b_vc_h);  cudaGetSymbolAddress((void**)&vcl,  b_vc_l);
    cudaGetSymbolAddress((void**)&h1kh, b_h1k_h); cudaGetSymbolAddress((void**)&h1kl, b_h1k_l);
    cudaGetSymbolAddress((void**)&h1vh, b_h1v_h); cudaGetSymbolAddress((void**)&h1vl, b_h1v_l);
    cudaGetSymbolAddress((void**)&oph,  b_op_h);  cudaGetSymbolAddress((void**)&opl,  b_op_l);

    const int SMEM_C = (64 * 128 + 64 * 132 + 32 * 132) * 4;
    cudaFuncSetAttribute(attn_c_k, cudaFuncAttributeMaxDynamicSharedMemorySize, SMEM_C);
    cudaFuncSetAttribute(attn_f_k, cudaFuncAttributeMaxDynamicSharedMemorySize, SMEM_F2);
    cudaFuncSetAttribute(tgemm_k<0,1,0,0,2>, cudaFuncAttributeMaxDynamicSharedMemorySize, GSMEM);
    cudaFuncSetAttribute(tgemm_k<0,3,0,0,2>, cudaFuncAttributeMaxDynamicSharedMemorySize, GSMEM);
    cudaFuncSetAttribute(tgemm_k<0,4,0,0,2>, cudaFuncAttributeMaxDynamicSharedMemorySize, GSMEM);
    cudaFuncSetAttribute(tgemm_k<2,0,1,1,2>, cudaFuncAttributeMaxDynamicSharedMemorySize, GSMEM);
    cudaFuncSetAttribute(tgemm_k<1,2,0,1,2>, cudaFuncAttributeMaxDynamicSharedMemorySize, GSMEM);
    cudaFuncSetAttribute(tgemm_k<0,0,0,0,2>, cudaFuncAttributeMaxDynamicSharedMemorySize, GSMEM);

    // 0) converts
    cvt_k<<<(ROWS*DIM/4 + 255)/256, 256>>>((const float4*)inp, (__half2*)inph, (__half2*)inpl, ROWS*DIM/4);
    cvtT_k<<<dim3(DIM/32, DIM/32), 256>>>(Wq, wqh, wql, DIM, DIM);
    cvtT_k<<<dim3(DIM/32, DIM/32), 256>>>(Wk, wkh, wkl, DIM, DIM);
    cvtT_k<<<dim3(DIM/32, DIM/32), 256>>>(Wv, wvh, wvl, DIM, DIM);
    cvtT_k<<<dim3(HIDC/32, HIDC/32), 256>>>(kW1, kw1h, kw1l, HIDC, HIDC);

    // 1) QKV projections with fused RoPE / pos-pack epilogues
    dim3 gq(DIM/128, ROWS/128);
    tgemm_k<0,1,0,0,2><<<gq, 256, GSMEM>>>(inph, inpl, wqh, wql, nullptr, q, nullptr, nullptr,
        qr, nullptr, nullptr, nullptr, nullptr, nullptr, nullptr, nullptr, nullptr, nullptr,
        ROWS, DIM, DIM);
    tgemm_k<0,3,0,0,2><<<gq, 256, GSMEM>>>(inph, inpl, wkh, wkl, nullptr, nullptr, kch, kcl,
        kr, kpos, nullptr, nullptr, nullptr, nullptr, nullptr, nullptr, nullptr, nullptr,
        ROWS, DIM, DIM);
    tgemm_k<0,4,0,0,2><<<gq, 256, GSMEM>>>(inph, inpl, wvh, wvl, nullptr, v, vch, vcl,
        nullptr, vpos, nullptr, nullptr, nullptr, nullptr, nullptr, nullptr, nullptr, nullptr,
        ROWS, DIM, DIM);

    // remaining converts + gates (overlap with GEMM tails)
    cvtT_k<<<dim3(HIDC/32, HIDC/32), 256>>>(vW1, vw1h, vw1l, HIDC, HIDC);
    cvtT_k<<<dim3(DHEAD/32, HIDC/32), 256>>>(kW2, kw2h, kw2l, HIDC, DHEAD);
    cvtT_k<<<dim3(DHEAD/32, HIDC/32), 256>>>(vW2, vw2h, vw2l, HIDC, DHEAD);
    cvtT_k<<<dim3(DIM/32, DIM/32), 256>>>(Wo, woh, wol, DIM, DIM);
    gates_k<<<ROWS, 256>>>(inp, g, Wg, bg, gates);

    // 3) compress MLP layer 1 — k and v dual launch (both 2-term)
    tgemm_k<2,0,1,1,2><<<dim3(HIDC/128, 2*(HIDC/128)), 256, GSMEM>>>(
        kch, kcl, kw1h, kw1l, kb1, nullptr, h1kh, h1kl, nullptr, nullptr,
        vch, vcl, vw1h, vw1l, vb1, nullptr, h1vh, h1vl,
        BATCH*HEADS*WBLK, HIDC, HIDC);

    // 4) compress MLP layer 2 — k and v dual launch (both 2-term)
    tgemm_k<1,2,0,1,2><<<dim3(1, 64), 256, GSMEM>>>(
        h1kh, h1kl, kw2h, kw2l, kb2, ckf, nullptr, nullptr, nullptr, nullptr,
        h1vh, h1vl, vw2h, vw2l, vb2, cvf, nullptr, nullptr,
        BATCH*HEADS*WBLK, DHEAD, HIDC);
    fillmem_k<<<16, 256>>>(memkv, ckf, cvf);

    // 5) compressed attention + importance partials
    attn_c_k<<<dim3(SEQ/64, BATCH*HEADS), 256, SMEM_C>>>(q, ckf, cvf, cout, imp);

    // 6) top-k
    topk_k<<<BATCH*HEADS, 128>>>(imp, idxs, msk);

    // 7) fine attention (HMMA, gather fused via block indices)
    attn_f_k<<<dim3(SEQ/32, BATCH*HEADS), 256, SMEM_F2>>>(qr, kr, v, idxs, msk, fout);

    // 8) gate-combine -> split fp16
    combine2_k<<<QKVN/256, 256>>>(cout, fout, gates, oph, opl);

    // 9) output projection (fp32 out, 2-term)
    tgemm_k<0,0,0,0,2><<<dim3(DIM/128, ROWS/128), 256, GSMEM>>>(
        oph, opl, woh, wol, nullptr, out, nullptr, nullptr, nullptr, nullptr,
        nullptr, nullptr, nullptr, nullptr, nullptr, nullptr, nullptr, nullptr,
        ROWS, DIM, DIM);
}

// round 17
// speedup vs baseline: 1.3293x; 1.0243x over previous
#include <cuda_runtime.h>
#include <cuda_fp16.h>
#include <math.h>
#include <stdint.h>

// Problem constants
#define BATCH 2
#define SEQ   4096
#define DIM   2048
#define HEADS 16
#define DHEAD 128
#define BLKSZ 32
#define SELK  16
#define HIDC  4096
#define WBLK  128
#define CM    129
#define CMP   160
#define ROWS  (BATCH*SEQ)
#define QKVN  (BATCH*HEADS*SEQ*DHEAD)
#define NEGV  (-1e30f)
#define EPSV  1.1920929e-7f
#define SCALEV 0.08838834764831845f

// ------------------------- scratch (device globals) -------------------------
__device__ __align__(256) float g_q [QKVN];
__device__ __align__(256) float g_qr[QKVN];
__device__ __align__(256) float g_kr[QKVN];
__device__ __align__(256) float g_v [QKVN];
__device__ __align__(256) float g_ckf[BATCH*HEADS*CMP*DHEAD];
__device__ __align__(256) float g_cvf[BATCH*HEADS*CMP*DHEAD];
__device__ __align__(256) float g_cout[QKVN];
__device__ __align__(256) float g_fout[QKVN];
__device__ __align__(256) float g_gates[ROWS*2*HEADS];
__device__ __align__(256) float g_imp_part[BATCH*HEADS*64*WBLK];
__device__ int g_idx[BATCH*HEADS*SELK];
__device__ int g_msk[BATCH*HEADS*SELK];

// fp16 hi/lo split operands
__device__ __align__(256) __half b_inp_h[ROWS*DIM],  b_inp_l[ROWS*DIM];
__device__ __align__(256) __half b_wq_h[DIM*DIM],    b_wq_l[DIM*DIM];
__device__ __align__(256) __half b_wk_h[DIM*DIM],    b_wk_l[DIM*DIM];
__device__ __align__(256) __half b_wv_h[DIM*DIM],    b_wv_l[DIM*DIM];
__device__ __align__(256) __half b_kw1_h[HIDC*HIDC], b_kw1_l[HIDC*HIDC];
__device__ __align__(256) __half b_vw1_h[HIDC*HIDC], b_vw1_l[HIDC*HIDC];
__device__ __align__(256) __half b_kw2_h[DHEAD*HIDC],b_kw2_l[DHEAD*HIDC];
__device__ __align__(256) __half b_vw2_h[DHEAD*HIDC],b_vw2_l[DHEAD*HIDC];
__device__ __align__(256) __half b_wo_h[DIM*DIM],    b_wo_l[DIM*DIM];
__device__ __align__(256) __half b_kc_h[QKVN],       b_kc_l[QKVN];
__device__ __align__(256) __half b_vc_h[QKVN],       b_vc_l[QKVN];
__device__ __align__(256) __half b_h1k_h[HIDC*HIDC], b_h1k_l[HIDC*HIDC];
__device__ __align__(256) __half b_h1v_h[HIDC*HIDC], b_h1v_l[HIDC*HIDC];
__device__ __align__(256) __half b_op_h[ROWS*DIM],   b_op_l[ROWS*DIM];

// ------------------------- helpers ------------------------------------------
__device__ __forceinline__ uint32_t smem_u32(const void* p){
    uint32_t a;
    asm("{ .reg .u64 t; cvta.to.shared.u64 t, %1; cvt.u32.u64 %0, t; }" : "=r"(a) : "l"(p));
    return a;
}
__device__ __forceinline__ void cp16(uint32_t saddr, const void* gaddr){
    asm volatile("cp.async.cg.shared.global [%0], [%1], 16;" :: "r"(saddr), "l"(gaddr));
}
__device__ __forceinline__ void mma_f32(float* c, const uint32_t* a, const uint32_t* b){
    asm volatile("mma.sync.aligned.m16n8k16.row.col.f32.f16.f16.f32 "
        "{%0,%1,%2,%3}, {%4,%5,%6,%7}, {%8,%9}, {%0,%1,%2,%3};"
        : "+f"(c[0]), "+f"(c[1]), "+f"(c[2]), "+f"(c[3])
        : "r"(a[0]), "r"(a[1]), "r"(a[2]), "r"(a[3]), "r"(b[0]), "r"(b[1]));
}
__device__ __forceinline__ void mma_f16(uint32_t* c, const uint32_t* a, const uint32_t* b){
    asm volatile("mma.sync.aligned.m16n8k16.row.col.f16.f16.f16.f16 "
        "{%0,%1}, {%2,%3,%4,%5}, {%6,%7}, {%0,%1};"
        : "+r"(c[0]), "+r"(c[1])
        : "r"(a[0]), "r"(a[1]), "r"(a[2]), "r"(a[3]), "r"(b[0]), "r"(b[1]));
}
__device__ __forceinline__ void ldsm4(uint32_t* r, uint32_t addr){
    asm volatile("ldmatrix.sync.aligned.m8n8.x4.shared.b16 {%0,%1,%2,%3}, [%4];"
        : "=r"(r[0]), "=r"(r[1]), "=r"(r[2]), "=r"(r[3]) : "r"(addr));
}
__device__ __forceinline__ void ldsm4t(uint32_t* r, uint32_t addr){
    asm volatile("ldmatrix.sync.aligned.m8n8.x4.trans.shared.b16 {%0,%1,%2,%3}, [%4];"
        : "=r"(r[0]), "=r"(r[1]), "=r"(r[2]), "=r"(r[3]) : "r"(addr));
}
__device__ __forceinline__ void hsplit(float v, __half& h, __half& l){
    h = __float2half_rn(v);
    l = __float2half_rn(v - __half2float(h));
}

// ------------------------- split-fp16 tensor-core GEMM ----------------------
// Terms (TRM=2): Ah*Bh(f32) + Ah*Bl(f16)   [= Ah * B_exact; A-side fp16 hi]
// EPI: 0 none, 1 +bias, 2 +bias+relu.
// PERM: 0 rowmajor (OUTB 0 fp32 / 1 fp16 split), 1 q+rope, 2 memshift(CMP pad),
//       3 k: rope->X1 +pos split->Ch/Cl, 4 v: raw->C +pos split->Ch/Cl.
#define KCH   64
#define ASTR  72
#define TELEM (128*ASTR)
#define STAGEE (4*TELEM)
#define GSMEM (2*STAGEE*2)             // 147456 bytes

template<int EPI, int PERM, int OUTB, int DUAL, int TRM>
__global__ void __launch_bounds__(256, 1) tgemm_k(
    const __half* __restrict__ Ah, const __half* __restrict__ Al,
    const __half* __restrict__ Bh, const __half* __restrict__ Bl,
    const float* __restrict__ bias, float* __restrict__ C,
    __half* __restrict__ Ch, __half* __restrict__ Cl,
    float* __restrict__ X1, const float* __restrict__ pos,
    const __half* __restrict__ A2h, const __half* __restrict__ A2l,
    const __half* __restrict__ B2h, const __half* __restrict__ B2l,
    const float* __restrict__ bias2, float* __restrict__ C2,
    __half* __restrict__ Ch2, __half* __restrict__ Cl2,
    int M, int Nn, int K)
{
    extern __shared__ __half sm[];
    const uint32_t sb = smem_u32(sm);
    int tid = threadIdx.x;
    int warp = tid >> 5, lane = tid & 31;
    int wm = warp & 1, wn = warp >> 1;          // 2 x 4 warps, warp tile 64x32
    int grp = lane >> 2, tig = lane & 3;
    int bx = blockIdx.x, by = blockIdx.y;

    const __half* Au = Ah; const __half* Aul = Al;
    const __half* Bu = Bh; const __half* Bul = Bl;
    const float* bu = bias; float* Cu = C;
    __half* Chu = Ch; __half* Clu = Cl;
    if (DUAL) {
        int half_ = gridDim.y >> 1;
        if (by >= half_) {
            Au = A2h; Aul = A2l; Bu = B2h; Bul = B2l;
            bu = bias2; Cu = C2; Chu = Ch2; Clu = Cl2;
            by -= half_;
        }
    }
    const int terms = TRM;

    const __half* Agh = Au  + (size_t)by * 128 * K;
    const __half* Agl = Aul + (size_t)by * 128 * K;
    const __half* Bgh = Bu  + (size_t)bx * 128 * K;
    const __half* Bgl = Bul + (size_t)bx * 128 * K;

    float acc[4][4][4];
    uint32_t acc16[4][4][2];
#pragma unroll
    for (int i = 0; i < 4; i++)
#pragma unroll
        for (int j = 0; j < 4; j++) {
#pragma unroll
            for (int r = 0; r < 4; r++) acc[i][j][r] = 0.f;
            acc16[i][j][0] = 0u; acc16[i][j][1] = 0u;
        }

    int NC = K / KCH;

    auto load_stage = [&](int c, int s) {
        int k0 = c * KCH;
        uint32_t sbase = sb + s * STAGEE * 2;
#pragma unroll
        for (int i = 0; i < 4; i++) {
            int idx = tid + i * 256;
            int row = idx >> 3, kc = (idx & 7) * 8;
            uint32_t so = sbase + (uint32_t)(row * ASTR + kc) * 2;
            size_t go = (size_t)row * K + k0 + kc;
            cp16(so,                 Agh + go);
            if (terms == 3) cp16(so + TELEM * 2, Agl + go);
            cp16(so + 2 * TELEM * 2, Bgh + go);
            cp16(so + 3 * TELEM * 2, Bgl + go);
        }
    };

    load_stage(0, 0);
    asm volatile("cp.async.commit_group;");

    int a_r  = lane & 15;
    int a_k8 = (lane >> 4) * 8;
    int b_l  = lane & 7;
    int b_seg = lane >> 3;
    int b_r  = (b_seg >= 2) ? b_l + 8 : b_l;
    int b_k8 = (b_seg & 1) * 8;

    for (int c = 0; c < NC; c++) {
        if (c + 1 < NC) {
            load_stage(c + 1, (c + 1) & 1);
            asm volatile("cp.async.commit_group;");
            asm volatile("cp.async.wait_group 1;");
        } else {
            asm volatile("cp.async.wait_group 0;");
        }
        __syncthreads();

        uint32_t sA  = sb + (c & 1) * STAGEE * 2;
        uint32_t sAl = sA + TELEM * 2;
        uint32_t sBh = sA + 2 * TELEM * 2;
        uint32_t sBl = sA + 3 * TELEM * 2;

#pragma unroll
        for (int ks = 0; ks < KCH / 16; ks++) {
            int kbase = ks * 16;
            uint32_t ah[4][4], al[4][4], bh[2][4], bl[2][4];
#pragma unroll
            for (int mt = 0; mt < 4; mt++) {
                uint32_t off = (uint32_t)((wm * 64 + mt * 16 + a_r) * ASTR + kbase + a_k8) * 2;
                ldsm4(ah[mt], sA  + off);
                if (terms == 3) ldsm4(al[mt], sAl + off);
            }
#pragma unroll
            for (int np = 0; np < 2; np++) {
                uint32_t off = (uint32_t)((wn * 32 + np * 16 + b_r) * ASTR + kbase + b_k8) * 2;
                ldsm4(bh[np], sBh + off);
                ldsm4(bl[np], sBl + off);
            }
#pragma unroll
            for (int mt = 0; mt < 4; mt++)
#pragma unroll
                for (int nt = 0; nt < 4; nt++) {
                    const uint32_t* bhp = &bh[nt >> 1][(nt & 1) * 2];
                    const uint32_t* blp = &bl[nt >> 1][(nt & 1) * 2];
                    mma_f32(acc[mt][nt], ah[mt], bhp);
                    mma_f16(acc16[mt][nt], ah[mt], blp);
                    if (terms == 3) mma_f16(acc16[mt][nt], al[mt], bhp);
                }
        }
        __syncthreads();
    }

    // epilogue (merge f16 correction accumulators)
#pragma unroll
    for (int mt = 0; mt < 4; mt++)
#pragma unroll
        for (int h8 = 0; h8 < 2; h8++) {
            int rowg = by * 128 + wm * 64 + mt * 16 + grp + h8 * 8;
#pragma unroll
            for (int nt = 0; nt < 4; nt++) {
                int colg = bx * 128 + wn * 32 + nt * 8 + tig * 2;
                __half2 hc = *(__half2*)&acc16[mt][nt][h8];
                float v0 = acc[mt][nt][h8 * 2 + 0] + __low2float(hc);
                float v1 = acc[mt][nt][h8 * 2 + 1] + __high2float(hc);
                if (EPI >= 1) { v0 += bu[colg]; v1 += bu[colg + 1]; }
                if (EPI == 2) { v0 = fmaxf(v0, 0.f); v1 = fmaxf(v1, 0.f); }
                if (PERM == 0) {
                    size_t rb = (size_t)rowg * Nn + colg;
                    if (OUTB) {
                        __half2 H, L;
                        hsplit(v0, H.x, L.x); hsplit(v1, H.y, L.y);
                        *(__half2*)(Chu + rb) = H;
                        *(__half2*)(Clu + rb) = L;
                    } else {
                        float2 p; p.x = v0; p.y = v1;
                        *(float2*)(Cu + rb) = p;
                    }
                } else if (PERM == 2) {
                    size_t rb = (size_t)(rowg + ((rowg >> 7) << 5) + 1) * Nn + colg;
                    float2 p; p.x = v0; p.y = v1;
                    *(float2*)(Cu + rb) = p;
                } else {
                    int b = rowg >> 12, n = rowg & 4095;
                    int h = colg >> 7, d = colg & 127;
                    size_t dst = (((size_t)((b * HEADS + h) * SEQ + n)) << 7) + d;
                    if (PERM == 1 || PERM == 3) {
                        float inv = (float)exp(-(double)d * (9.210340371976184 / 128.0));
                        float t = (float)n * inv;
                        float s, cc; sincosf(t, &s, &cc);
                        float r0 = v0 * cc - v1 * s;
                        float r1 = v0 * s + v1 * cc;
                        float2 rp; rp.x = r0; rp.y = r1;
                        *(float2*)(X1 + dst) = rp;
                    }
                    if (PERM == 1 || PERM == 4) {
                        float2 p; p.x = v0; p.y = v1;
                        *(float2*)(Cu + dst) = p;
                    }
                    if (PERM == 3 || PERM == 4) {
                        const float* pp = pos + h * 4096 + (n & 31) * 128 + d;
                        __half2 H, L;
                        hsplit(v0 + pp[0], H.x, L.x);
                        hsplit(v1 + pp[1], H.y, L.y);
                        *(__half2*)(Chu + dst) = H;
                        *(__half2*)(Clu + dst) = L;
                    }
                }
            }
        }
}

// ------------------------- fp32 -> hi/lo fp16 convert ------------------------
__global__ void cvt_k(const float4* __restrict__ x, __half2* __restrict__ hi,
                      __half2* __restrict__ lo, int n4)
{
    int i = blockIdx.x * 256 + threadIdx.x;
    if (i >= n4) return;
    float4 v = x[i];
    __half2 H0, H1, L0, L1;
    hsplit(v.x, H0.x, L0.x); hsplit(v.y, H0.y, L0.y);
    hsplit(v.z, H1.x, L1.x); hsplit(v.w, H1.y, L1.y);
    hi[i * 2] = H0; hi[i * 2 + 1] = H1;
    lo[i * 2] = L0; lo[i * 2 + 1] = L1;
}

// transpose-convert: W[K,N] fp32 -> Wt hi/lo [N,K] fp16
__global__ void cvtT_k(const float* __restrict__ x, __half* __restrict__ hi,
                       __half* __restrict__ lo, int K, int N)
{
    __shared__ float t[32][33];
    int bx = blockIdx.x, by = blockIdx.y;
    int tx = threadIdx.x & 31, ty = threadIdx.x >> 5;
#pragma unroll
    for (int i = 0; i < 32; i += 8) {
        int kk = by * 32 + ty + i;
        t[ty + i][tx] = x[(size_t)kk * N + bx * 32 + tx];
    }
    __syncthreads();
#pragma unroll
    for (int i = 0; i < 32; i += 8) {
        int n = bx * 32 + ty + i;
        int kk = by * 32 + tx;
        float v = t[tx][ty + i];
        __half h, l; hsplit(v, h, l);
        hi[(size_t)n * K + kk] = h;
        lo[(size_t)n * K + kk] = l;
    }
}

// ------------------------- fused rmsnorm + gates ----------------------------
__global__ void gates_k(const float* __restrict__ inp, const float* __restrict__ g,
                        const float* __restrict__ Wg, const float* __restrict__ bg,
                        float* __restrict__ gates)
{
    __shared__ float xs[DIM];
    __shared__ float red[8];
    int row = blockIdx.x;
    int tid = threadIdx.x;
    const float* ip = inp + (size_t)row * DIM;
    float ss = 0.f;
    for (int k = tid; k < DIM; k += 256) { float v = ip[k]; xs[k] = v; ss += v * v; }
#pragma unroll
    for (int o = 16; o > 0; o >>= 1) ss += __shfl_xor_sync(~0u, ss, o);
    if ((tid & 31) == 0) red[tid >> 5] = ss;
    __syncthreads();
    float tot = red[0] + red[1] + red[2] + red[3] + red[4] + red[5] + red[6] + red[7];
    float rn = 1.0f / sqrtf(tot * (1.0f / DIM) + EPSV);
    int lane = tid & 31, warp = tid >> 5;
    for (int c = warp; c < 2 * HEADS; c += 8) {
        float acc = 0.f;
        for (int k = lane; k < DIM; k += 32) acc += xs[k] * g[k] * Wg[(size_t)k * (2 * HEADS) + c];
#pragma unroll
        for (int o = 16; o > 0; o >>= 1) acc += __shfl_xor_sync(~0u, acc, o);
        if (lane == 0) gates[(size_t)row * (2 * HEADS) + c] = 1.f / (1.f + expf(-(acc * rn + bg[c])));
    }
}

// --------- mem slots into ckf/cvf + zero padded rows [CM, CMP) --------------
__global__ void fillmem_k(const float* __restrict__ memkv,
                          float* __restrict__ ckf, float* __restrict__ cvf)
{
    int idx = blockIdx.x * 256 + threadIdx.x;      // 32 bh * 32 rows * 128 d
    if (idx >= BATCH * HEADS * 32 * DHEAD) return;
    int d = idx & 127; int r = (idx >> 7) & 31; int bh = idx >> 12;
    if (r == 0) {
        size_t dst = ((size_t)bh * CMP) * DHEAD + d;
        ckf[dst] = memkv[(bh & 15) * 128 + d];
        cvf[dst] = memkv[HEADS * 128 + (bh & 15) * 128 + d];
    } else {
        size_t dst = ((size_t)bh * CMP + 128 + r) * DHEAD + d;   // rows 129..159
        ckf[dst] = 0.f;
        cvf[dst] = 0.f;
    }
}

// ------------- compressed attention: HMMA (padded 160 keys) -----------------
// 256 thr, 8 warps; CTA = 64 q-rows.
// S phase: 3-term exact (qh+ql)*(ckh+ckl)  -> scores faithful -> top-k safe.
// O phase: P(fp16) * cv(fp16)              -> linear-only error.
#define QSTR 136
#define SSTR 164
#define PSTR 168
#define SMEM_C2 (2*64*QSTR*2 + 2*32*QSTR*2 + 64*SSTR*4 + 64*PSTR*2)   // 115712

__global__ void __launch_bounds__(256) attn_c_k(
    const float* __restrict__ q, const float* __restrict__ ckf,
    const float* __restrict__ cvf, float* __restrict__ cout,
    float* __restrict__ imp_part)
{
    extern __shared__ char smc[];
    __half* qh  = (__half*)smc;                       // 64 x QSTR
    __half* ql  = qh + 64 * QSTR;
    __half* kvh = ql + 64 * QSTR;                     // 32 x QSTR
    __half* kvl = kvh + 32 * QSTR;                    // 32 x QSTR (ck lo)
    float*  sims = (float*)(kvl + 32 * QSTR);         // 64 x SSTR
    __half* ph  = (__half*)(sims + 64 * SSTR);        // 64 x PSTR
    int tid = threadIdx.x, w = tid >> 5, lane = tid & 31;
    int grp = lane >> 2, tig = lane & 3;
    int bh = blockIdx.y, n0 = blockIdx.x * 64;

    const float* qb = q + (((size_t)bh * SEQ + n0) << 7);
    for (int i = tid; i < 64 * 32; i += 256) {
        int r = i >> 5, c4 = (i & 31) * 4;
        float4 t = *(const float4*)(qb + r * 128 + c4);
        __half2 H0, H1, L0, L1;
        hsplit(t.x, H0.x, L0.x); hsplit(t.y, H0.y, L0.y);
        hsplit(t.z, H1.x, L1.x); hsplit(t.w, H1.y, L1.y);
        *(__half2*)&qh[r * QSTR + c4]     = H0;
        *(__half2*)&qh[r * QSTR + c4 + 2] = H1;
        *(__half2*)&ql[r * QSTR + c4]     = L0;
        *(__half2*)&ql[r * QSTR + c4 + 2] = L1;
    }
    __syncthreads();

    uint32_t sqh = smem_u32(qh), sql = smem_u32(ql);
    uint32_t skvh = smem_u32(kvh), skvl = smem_u32(kvl), sph = smem_u32(ph);
    int mt = w & 3;                      // q-tile 0..3 (16 rows each)
    int nt = w >> 2;                     // key-tile 0..1 (16 keys each)
    int a_r = lane & 15, a_k8 = (lane >> 4) * 8;
    int b_l = lane & 7, b_k8p = (lane >> 3) * 8;

    // ---- phase 1: S = q . ck^T over 5 chunks of 32 keys (3-term exact) ----
    for (int ch = 0; ch < 5; ch++) {
        const float* kb = ckf + ((size_t)bh * CMP + ch * 32) * DHEAD;
        for (int i = tid; i < 32 * 32; i += 256) {
            int r = i >> 5, c4 = (i & 31) * 4;
            float4 t = *(const float4*)(kb + r * 128 + c4);
            __half2 H0, H1, L0, L1;
            hsplit(t.x, H0.x, L0.x); hsplit(t.y, H0.y, L0.y);
            hsplit(t.z, H1.x, L1.x); hsplit(t.w, H1.y, L1.y);
            *(__half2*)&kvh[r * QSTR + c4]     = H0;
            *(__half2*)&kvh[r * QSTR + c4 + 2] = H1;
            *(__half2*)&kvl[r * QSTR + c4]     = L0;
            *(__half2*)&kvl[r * QSTR + c4 + 2] = L1;
        }
        __syncthreads();
        float c0[4] = {0.f,0.f,0.f,0.f}, c1[4] = {0.f,0.f,0.f,0.f};
#pragma unroll
        for (int ks2 = 0; ks2 < 4; ks2++) {
            uint32_t bf0h[4], bf0l[4], bf1h[4], bf1l[4];
            uint32_t boff0 = (uint32_t)((nt * 16 + b_l) * QSTR + ks2 * 32 + b_k8p) * 2;
            uint32_t boff1 = (uint32_t)((nt * 16 + 8 + b_l) * QSTR + ks2 * 32 + b_k8p) * 2;
            ldsm4(bf0h, skvh + boff0);
            ldsm4(bf0l, skvl + boff0);
            ldsm4(bf1h, skvh + boff1);
            ldsm4(bf1l, skvl + boff1);
#pragma unroll
            for (int sub = 0; sub < 2; sub++) {
                uint32_t ah[4], al[4];
                uint32_t aoff = (uint32_t)((mt * 16 + a_r) * QSTR + ks2 * 32 + sub * 16 + a_k8) * 2;
                ldsm4(ah, sqh + aoff);
                ldsm4(al, sql + aoff);
                mma_f32(c0, ah, &bf0h[sub * 2]);
                mma_f32(c0, al, &bf0h[sub * 2]);
                mma_f32(c0, ah, &bf0l[sub * 2]);
                mma_f32(c1, ah, &bf1h[sub * 2]);
                mma_f32(c1, al, &bf1h[sub * 2]);
                mma_f32(c1, ah, &bf1l[sub * 2]);
            }
        }
        int r0 = mt * 16 + grp;
        int cb = ch * 32 + nt * 16 + tig * 2;
        sims[r0 * SSTR + cb]           = c0[0] * SCALEV;
        sims[r0 * SSTR + cb + 1]       = c0[1] * SCALEV;
        sims[(r0 + 8) * SSTR + cb]     = c0[2] * SCALEV;
        sims[(r0 + 8) * SSTR + cb + 1] = c0[3] * SCALEV;
        sims[r0 * SSTR + cb + 8]           = c1[0] * SCALEV;
        sims[r0 * SSTR + cb + 9]           = c1[1] * SCALEV;
        sims[(r0 + 8) * SSTR + cb + 8]     = c1[2] * SCALEV;
        sims[(r0 + 8) * SSTR + cb + 9]     = c1[3] * SCALEV;
        __syncthreads();
    }

    // ---- phase 2: softmax over 129 valid keys (mask pads) ----
    for (int r = w; r < 64; r += 8) {
        float* srow = sims + r * SSTR;
        __half* prow = ph + r * PSTR;
        float mx = -1e38f;
        for (int m = lane; m < CMP; m += 32) {
            float vv = (m < CM) ? srow[m] : NEGV;
            srow[m] = vv;
            mx = fmaxf(mx, vv);
        }
#pragma unroll
        for (int o = 16; o > 0; o >>= 1) mx = fmaxf(mx, __shfl_xor_sync(~0u, mx, o));
        float sum = 0.f;
        for (int m = lane; m < CMP; m += 32) { float e = expf(srow[m] - mx); srow[m] = e; sum += e; }
#pragma unroll
        for (int o = 16; o > 0; o >>= 1) sum += __shfl_xor_sync(~0u, sum, o);
        float inv = 1.f / sum;
        for (int m = lane; m < CMP; m += 32) {
            float p = srow[m] * inv;
            srow[m] = p;
            prow[m] = __float2half_rn(p);
        }
    }
    __syncthreads();
    if (tid < 128) {
        float s = 0.f;
        for (int r = 0; r < 64; r++) s += sims[r * SSTR + 1 + tid];
        imp_part[(((size_t)bh * 64) + blockIdx.x) * 128 + tid] = s;
    }
    __syncthreads();

    // ---- phase 3: O = P . cv over 5 chunks (fp16 cv, linear-safe) ----
    int dg = w >> 2;                     // d-group 0..1 (64 dims each)
    int t_key = (lane & 7) + ((lane >> 3) & 1) * 8;
    int t_d8  = (lane >> 4) * 8;
    float oacc[8][4];
#pragma unroll
    for (int i = 0; i < 8; i++)
#pragma unroll
        for (int j = 0; j < 4; j++) oacc[i][j] = 0.f;

    for (int ch = 0; ch < 5; ch++) {
        const float* vb = cvf + ((size_t)bh * CMP + ch * 32) * DHEAD;
        for (int i = tid; i < 32 * 32; i += 256) {
            int r = i >> 5, c4 = (i & 31) * 4;
            float4 t = *(const float4*)(vb + r * 128 + c4);
            *(__half2*)&kvh[r * QSTR + c4]     = __floats2half2_rn(t.x, t.y);
            *(__half2*)&kvh[r * QSTR + c4 + 2] = __floats2half2_rn(t.z, t.w);
        }
        __syncthreads();
#pragma unroll
        for (int s = 0; s < 2; s++) {
            uint32_t af[4];
            ldsm4(af, sph + (uint32_t)((mt * 16 + a_r) * PSTR + ch * 32 + s * 16 + a_k8) * 2);
#pragma unroll
            for (int p = 0; p < 4; p++) {
                uint32_t bf[4];
                uint32_t boff = (uint32_t)((s * 16 + t_key) * QSTR + dg * 64 + p * 16 + t_d8) * 2;
                ldsm4t(bf, skvh + boff);
                mma_f32(oacc[p * 2 + 0], af, &bf[0]);
                mma_f32(oacc[p * 2 + 1], af, &bf[2]);
            }
        }
        __syncthreads();
    }

#pragma unroll
    for (int p = 0; p < 4; p++)
#pragma unroll
        for (int t = 0; t < 2; t++) {
            float* c = oacc[p * 2 + t];
            int d0 = dg * 64 + p * 16 + t * 8 + tig * 2;
            size_t r0 = (((size_t)bh * SEQ) + n0 + mt * 16 + grp) * 128 + d0;
            size_t r1 = r0 + 8 * 128;
            float2 v0; v0.x = c[0]; v0.y = c[1];
            float2 v1; v1.x = c[2]; v1.y = c[3];
            *(float2*)(cout + r0) = v0;
            *(float2*)(cout + r1) = v1;
        }
}

// ------------------------- importance reduce + top-k ------------------------
__global__ void topk_k(const float* __restrict__ imp_part,
                       int* __restrict__ idxout, int* __restrict__ maskout)
{
    __shared__ float vals[WBLK];
    int bh = blockIdx.x, tid = threadIdx.x;
    float s = 0.f;
    for (int t = 0; t < 64; t++) s += imp_part[(((size_t)bh * 64) + t) * 128 + tid];
    vals[tid] = s * (1.0f / SEQ);
    __syncthreads();
    if (tid == 0) {
        for (int sel = 0; sel < SELK; sel++) {
            float best = -1e38f; int bi = 0;
            for (int m = 0; m < WBLK; m++)
                if (vals[m] > best) { best = vals[m]; bi = m; }
            idxout[bh * SELK + sel] = bi;
            maskout[bh * SELK + sel] = (best > 1e-10f) ? 1 : 0;
            vals[bi] = -1e38f;
        }
    }
}

// ------------- selected (fine) attention: HMMA + fused gather ---------------
#define FPSTR 520
#define SMEM_F2 ((3*32*QSTR)*2 + 32*516*4 + 32*FPSTR*2)

__global__ void __launch_bounds__(256) attn_f_k(
    const float* __restrict__ qr, const float* __restrict__ kr,
    const float* __restrict__ v, const int* __restrict__ idxs,
    const int* __restrict__ fmask, float* __restrict__ fout)
{
    extern __shared__ char smc[];
    __half* qh  = (__half*)smc;                       // 32 x QSTR
    __half* ql  = qh + 32 * QSTR;
    __half* kvh = ql + 32 * QSTR;
    float*  sims = (float*)(kvh + 32 * QSTR);         // 32 x 516
    __half* ph  = (__half*)(sims + 32 * 516);         // 32 x FPSTR
    __shared__ int maskS[SELK];
    __shared__ int blkS[SELK];
    int tid = threadIdx.x, w = tid >> 5, lane = tid & 31;
    int grp = lane >> 2, tig = lane & 3;
    int bh = blockIdx.y, n0 = blockIdx.x * 32;
    if (tid < SELK) {
        maskS[tid] = fmask[bh * SELK + tid];
        blkS[tid]  = idxs[bh * SELK + tid];
    }
    const float* qb = qr + (((size_t)bh * SEQ + n0) << 7);
    for (int i = tid; i < 32 * 32; i += 256) {
        int r = i >> 5, c4 = (i & 31) * 4;
        float4 t = *(const float4*)(qb + r * 128 + c4);
        __half2 H0, H1, L0, L1;
        hsplit(t.x, H0.x, L0.x); hsplit(t.y, H0.y, L0.y);
        hsplit(t.z, H1.x, L1.x); hsplit(t.w, H1.y, L1.y);
        *(__half2*)&qh[r * QSTR + c4]     = H0;
        *(__half2*)&qh[r * QSTR + c4 + 2] = H1;
        *(__half2*)&ql[r * QSTR + c4]     = L0;
        *(__half2*)&ql[r * QSTR + c4 + 2] = L1;
    }
    __syncthreads();

    uint32_t sqh = smem_u32(qh), sql = smem_u32(ql), skv = smem_u32(kvh), sph = smem_u32(ph);
    int mt = w & 1;
    int nt = w >> 1;
    int a_r = lane & 15, a_k8 = (lane >> 4) * 8;
    int b_key = nt * 8 + (lane & 7);
    int b_k8  = (lane >> 3) * 8;

    for (int b = 0; b < SELK; b++) {
        int blk = blkS[b];
        const float* kb = kr + (((size_t)bh * SEQ + blk * BLKSZ) << 7);
        for (int i = tid; i < 32 * 32; i += 256) {
            int r = i >> 5, c4 = (i & 31) * 4;
            float4 t = *(const float4*)(kb + r * 128 + c4);
            *(__half2*)&kvh[r * QSTR + c4]     = __floats2half2_rn(t.x, t.y);
            *(__half2*)&kvh[r * QSTR + c4 + 2] = __floats2half2_rn(t.z, t.w);
        }
        __syncthreads();
        float c[4] = {0.f, 0.f, 0.f, 0.f};
#pragma unroll
        for (int ks2 = 0; ks2 < 4; ks2++) {
            uint32_t bf[4];
            ldsm4(bf, skv + (uint32_t)(b_key * QSTR + ks2 * 32 + b_k8) * 2);
#pragma unroll
            for (int sub = 0; sub < 2; sub++) {
                int kb16 = ks2 * 32 + sub * 16;
                uint32_t ah[4], al[4];
                uint32_t aoff = (uint32_t)((mt * 16 + a_r) * QSTR + kb16 + a_k8) * 2;
                ldsm4(ah, sqh + aoff);
                ldsm4(al, sql + aoff);
                mma_f32(c, ah, &bf[sub * 2]);
                mma_f32(c, al, &bf[sub * 2]);
            }
        }
        int srow0 = mt * 16 + grp;
        int scol  = b * 32 + nt * 8 + tig * 2;
        sims[srow0 * 516 + scol]       = c[0] * SCALEV;
        sims[srow0 * 516 + scol + 1]   = c[1] * SCALEV;
        sims[(srow0 + 8) * 516 + scol]     = c[2] * SCALEV;
        sims[(srow0 + 8) * 516 + scol + 1] = c[3] * SCALEV;
        __syncthreads();
    }

    for (int r = w; r < 32; r += 8) {
        float* srow = sims + r * 516;
        __half* prow = ph + r * FPSTR;
        float mx = -1e38f;
        for (int m = lane; m < 512; m += 32) {
            float vv = srow[m];
            if (!maskS[m >> 5]) vv = NEGV;
            srow[m] = vv;
            mx = fmaxf(mx, vv);
        }
#pragma unroll
        for (int o = 16; o > 0; o >>= 1) mx = fmaxf(mx, __shfl_xor_sync(~0u, mx, o));
        float sum = 0.f;
        for (int m = lane; m < 512; m += 32) { float e = expf(srow[m] - mx); srow[m] = e; sum += e; }
#pragma unroll
        for (int o = 16; o > 0; o >>= 1) sum += __shfl_xor_sync(~0u, sum, o);
        float inv = 1.f / sum;
        for (int m = lane; m < 512; m += 32) prow[m] = __float2half_rn(srow[m] * inv);
    }
    __syncthreads();

    int dg = w >> 1;
    int t_key = (lane & 7) + ((lane >> 3) & 1) * 8;
    int t_d8  = (lane >> 4) * 8;
    float oacc[4][4];
#pragma unroll
    for (int i = 0; i < 4; i++)
#pragma unroll
        for (int j = 0; j < 4; j++) oacc[i][j] = 0.f;

    for (int b = 0; b < SELK; b++) {
        int blk = blkS[b];
        const float* vb = v + (((size_t)bh * SEQ + blk * BLKSZ) << 7);
        for (int i = tid; i < 32 * 32; i += 256) {
            int r = i >> 5, c4 = (i & 31) * 4;
            float4 t = *(const float4*)(vb + r * 128 + c4);
            *(__half2*)&kvh[r * QSTR + c4]     = __floats2half2_rn(t.x, t.y);
            *(__half2*)&kvh[r * QSTR + c4 + 2] = __floats2half2_rn(t.z, t.w);
        }
        __syncthreads();
#pragma unroll
        for (int s = 0; s < 2; s++) {
            uint32_t af[4];
            ldsm4(af, sph + (uint32_t)((mt * 16 + a_r) * FPSTR + b * 32 + s * 16 + a_k8) * 2);
#pragma unroll
            for (int p = 0; p < 2; p++) {
                uint32_t bf[4];
                uint32_t boff = (uint32_t)((s * 16 + t_key) * QSTR + dg * 32 + p * 16 + t_d8) * 2;
                ldsm4t(bf, skv + boff);
                mma_f32(oacc[p * 2 + 0], af, &bf[0]);
                mma_f32(oacc[p * 2 + 1], af, &bf[2]);
            }
        }
        __syncthreads();
    }

#pragma unroll
    for (int p = 0; p < 2; p++)
#pragma unroll
        for (int t = 0; t < 2; t++) {
            float* c = oacc[p * 2 + t];
            int d0 = dg * 32 + p * 16 + t * 8 + tig * 2;
            size_t r0 = (((size_t)bh * SEQ) + n0 + mt * 16 + grp) * 128 + d0;
            size_t r1 = r0 + 8 * 128;
            float2 v0; v0.x = c[0]; v0.y = c[1];
            float2 v1; v1.x = c[2]; v1.y = c[3];
            *(float2*)(fout + r0) = v0;
            *(float2*)(fout + r1) = v1;
        }
}

// ------------------------- combine gates -> fp16 hi/lo ----------------------
__global__ void combine2_k(const float* __restrict__ cout, const float* __restrict__ fout,
                           const float* __restrict__ gates,
                           __half* __restrict__ oh, __half* __restrict__ ol)
{
    int idx = blockIdx.x * 256 + threadIdx.x;
    int d = idx & 127; int h = (idx >> 7) & 15; int nrow = idx >> 11;
    int b = nrow >> 12; int n = nrow & 4095;
    size_t src = (((size_t)(b * HEADS + h) * SEQ) + n) * 128 + d;
    float g0 = gates[(size_t)nrow * (2 * HEADS) + 2 * h];
    float g1 = gates[(size_t)nrow * (2 * HEADS) + 2 * h + 1];
    float v = g0 * cout[src] + g1 * fout[src];
    __half hh, ll; hsplit(v, hh, ll);
    oh[idx] = hh; ol[idx] = ll;
}

// ------------------------- launch ------------------------------------------
extern "C" void kernel_launch(void* const* d_in, const int* in_sizes, int n_in,
                              void* d_out, int out_size)
{
    const float* inp  = (const float*)d_in[0];
    const float* g    = (const float*)d_in[1];
    const float* Wq   = (const float*)d_in[2];
    const float* Wk   = (const float*)d_in[3];
    const float* Wv   = (const float*)d_in[4];
    const float* kpos = (const float*)d_in[5];
    const float* vpos = (const float*)d_in[6];
    const float* memkv= (const float*)d_in[7];
    const float* kW1  = (const float*)d_in[8];
    const float* kb1  = (const float*)d_in[9];
    const float* kW2  = (const float*)d_in[10];
    const float* kb2  = (const float*)d_in[11];
    const float* vW1  = (const float*)d_in[12];
    const float* vb1  = (const float*)d_in[13];
    const float* vW2  = (const float*)d_in[14];
    const float* vb2  = (const float*)d_in[15];
    const float* Wg   = (const float*)d_in[16];
    const float* bg   = (const float*)d_in[17];
    const float* Wo   = (const float*)d_in[18];
    float* out = (float*)d_out;

    float *q, *qr, *kr, *v, *ckf, *cvf, *cout, *fout, *gates, *imp;
    int *idxs, *msk;
    cudaGetSymbolAddress((void**)&q,    g_q);
    cudaGetSymbolAddress((void**)&qr,   g_qr);
    cudaGetSymbolAddress((void**)&kr,   g_kr);
    cudaGetSymbolAddress((void**)&v,    g_v);
    cudaGetSymbolAddress((void**)&ckf,  g_ckf);
    cudaGetSymbolAddress((void**)&cvf,  g_cvf);
    cudaGetSymbolAddress((void**)&cout, g_cout);
    cudaGetSymbolAddress((void**)&fout, g_fout);
    cudaGetSymbolAddress((void**)&gates,g_gates);
    cudaGetSymbolAddress((void**)&imp,  g_imp_part);
    cudaGetSymbolAddress((void**)&idxs, g_idx);
    cudaGetSymbolAddress((void**)&msk,  g_msk);

    __half *inph,*inpl,*wqh,*wql,*wkh,*wkl,*wvh,*wvl,*kw1h,*kw1l,*vw1h,*vw1l;
    __half *kw2h,*kw2l,*vw2h,*vw2l,*woh,*wol,*kch,*kcl,*vch,*vcl;
    __half *h1kh,*h1kl,*h1vh,*h1vl,*oph,*opl;
    cudaGetSymbolAddress((void**)&inph, b_inp_h); cudaGetSymbolAddress((void**)&inpl, b_inp_l);
    cudaGetSymbolAddress((void**)&wqh,  b_wq_h);  cudaGetSymbolAddress((void**)&wql,  b_wq_l);
    cudaGetSymbolAddress((void**)&wkh,  b_wk_h);  cudaGetSymbolAddress((void**)&wkl,  b_wk_l);
    cudaGetSymbolAddress((void**)&wvh,  b_wv_h);  cudaGetSymbolAddress((void**)&wvl,  b_wv_l);
    cudaGetSymbolAddress((void**)&kw1h, b_kw1_h); cudaGetSymbolAddress((void**)&kw1l, b_kw1_l);
    cudaGetSymbolAddress((void**)&vw1h, b_vw1_h); cudaGetSymbolAddress((void**)&vw1l, b_vw1_l);
    cudaGetSymbolAddress((void**)&kw2h, b_kw2_h); cudaGetSymbolAddress((void**)&kw2l, b_kw2_l);
    cudaGetSymbolAddress((void**)&vw2h, b_vw2_h); cudaGetSymbolAddress((void**)&vw2l, b_vw2_l);
    cudaGetSymbolAddress((void**)&woh,  b_wo_h);  cudaGetSymbolAddress((void**)&wol,  b_wo_l);
    cudaGetSymbolAddress((void**)&kch,  b_kc_h);  cudaGetSymbolAddress((void**)&kcl,  b_kc_l);
    cudaGetSymbolAddress((void**)&vch,  b_vc_h);  cudaGetSymbolAddress((void**)&vcl,  b_vc_l);
    cudaGetSymbolAddress((void**)&h1kh, b_h1k_h); cudaGetSymbolAddress((void**)&h1kl, b_h1k_l);
    cudaGetSymbolAddress((void**)&h1vh, b_h1v_h); cudaGetSymbolAddress((void**)&h1vl, b_h1v_l);
    cudaGetSymbolAddress((void**)&oph,  b_op_h);  cudaGetSymbolAddress((void**)&opl,  b_op_l);

    cudaFuncSetAttribute(attn_c_k, cudaFuncAttributeMaxDynamicSharedMemorySize, SMEM_C2);
    cudaFuncSetAttribute(attn_f_k, cudaFuncAttributeMaxDynamicSharedMemorySize, SMEM_F2);
    cudaFuncSetAttribute(tgemm_k<0,1,0,0,2>, cudaFuncAttributeMaxDynamicSharedMemorySize, GSMEM);
    cudaFuncSetAttribute(tgemm_k<0,3,0,0,2>, cudaFuncAttributeMaxDynamicSharedMemorySize, GSMEM);
    cudaFuncSetAttribute(tgemm_k<0,4,0,0,2>, cudaFuncAttributeMaxDynamicSharedMemorySize, GSMEM);
    cudaFuncSetAttribute(tgemm_k<2,0,1,1,2>, cudaFuncAttributeMaxDynamicSharedMemorySize, GSMEM);
    cudaFuncSetAttribute(tgemm_k<1,2,0,1,2>, cudaFuncAttributeMaxDynamicSharedMemorySize, GSMEM);
    cudaFuncSetAttribute(tgemm_k<0,0,0,0,2>, cudaFuncAttributeMaxDynamicSharedMemorySize, GSMEM);

    // 0) converts
    cvt_k<<<(ROWS*DIM/4 + 255)/256, 256>>>((const float4*)inp, (__half2*)inph, (__half2*)inpl, ROWS*DIM/4);
    cvtT_k<<<dim3(DIM/32, DIM/32), 256>>>(Wq, wqh, wql, DIM, DIM);
    cvtT_k<<<dim3(DIM/32, DIM/32), 256>>>(Wk, wkh, wkl, DIM, DIM);
    cvtT_k<<<dim3(DIM/32, DIM/32), 256>>>(Wv, wvh, wvl, DIM, DIM);
    cvtT_k<<<dim3(HIDC/32, HIDC/32), 256>>>(kW1, kw1h, kw1l, HIDC, HIDC);

    // 1) QKV projections with fused RoPE / pos-pack epilogues
    dim3 gq(DIM/128, ROWS/128);
    tgemm_k<0,1,0,0,2><<<gq, 256, GSMEM>>>(inph, inpl, wqh, wql, nullptr, q, nullptr, nullptr,
        qr, nullptr, nullptr, nullptr, nullptr, nullptr, nullptr, nullptr, nullptr, nullptr,
        ROWS, DIM, DIM);
    tgemm_k<0,3,0,0,2><<<gq, 256, GSMEM>>>(inph, inpl, wkh, wkl, nullptr, nullptr, kch, kcl,
        kr, kpos, nullptr, nullptr, nullptr, nullptr, nullptr, nullptr, nullptr, nullptr,
        ROWS, DIM, DIM);
    tgemm_k<0,4,0,0,2><<<gq, 256, GSMEM>>>(inph, inpl, wvh, wvl, nullptr, v, vch, vcl,
        nullptr, vpos, nullptr, nullptr, nullptr, nullptr, nullptr, nullptr, nullptr, nullptr,
        ROWS, DIM, DIM);

    // remaining converts + gates
    cvtT_k<<<dim3(HIDC/32, HIDC/32), 256>>>(vW1, vw1h, vw1l, HIDC, HIDC);
    cvtT_k<<<dim3(DHEAD/32, HIDC/32), 256>>>(kW2, kw2h, kw2l, HIDC, DHEAD);
    cvtT_k<<<dim3(DHEAD/32, HIDC/32), 256>>>(vW2, vw2h, vw2l, HIDC, DHEAD);
    cvtT_k<<<dim3(DIM/32, DIM/32), 256>>>(Wo, woh, wol, DIM, DIM);
    gates_k<<<ROWS, 256>>>(inp, g, Wg, bg, gates);

    // 3) compress MLP layer 1 — dual launch (2-term)
    tgemm_k<2,0,1,1,2><<<dim3(HIDC/128, 2*(HIDC/128)), 256, GSMEM>>>(
        kch, kcl, kw1h, kw1l, kb1, nullptr, h1kh, h1kl, nullptr, nullptr,
        vch, vcl, vw1h, vw1l, vb1, nullptr, h1vh, h1vl,
        BATCH*HEADS*WBLK, HIDC, HIDC);

    // 4) compress MLP layer 2 — dual launch, memshift into padded CMP layout
    tgemm_k<1,2,0,1,2><<<dim3(1, 64), 256, GSMEM>>>(
        h1kh, h1kl, kw2h, kw2l, kb2, ckf, nullptr, nullptr, nullptr, nullptr,
        h1vh, h1vl, vw2h, vw2l, vb2, cvf, nullptr, nullptr,
        BATCH*HEADS*WBLK, DHEAD, HIDC);
    fillmem_k<<<(BATCH*HEADS*32*DHEAD + 255)/256, 256>>>(memkv, ckf, cvf);

    // 5) compressed attention (HMMA, exact scores) + importance partials
    attn_c_k<<<dim3(SEQ/64, BATCH*HEADS), 256, SMEM_C2>>>(q, ckf, cvf, cout, imp);

    // 6) top-k
    topk_k<<<BATCH*HEADS, 128>>>(imp, idxs, msk);

    // 7) fine attention (HMMA, gather fused)
    attn_f_k<<<dim3(SEQ/32, BATCH*HEADS), 256, SMEM_F2>>>(qr, kr, v, idxs, msk, fout);

    // 8) gate-combine -> split fp16
    combine2_k<<<QKVN/256, 256>>>(cout, fout, gates, oph, opl);

    // 9) output projection (fp32 out, 2-term)
    tgemm_k<0,0,0,0,2><<<dim3(DIM/128, ROWS/128), 256, GSMEM>>>(
        oph, opl, woh, wol, nullptr, out, nullptr, nullptr, nullptr, nullptr,
        nullptr, nullptr, nullptr, nullptr, nullptr, nullptr, nullptr, nullptr,
        ROWS, DIM, DIM);
}